// round 3
// baseline (speedup 1.0000x reference)
#include <cuda_runtime.h>
#include <math.h>

#define SEQ 4096
#define CD  640
#define NHD 8
#define HDD 80

// ---- device scratch (static; no runtime allocation) ----
__device__ float g_proj[9ull * SEQ * CD];          // 9 projections (94 MB)
__device__ float g_scores[17ull * SEQ * SEQ];      // 17 score matrices (1.14 GB)
__device__ float g_hs[(size_t)SEQ * CD];           // summed attention output
__device__ int   g_lab[SEQ];                       // entity labels (0..3)
__device__ int   g_outs[SEQ];                      // inpainting==0 flag

// ---------------------------------------------------------------------------
// labels: nearest-resize 512x512 -> 64x64 (idx = floor(i*512/64) = i*8)
// ---------------------------------------------------------------------------
__global__ void labels_kernel(const int* __restrict__ mask,
                              const int* __restrict__ inp) {
    int t = blockIdx.x * blockDim.x + threadIdx.x;
    if (t >= SEQ) return;
    int i = t >> 6, j = t & 63;
    int idx = (i * 8) * 512 + j * 8;
    g_lab[t]  = mask[idx];
    g_outs[t] = (inp[idx] == 0) ? 1 : 0;
}

// ---------------------------------------------------------------------------
// 9 projections: Y_z = X @ W_z^T   (M=4096, N=640, K=640)
// ---------------------------------------------------------------------------
struct W9 { const float* w[9]; };

__global__ __launch_bounds__(256) void proj_kernel(const float* __restrict__ X, W9 ws) {
    __shared__ float Xs[64][17];
    __shared__ float Ws[64][17];
    int z = blockIdx.z;
    const float* W = ws.w[z];
    float* Y = g_proj + (size_t)z * SEQ * CD;
    int n0 = blockIdx.x * 64, m0 = blockIdx.y * 64;
    int tid = threadIdx.x;
    int ty = tid >> 4, tx = tid & 15;
    float acc[4][4] = {};
    for (int k0 = 0; k0 < CD; k0 += 16) {
        #pragma unroll
        for (int e = 0; e < 4; e++) {
            int idx = tid + e * 256;
            int r = idx >> 4, c = idx & 15;
            Xs[r][c] = X[(size_t)(m0 + r) * CD + k0 + c];
            Ws[r][c] = W[(size_t)(n0 + r) * CD + k0 + c];
        }
        __syncthreads();
        #pragma unroll
        for (int kk = 0; kk < 16; kk++) {
            float xr[4], wr[4];
            #pragma unroll
            for (int i = 0; i < 4; i++) xr[i] = Xs[ty * 4 + i][kk];
            #pragma unroll
            for (int j = 0; j < 4; j++) wr[j] = Ws[tx * 4 + j][kk];
            #pragma unroll
            for (int i = 0; i < 4; i++)
                #pragma unroll
                for (int j = 0; j < 4; j++)
                    acc[i][j] += xr[i] * wr[j];
        }
        __syncthreads();
    }
    #pragma unroll
    for (int i = 0; i < 4; i++)
        #pragma unroll
        for (int j = 0; j < 4; j++)
            Y[(size_t)(m0 + ty * 4 + i) * CD + n0 + tx * 4 + j] = acc[i][j];
}

// ---------------------------------------------------------------------------
// scores: S[q,k] = mask ? (Q_h[q].K_h[k]) * scale : -1e9
// grid: (64 key-tiles, 64 query-tiles, heads)
// ---------------------------------------------------------------------------
__global__ __launch_bounds__(256) void scores_kernel(int qsel, int ksel, int zbase,
                                                     int headDim, float scale,
                                                     int applyOutside) {
    __shared__ float Qs[64][81];
    __shared__ float Ks[64][81];
    __shared__ int labq[64], labk[64], outk[64];
    int z = blockIdx.z;
    int k0 = blockIdx.x * 64, q0 = blockIdx.y * 64;
    int tid = threadIdx.x;
    const float* Q = g_proj + (size_t)qsel * SEQ * CD + (size_t)z * headDim;
    const float* K = g_proj + (size_t)ksel * SEQ * CD + (size_t)z * headDim;
    float* Sc = g_scores + (size_t)(zbase + z) * SEQ * SEQ;
    if (tid < 64) {
        labq[tid] = g_lab[q0 + tid];
        labk[tid] = g_lab[k0 + tid];
        outk[tid] = g_outs[k0 + tid];
    }
    int ty = tid >> 4, tx = tid & 15;
    float acc[4][4] = {};
    int nch = headDim / 80;
    for (int ch = 0; ch < nch; ch++) {
        #pragma unroll
        for (int e = 0; e < 20; e++) {
            int idx = tid + e * 256;         // 0..5119
            int r = idx / 80, c = idx % 80;
            Qs[r][c] = Q[(size_t)(q0 + r) * CD + ch * 80 + c];
            Ks[r][c] = K[(size_t)(k0 + r) * CD + ch * 80 + c];
        }
        __syncthreads();
        #pragma unroll 5
        for (int kk = 0; kk < 80; kk++) {
            float qr[4], kr[4];
            #pragma unroll
            for (int i = 0; i < 4; i++) qr[i] = Qs[ty * 4 + i][kk];
            #pragma unroll
            for (int j = 0; j < 4; j++) kr[j] = Ks[tx * 4 + j][kk];
            #pragma unroll
            for (int i = 0; i < 4; i++)
                #pragma unroll
                for (int j = 0; j < 4; j++)
                    acc[i][j] += qr[i] * kr[j];
        }
        __syncthreads();
    }
    #pragma unroll
    for (int i = 0; i < 4; i++) {
        int r = ty * 4 + i;
        int lq = labq[r];
        #pragma unroll
        for (int j = 0; j < 4; j++) {
            int c = tx * 4 + j;
            bool m = (lq == labk[c]) && (!applyOutside || outk[c]);
            Sc[(size_t)(q0 + r) * SEQ + (k0 + c)] = m ? acc[i][j] * scale : -1e9f;
        }
    }
}

// ---------------------------------------------------------------------------
// row softmax over 4096 keys (one block per row, row cached in SMEM)
// ---------------------------------------------------------------------------
__global__ __launch_bounds__(256) void softmax_kernel() {
    __shared__ float buf[SEQ];
    __shared__ float red[256];
    int row = blockIdx.x, z = blockIdx.y;
    float* p = g_scores + (size_t)z * SEQ * SEQ + (size_t)row * SEQ;
    int tid = threadIdx.x;
    float mx = -INFINITY;
    for (int i = tid; i < SEQ; i += 256) { float v = p[i]; buf[i] = v; mx = fmaxf(mx, v); }
    red[tid] = mx; __syncthreads();
    for (int s = 128; s > 0; s >>= 1) {
        if (tid < s) red[tid] = fmaxf(red[tid], red[tid + s]);
        __syncthreads();
    }
    mx = red[0]; __syncthreads();
    float sum = 0.f;
    for (int i = tid; i < SEQ; i += 256) { float e = __expf(buf[i] - mx); buf[i] = e; sum += e; }
    red[tid] = sum; __syncthreads();
    for (int s = 128; s > 0; s >>= 1) {
        if (tid < s) red[tid] += red[tid + s];
        __syncthreads();
    }
    float inv = 1.0f / red[0];
    for (int i = tid; i < SEQ; i += 256) p[i] = buf[i] * inv;
}

// ---------------------------------------------------------------------------
// AV: Out[:, c0:c0+80] (+)= P(4096x4096) @ V_h(4096x80)
// grid: (64 q-tiles, headDim/80 col-chunks, heads)
// ---------------------------------------------------------------------------
__global__ __launch_bounds__(256) void av_kernel(int zbase, int vsel, int headDim,
                                                 int accumulate) {
    __shared__ float Ps[64][33];
    __shared__ float Vs[32][81];
    int z = blockIdx.z;
    int q0 = blockIdx.x * 64;
    int c0 = z * headDim + blockIdx.y * 80;
    const float* P = g_scores + (size_t)(zbase + z) * SEQ * SEQ;
    const float* V = g_proj + (size_t)vsel * SEQ * CD;
    int tid = threadIdx.x;
    int ty = tid >> 4, tx = tid & 15;
    float acc[4][5] = {};
    for (int k0 = 0; k0 < SEQ; k0 += 32) {
        #pragma unroll
        for (int e = 0; e < 8; e++) {
            int idx = tid + e * 256;
            int r = idx >> 5, c = idx & 31;
            Ps[r][c] = P[(size_t)(q0 + r) * SEQ + k0 + c];
        }
        #pragma unroll
        for (int e = 0; e < 10; e++) {
            int idx = tid + e * 256;
            int r = idx / 80, c = idx % 80;
            Vs[r][c] = V[(size_t)(k0 + r) * CD + c0 + c];
        }
        __syncthreads();
        #pragma unroll 8
        for (int kk = 0; kk < 32; kk++) {
            float pr[4], vr[5];
            #pragma unroll
            for (int i = 0; i < 4; i++) pr[i] = Ps[ty * 4 + i][kk];
            #pragma unroll
            for (int j = 0; j < 5; j++) vr[j] = Vs[kk][tx * 5 + j];
            #pragma unroll
            for (int i = 0; i < 4; i++)
                #pragma unroll
                for (int j = 0; j < 5; j++)
                    acc[i][j] += pr[i] * vr[j];
        }
        __syncthreads();
    }
    #pragma unroll
    for (int i = 0; i < 4; i++)
        #pragma unroll
        for (int j = 0; j < 5; j++) {
            size_t o = (size_t)(q0 + ty * 4 + i) * CD + c0 + tx * 5 + j;
            if (accumulate) g_hs[o] += acc[i][j];
            else            g_hs[o] = acc[i][j];
        }
}

// ---------------------------------------------------------------------------
// final: out = g_hs @ Wo^T + residual
// ---------------------------------------------------------------------------
__global__ __launch_bounds__(256) void final_kernel(const float* __restrict__ Wo,
                                                    const float* __restrict__ resid,
                                                    float* __restrict__ Y) {
    __shared__ float Xs[64][17];
    __shared__ float Ws[64][17];
    int n0 = blockIdx.x * 64, m0 = blockIdx.y * 64;
    int tid = threadIdx.x;
    int ty = tid >> 4, tx = tid & 15;
    float acc[4][4] = {};
    for (int k0 = 0; k0 < CD; k0 += 16) {
        #pragma unroll
        for (int e = 0; e < 4; e++) {
            int idx = tid + e * 256;
            int r = idx >> 4, c = idx & 15;
            Xs[r][c] = g_hs[(size_t)(m0 + r) * CD + k0 + c];
            Ws[r][c] = Wo[(size_t)(n0 + r) * CD + k0 + c];
        }
        __syncthreads();
        #pragma unroll
        for (int kk = 0; kk < 16; kk++) {
            float xr[4], wr[4];
            #pragma unroll
            for (int i = 0; i < 4; i++) xr[i] = Xs[ty * 4 + i][kk];
            #pragma unroll
            for (int j = 0; j < 4; j++) wr[j] = Ws[tx * 4 + j][kk];
            #pragma unroll
            for (int i = 0; i < 4; i++)
                #pragma unroll
                for (int j = 0; j < 4; j++)
                    acc[i][j] += xr[i] * wr[j];
        }
        __syncthreads();
    }
    #pragma unroll
    for (int i = 0; i < 4; i++)
        #pragma unroll
        for (int j = 0; j < 4; j++) {
            size_t o = (size_t)(m0 + ty * 4 + i) * CD + n0 + tx * 4 + j;
            Y[o] = acc[i][j] + resid[o];
        }
}

// ---------------------------------------------------------------------------
// launch: 11 kernel launches, all graph-capturable, no allocations
// ---------------------------------------------------------------------------
extern "C" void kernel_launch(void* const* d_in, const int* in_sizes, int n_in,
                              void* d_out, int out_size) {
    const float* hidden = (const float*)d_in[0];
    const int*   mask   = (const int*)d_in[1];
    const int*   inp    = (const int*)d_in[2];
    W9 ws;
    for (int i = 0; i < 9; i++) ws.w[i] = (const float*)d_in[3 + i];
    const float* Wo = (const float*)d_in[12];
    float* out = (float*)d_out;

    const float s80  = 1.0f / sqrtf(80.0f);
    const float s640 = 1.0f / sqrtf(640.0f);

    labels_kernel<<<16, 256>>>(mask, inp);
    proj_kernel<<<dim3(10, 64, 9), 256>>>(hidden, ws);

    // proj indices: 0=q 1=k 2=v 3=q_ent 4=k_ent 5=v_ent 6=q_out 7=k_out 8=v_out
    scores_kernel<<<dim3(64, 64, 8), 256>>>(0, 1, 0, 80,  s80,  0);  // original
    scores_kernel<<<dim3(64, 64, 1), 256>>>(3, 4, 8, 640, s640, 0);  // entity (1 head)
    scores_kernel<<<dim3(64, 64, 8), 256>>>(6, 7, 9, 80,  s80,  1);  // outside

    softmax_kernel<<<dim3(SEQ, 17), 256>>>();

    av_kernel<<<dim3(64, 1, 8), 256>>>(0, 2, 80,  0);  // writes g_hs
    av_kernel<<<dim3(64, 8, 1), 256>>>(8, 5, 640, 1);  // accumulates
    av_kernel<<<dim3(64, 1, 8), 256>>>(9, 8, 80,  1);  // accumulates

    final_kernel<<<dim3(10, 64, 1), 256>>>(Wo, hidden, out);
}

// round 4
// speedup vs baseline: 3.0735x; 3.0735x over previous
#include <cuda_runtime.h>
#include <math.h>

#define SEQ 4096
#define CD  640
#define NHD 8
#define HDD 80
#define MATSZ ((size_t)SEQ * SEQ + 16384)   // per-matrix compact grouped storage (padded)

// ---- device scratch (static; no runtime allocation) ----
__device__ float g_proj[9ull * SEQ * CD];          // 9 projections, PERMUTED row order
__device__ float g_scores[17ull * MATSZ];          // 17 grouped score matrices
__device__ float g_hs[(size_t)SEQ * CD];           // attention output, PERMUTED order
__device__ float g_meanVo[CD];                     // column mean of V_out (fallback)
__device__ int   g_lab[SEQ];                       // entity labels (0..3)
__device__ int   g_outs[SEQ];                      // inpainting==0 flag
__device__ int   g_iperm[SEQ];                     // original row -> permuted row
__device__ int   d_off[4], d_cnt[4], d_cntOut[4], d_cntPad[4];
__device__ long long d_scbase[4];
__device__ int   d_qtileG[68], d_qtileQ0[68];
__device__ int   d_nqtiles;
__device__ int   d_rowg[SEQ], d_rowloc[SEQ];       // per permuted row: group, local idx

// ---------------------------------------------------------------------------
// labels: nearest-resize 512x512 -> 64x64 (idx = i*8)
// ---------------------------------------------------------------------------
__global__ void labels_kernel(const int* __restrict__ mask,
                              const int* __restrict__ inp) {
    int t = blockIdx.x * blockDim.x + threadIdx.x;
    if (t >= SEQ) return;
    int i = t >> 6, j = t & 63;
    int idx = (i * 8) * 512 + j * 8;
    g_lab[t]  = mask[idx];
    g_outs[t] = (inp[idx] == 0) ? 1 : 0;
}

// ---------------------------------------------------------------------------
// prep: bucket sort by (label, !outside); group metadata; q-tile list
// ---------------------------------------------------------------------------
__global__ void prep_kernel() {
    __shared__ int cnt8[8], off8[8], cur8[8];
    int tid = threadIdx.x;
    if (tid < 8) cnt8[tid] = 0;
    __syncthreads();
    for (int t = tid; t < SEQ; t += 256) {
        int b = g_lab[t] * 2 + (g_outs[t] ? 0 : 1);
        atomicAdd(&cnt8[b], 1);
    }
    __syncthreads();
    if (tid == 0) {
        int acc = 0;
        for (int b = 0; b < 8; b++) { off8[b] = acc; acc += cnt8[b]; }
        long long sb = 0;
        int nq = 0;
        for (int g = 0; g < 4; g++) {
            int c = cnt8[2 * g] + cnt8[2 * g + 1];
            d_cnt[g] = c;
            d_cntOut[g] = cnt8[2 * g];
            d_off[g] = off8[2 * g];
            int pad = ((c + 63) >> 6) << 6;
            d_cntPad[g] = pad;
            d_scbase[g] = sb;
            sb += (long long)pad * pad;
            for (int j = 0; j < c; j += 64) { d_qtileG[nq] = g; d_qtileQ0[nq] = j; nq++; }
        }
        d_nqtiles = nq;
    }
    __syncthreads();
    if (tid < 8) cur8[tid] = off8[tid];
    __syncthreads();
    for (int t = tid; t < SEQ; t += 256) {
        int b = g_lab[t] * 2 + (g_outs[t] ? 0 : 1);
        int pos = atomicAdd(&cur8[b], 1);
        g_iperm[t] = pos;
    }
    __syncthreads();
    for (int i = tid; i < SEQ; i += 256) {
        int g = 3;
        if      (i < d_off[1]) g = 0;
        else if (i < d_off[2]) g = 1;
        else if (i < d_off[3]) g = 2;
        d_rowg[i] = g;
        d_rowloc[i] = i - d_off[g];
    }
}

// ---------------------------------------------------------------------------
// 9 projections: Y_z[iperm[m]] = (X @ W_z^T)[m]    128x128 tile, 8x8 micro
// ---------------------------------------------------------------------------
struct W9 { const float* w[9]; };

__global__ __launch_bounds__(256) void proj_kernel(const float* __restrict__ X, W9 ws) {
    __shared__ float Xs[16][132];
    __shared__ float Ws[16][132];
    __shared__ int ip[128];
    int z = blockIdx.z;
    const float* W = ws.w[z];
    float* Y = g_proj + (size_t)z * SEQ * CD;
    int n0 = blockIdx.x * 128, m0 = blockIdx.y * 128;
    int tid = threadIdx.x;
    int ty = tid >> 4, tx = tid & 15;
    if (tid < 128) ip[tid] = g_iperm[m0 + tid];
    float acc[8][8] = {};
    for (int k0 = 0; k0 < CD; k0 += 16) {
        #pragma unroll
        for (int e = 0; e < 8; e++) {
            int lin = tid + e * 256;
            int r = lin >> 4, c = lin & 15;
            Xs[c][r] = X[(size_t)(m0 + r) * CD + k0 + c];
            Ws[c][r] = W[(size_t)(n0 + r) * CD + k0 + c];
        }
        __syncthreads();
        #pragma unroll
        for (int kk = 0; kk < 16; kk++) {
            float a[8], b[8];
            *(float4*)&a[0] = *(float4*)&Xs[kk][ty * 8];
            *(float4*)&a[4] = *(float4*)&Xs[kk][ty * 8 + 4];
            *(float4*)&b[0] = *(float4*)&Ws[kk][tx * 8];
            *(float4*)&b[4] = *(float4*)&Ws[kk][tx * 8 + 4];
            #pragma unroll
            for (int i = 0; i < 8; i++)
                #pragma unroll
                for (int j = 0; j < 8; j++)
                    acc[i][j] += a[i] * b[j];
        }
        __syncthreads();
    }
    #pragma unroll
    for (int i = 0; i < 8; i++) {
        size_t row = (size_t)ip[ty * 8 + i] * CD + n0;
        #pragma unroll
        for (int j = 0; j < 8; j++)
            Y[row + tx * 8 + j] = acc[i][j];
    }
}

// ---------------------------------------------------------------------------
// grouped scores: S = Qp Kp^T * scale within a group segment (no masks!)
// grid: (q-tiles<=68, k-tiles<=64, heads)
// ---------------------------------------------------------------------------
__global__ __launch_bounds__(256) void scores_kernel(int qsel, int ksel, int zbase,
                                                     int headDim, float scale,
                                                     int useOut) {
    __shared__ float Qs[64][81];
    __shared__ float Ks[64][81];
    int qt = blockIdx.x;
    if (qt >= d_nqtiles) return;
    int g = d_qtileG[qt], q0 = d_qtileQ0[qt];
    int cnt = d_cnt[g];
    int len = useOut ? d_cntOut[g] : cnt;
    int k0 = blockIdx.y * 64;
    if (k0 >= len) return;
    int off = d_off[g];
    int stride = d_cntPad[g];
    int z = blockIdx.z;
    const float* Q = g_proj + (size_t)qsel * SEQ * CD;
    const float* K = g_proj + (size_t)ksel * SEQ * CD;
    float* Sc = g_scores + (size_t)(zbase + z) * MATSZ + (size_t)d_scbase[g];
    int tid = threadIdx.x;
    int ty = tid >> 4, tx = tid & 15;
    float acc[4][4] = {};
    int nch = headDim / 80;
    for (int ch = 0; ch < nch; ch++) {
        int colb = z * headDim + ch * 80;
        #pragma unroll
        for (int e = 0; e < 20; e++) {
            int idx = tid + e * 256;         // 0..5119
            int r = idx / 80, c = idx % 80;
            int qr = q0 + r, kc = k0 + r;
            Qs[r][c] = (qr < cnt) ? Q[(size_t)(off + qr) * CD + colb + c] : 0.f;
            Ks[r][c] = (kc < len) ? K[(size_t)(off + kc) * CD + colb + c] : 0.f;
        }
        __syncthreads();
        #pragma unroll 5
        for (int kk = 0; kk < 80; kk++) {
            float qr[4], kr[4];
            #pragma unroll
            for (int i = 0; i < 4; i++) qr[i] = Qs[ty * 4 + i][kk];
            #pragma unroll
            for (int j = 0; j < 4; j++) kr[j] = Ks[tx * 4 + j][kk];
            #pragma unroll
            for (int i = 0; i < 4; i++)
                #pragma unroll
                for (int j = 0; j < 4; j++)
                    acc[i][j] += qr[i] * kr[j];
        }
        __syncthreads();
    }
    #pragma unroll
    for (int i = 0; i < 4; i++) {
        int r = q0 + ty * 4 + i;
        if (r >= cnt) continue;
        #pragma unroll
        for (int j = 0; j < 4; j++) {
            int c = k0 + tx * 4 + j;
            if (c < len)
                Sc[(size_t)r * stride + c] = acc[i][j] * scale;
        }
    }
}

// ---------------------------------------------------------------------------
// grouped row softmax (length = group size or outside-prefix size)
// ---------------------------------------------------------------------------
__global__ __launch_bounds__(256) void softmax_kernel() {
    __shared__ float buf[SEQ];
    __shared__ float red[256];
    int row = blockIdx.x, z = blockIdx.y;
    int g = d_rowg[row], rl = d_rowloc[row];
    int len = (z >= 9) ? d_cntOut[g] : d_cnt[g];
    if (len == 0) return;
    float* p = g_scores + (size_t)z * MATSZ + (size_t)d_scbase[g]
             + (size_t)rl * d_cntPad[g];
    int tid = threadIdx.x;
    float mx = -INFINITY;
    for (int i = tid; i < len; i += 256) { float v = p[i]; buf[i] = v; mx = fmaxf(mx, v); }
    red[tid] = mx; __syncthreads();
    for (int s = 128; s > 0; s >>= 1) {
        if (tid < s) red[tid] = fmaxf(red[tid], red[tid + s]);
        __syncthreads();
    }
    mx = red[0]; __syncthreads();
    float sum = 0.f;
    for (int i = tid; i < len; i += 256) { float e = __expf(buf[i] - mx); buf[i] = e; sum += e; }
    red[tid] = sum; __syncthreads();
    for (int s = 128; s > 0; s >>= 1) {
        if (tid < s) red[tid] += red[tid + s];
        __syncthreads();
    }
    float inv = 1.0f / red[0];
    for (int i = tid; i < len; i += 256) p[i] = buf[i] * inv;
}

// ---------------------------------------------------------------------------
// grouped AV: Out[:, c0:c0+80] (+)= P(group) @ Vp(group)
// grid: (q-tiles<=68, col-chunks, heads)
// ---------------------------------------------------------------------------
__global__ __launch_bounds__(256) void av_kernel(int zbase, int vsel, int headDim,
                                                 int accumulate, int useOut) {
    __shared__ float Ps[64][33];
    __shared__ float Vs[32][81];
    int qt = blockIdx.x;
    if (qt >= d_nqtiles) return;
    int g = d_qtileG[qt], q0 = d_qtileQ0[qt];
    int cnt = d_cnt[g];
    int len = useOut ? d_cntOut[g] : cnt;
    if (len == 0) return;          // only possible for accumulate branches
    int off = d_off[g];
    int stride = d_cntPad[g];
    int z = blockIdx.z;
    int c0 = z * headDim + blockIdx.y * 80;
    const float* P = g_scores + (size_t)(zbase + z) * MATSZ + (size_t)d_scbase[g];
    const float* V = g_proj + (size_t)vsel * SEQ * CD;
    int tid = threadIdx.x;
    int ty = tid >> 4, tx = tid & 15;
    float acc[4][5] = {};
    for (int k0 = 0; k0 < len; k0 += 32) {
        #pragma unroll
        for (int e = 0; e < 8; e++) {
            int idx = tid + e * 256;
            int r = idx >> 5, c = idx & 31;
            Ps[r][c] = (k0 + c < len) ? P[(size_t)(q0 + r) * stride + k0 + c] : 0.f;
        }
        #pragma unroll
        for (int e = 0; e < 10; e++) {
            int idx = tid + e * 256;
            int r = idx / 80, c = idx % 80;
            Vs[r][c] = (k0 + r < len) ? V[(size_t)(off + k0 + r) * CD + c0 + c] : 0.f;
        }
        __syncthreads();
        #pragma unroll 8
        for (int kk = 0; kk < 32; kk++) {
            float pr[4], vr[5];
            #pragma unroll
            for (int i = 0; i < 4; i++) pr[i] = Ps[ty * 4 + i][kk];
            #pragma unroll
            for (int j = 0; j < 5; j++) vr[j] = Vs[kk][tx * 5 + j];
            #pragma unroll
            for (int i = 0; i < 4; i++)
                #pragma unroll
                for (int j = 0; j < 5; j++)
                    acc[i][j] += pr[i] * vr[j];
        }
        __syncthreads();
    }
    #pragma unroll
    for (int i = 0; i < 4; i++) {
        int r = q0 + ty * 4 + i;
        if (r >= cnt) continue;
        #pragma unroll
        for (int j = 0; j < 5; j++) {
            size_t o = (size_t)(off + r) * CD + c0 + tx * 5 + j;
            if (accumulate) g_hs[o] += acc[i][j];
            else            g_hs[o] = acc[i][j];
        }
    }
}

// ---------------------------------------------------------------------------
// fallback for fully-masked outside rows: mean of ALL V_out rows
// ---------------------------------------------------------------------------
__global__ void meanv_kernel() {
    int c = blockIdx.x * blockDim.x + threadIdx.x;
    if (c >= CD) return;
    const float* V = g_proj + 8ull * SEQ * CD;
    float s = 0.f;
    for (int r = 0; r < SEQ; r++) s += V[(size_t)r * CD + c];
    g_meanVo[c] = s * (1.0f / SEQ);
}

__global__ void fb_kernel() {
    int row = blockIdx.x;
    int g = d_rowg[row];
    if (d_cntOut[g] != 0) return;
    for (int c = threadIdx.x; c < CD; c += 256)
        g_hs[(size_t)row * CD + c] += g_meanVo[c];
}

// ---------------------------------------------------------------------------
// final: out[m] = hs_p[iperm[m]] @ Wo^T + residual[m]
// ---------------------------------------------------------------------------
__global__ __launch_bounds__(256) void final_kernel(const float* __restrict__ Wo,
                                                    const float* __restrict__ resid,
                                                    float* __restrict__ Y) {
    __shared__ float Xs[64][17];
    __shared__ float Ws[64][17];
    __shared__ int ip[64];
    int n0 = blockIdx.x * 64, m0 = blockIdx.y * 64;
    int tid = threadIdx.x;
    if (tid < 64) ip[tid] = g_iperm[m0 + tid];
    int ty = tid >> 4, tx = tid & 15;
    float acc[4][4] = {};
    for (int k0 = 0; k0 < CD; k0 += 16) {
        __syncthreads();
        #pragma unroll
        for (int e = 0; e < 4; e++) {
            int idx = tid + e * 256;
            int r = idx >> 4, c = idx & 15;
            Xs[r][c] = g_hs[(size_t)ip[r] * CD + k0 + c];
            Ws[r][c] = Wo[(size_t)(n0 + r) * CD + k0 + c];
        }
        __syncthreads();
        #pragma unroll
        for (int kk = 0; kk < 16; kk++) {
            float xr[4], wr[4];
            #pragma unroll
            for (int i = 0; i < 4; i++) xr[i] = Xs[ty * 4 + i][kk];
            #pragma unroll
            for (int j = 0; j < 4; j++) wr[j] = Ws[tx * 4 + j][kk];
            #pragma unroll
            for (int i = 0; i < 4; i++)
                #pragma unroll
                for (int j = 0; j < 4; j++)
                    acc[i][j] += xr[i] * wr[j];
        }
    }
    #pragma unroll
    for (int i = 0; i < 4; i++)
        #pragma unroll
        for (int j = 0; j < 4; j++) {
            size_t o = (size_t)(m0 + ty * 4 + i) * CD + n0 + tx * 4 + j;
            Y[o] = acc[i][j] + resid[o];
        }
}

// ---------------------------------------------------------------------------
// launch
// ---------------------------------------------------------------------------
extern "C" void kernel_launch(void* const* d_in, const int* in_sizes, int n_in,
                              void* d_out, int out_size) {
    const float* hidden = (const float*)d_in[0];
    const int*   mask   = (const int*)d_in[1];
    const int*   inp    = (const int*)d_in[2];
    W9 ws;
    for (int i = 0; i < 9; i++) ws.w[i] = (const float*)d_in[3 + i];
    const float* Wo = (const float*)d_in[12];
    float* out = (float*)d_out;

    const float s80  = 1.0f / sqrtf(80.0f);
    const float s640 = 1.0f / sqrtf(640.0f);

    labels_kernel<<<16, 256>>>(mask, inp);
    prep_kernel<<<1, 256>>>();
    proj_kernel<<<dim3(5, 32, 9), 256>>>(hidden, ws);
    meanv_kernel<<<3, 256>>>();

    // proj indices: 0=q 1=k 2=v 3=q_ent 4=k_ent 5=v_ent 6=q_out 7=k_out 8=v_out
    scores_kernel<<<dim3(68, 64, 8), 256>>>(0, 1, 0, 80,  s80,  0);  // original
    scores_kernel<<<dim3(68, 64, 1), 256>>>(3, 4, 8, 640, s640, 0);  // entity (1 head)
    scores_kernel<<<dim3(68, 64, 8), 256>>>(6, 7, 9, 80,  s80,  1);  // outside

    softmax_kernel<<<dim3(SEQ, 17), 256>>>();

    av_kernel<<<dim3(68, 1, 8), 256>>>(0, 2, 80,  0, 0);  // writes g_hs
    av_kernel<<<dim3(68, 8, 1), 256>>>(8, 5, 640, 1, 0);  // accumulates
    av_kernel<<<dim3(68, 1, 8), 256>>>(9, 8, 80,  1, 1);  // accumulates

    fb_kernel<<<SEQ, 256>>>();
    final_kernel<<<dim3(10, 64, 1), 256>>>(Wo, hidden, out);
}

// round 5
// speedup vs baseline: 3.7551x; 1.2217x over previous
#include <cuda_runtime.h>
#include <math.h>

#define SEQ 4096
#define CD  640
#define NHD 8
#define HDD 80
#define MATSZ ((size_t)SEQ * SEQ + (1u << 21))   // grouped storage + 128-pad slack

// ---- device scratch (static; no runtime allocation) ----
__device__ float g_proj[9ull * SEQ * CD];          // 9 projections, PERMUTED row order
__device__ float g_scores[17ull * MATSZ];          // 17 grouped score matrices
__device__ float g_hs[(size_t)SEQ * CD];           // attention output, PERMUTED order
__device__ float g_meanVo[CD];                     // column mean of V_out (fallback)
__device__ int   g_lab[SEQ];                       // entity labels (0..3)
__device__ int   g_outs[SEQ];                      // inpainting==0 flag
__device__ int   g_iperm[SEQ];                     // original row -> permuted row
__device__ int   d_off[4], d_cnt[4], d_cntOut[4], d_cntPad[4];
__device__ long long d_scbase[4];
__device__ int   d_qtileG[40], d_qtileQ0[40];
__device__ int   d_nqtiles;
__device__ int   d_rowg[SEQ], d_rowloc[SEQ];       // per permuted row: group, local idx

// ---------------------------------------------------------------------------
// labels: nearest-resize 512x512 -> 64x64 (idx = i*8); also zero meanVo
// ---------------------------------------------------------------------------
__global__ void labels_kernel(const int* __restrict__ mask,
                              const int* __restrict__ inp) {
    int t = blockIdx.x * blockDim.x + threadIdx.x;
    if (t < CD) g_meanVo[t] = 0.f;
    if (t >= SEQ) return;
    int i = t >> 6, j = t & 63;
    int idx = (i * 8) * 512 + j * 8;
    g_lab[t]  = mask[idx];
    g_outs[t] = (inp[idx] == 0) ? 1 : 0;
}

// ---------------------------------------------------------------------------
// prep: bucket sort by (label, !outside); group metadata; 128-wide q-tiles
// ---------------------------------------------------------------------------
__global__ void prep_kernel() {
    __shared__ int cnt8[8], off8[8], cur8[8];
    int tid = threadIdx.x;
    if (tid < 8) cnt8[tid] = 0;
    __syncthreads();
    for (int t = tid; t < SEQ; t += 256) {
        int b = g_lab[t] * 2 + (g_outs[t] ? 0 : 1);
        atomicAdd(&cnt8[b], 1);
    }
    __syncthreads();
    if (tid == 0) {
        int acc = 0;
        for (int b = 0; b < 8; b++) { off8[b] = acc; acc += cnt8[b]; }
        long long sb = 0;
        int nq = 0;
        for (int g = 0; g < 4; g++) {
            int c = cnt8[2 * g] + cnt8[2 * g + 1];
            d_cnt[g] = c;
            d_cntOut[g] = cnt8[2 * g];
            d_off[g] = off8[2 * g];
            int pad = ((c + 127) >> 7) << 7;
            d_cntPad[g] = pad;
            d_scbase[g] = sb;
            sb += (long long)pad * pad;
            for (int j = 0; j < c; j += 128) { d_qtileG[nq] = g; d_qtileQ0[nq] = j; nq++; }
        }
        d_nqtiles = nq;
    }
    __syncthreads();
    if (tid < 8) cur8[tid] = off8[tid];
    __syncthreads();
    for (int t = tid; t < SEQ; t += 256) {
        int b = g_lab[t] * 2 + (g_outs[t] ? 0 : 1);
        int pos = atomicAdd(&cur8[b], 1);
        g_iperm[t] = pos;
    }
    __syncthreads();
    for (int i = tid; i < SEQ; i += 256) {
        int g = 3;
        if      (i < d_off[1]) g = 0;
        else if (i < d_off[2]) g = 1;
        else if (i < d_off[3]) g = 2;
        d_rowg[i] = g;
        d_rowloc[i] = i - d_off[g];
    }
}

// ---------------------------------------------------------------------------
// 9 projections: Y_z[iperm[m]] = (X @ W_z^T)[m]    128x128 tile, 8x8 micro
// ---------------------------------------------------------------------------
struct W9 { const float* w[9]; };

__global__ __launch_bounds__(256) void proj_kernel(const float* __restrict__ X, W9 ws) {
    __shared__ float Xs[16][132];
    __shared__ float Ws[16][132];
    __shared__ int ip[128];
    int z = blockIdx.z;
    const float* W = ws.w[z];
    float* Y = g_proj + (size_t)z * SEQ * CD;
    int n0 = blockIdx.x * 128, m0 = blockIdx.y * 128;
    int tid = threadIdx.x;
    int ty = tid >> 4, tx = tid & 15;
    if (tid < 128) ip[tid] = g_iperm[m0 + tid];
    float acc[8][8] = {};
    for (int k0 = 0; k0 < CD; k0 += 16) {
        #pragma unroll
        for (int e = 0; e < 8; e++) {
            int lin = tid + e * 256;
            int r = lin >> 4, c = lin & 15;
            Xs[c][r] = X[(size_t)(m0 + r) * CD + k0 + c];
            Ws[c][r] = W[(size_t)(n0 + r) * CD + k0 + c];
        }
        __syncthreads();
        #pragma unroll
        for (int kk = 0; kk < 16; kk++) {
            float a[8], b[8];
            *(float4*)&a[0] = *(float4*)&Xs[kk][ty * 8];
            *(float4*)&a[4] = *(float4*)&Xs[kk][ty * 8 + 4];
            *(float4*)&b[0] = *(float4*)&Ws[kk][tx * 8];
            *(float4*)&b[4] = *(float4*)&Ws[kk][tx * 8 + 4];
            #pragma unroll
            for (int i = 0; i < 8; i++)
                #pragma unroll
                for (int j = 0; j < 8; j++)
                    acc[i][j] += a[i] * b[j];
        }
        __syncthreads();
    }
    #pragma unroll
    for (int i = 0; i < 8; i++) {
        size_t row = (size_t)ip[ty * 8 + i] * CD + n0;
        #pragma unroll
        for (int j = 0; j < 8; j++)
            Y[row + tx * 8 + j] = acc[i][j];
    }
}

// ---------------------------------------------------------------------------
// grouped scores: S = Qp Kp^T * scale, 128x128 tile, 8x8 micro
// grid: (q-tiles<=40, 32 k-tiles, heads)
// ---------------------------------------------------------------------------
__global__ __launch_bounds__(256) void scores_kernel(int qsel, int ksel, int zbase,
                                                     int headDim, float scale,
                                                     int useOut) {
    __shared__ float Qs[16][136];
    __shared__ float Ks[16][136];
    int qt = blockIdx.x;
    if (qt >= d_nqtiles) return;
    int g = d_qtileG[qt], q0 = d_qtileQ0[qt];
    int cnt = d_cnt[g];
    int len = useOut ? d_cntOut[g] : cnt;
    int k0 = blockIdx.y * 128;
    if (k0 >= len) return;
    int off = d_off[g];
    int stride = d_cntPad[g];
    int z = blockIdx.z;
    const float* Q = g_proj + (size_t)qsel * SEQ * CD;
    const float* K = g_proj + (size_t)ksel * SEQ * CD;
    float* Sc = g_scores + (size_t)(zbase + z) * MATSZ + (size_t)d_scbase[g];
    int tid = threadIdx.x;
    int ty = tid >> 4, tx = tid & 15;
    float acc[8][8] = {};
    for (int kb = 0; kb < headDim; kb += 16) {
        int colb = z * headDim + kb;
        #pragma unroll
        for (int e = 0; e < 8; e++) {
            int lin = tid + e * 256;
            int r = lin >> 4, c = lin & 15;
            Qs[c][r] = (q0 + r < cnt) ? Q[(size_t)(off + q0 + r) * CD + colb + c] : 0.f;
            Ks[c][r] = (k0 + r < len) ? K[(size_t)(off + k0 + r) * CD + colb + c] : 0.f;
        }
        __syncthreads();
        #pragma unroll
        for (int kk = 0; kk < 16; kk++) {
            float a[8], b[8];
            *(float4*)&a[0] = *(float4*)&Qs[kk][ty * 8];
            *(float4*)&a[4] = *(float4*)&Qs[kk][ty * 8 + 4];
            *(float4*)&b[0] = *(float4*)&Ks[kk][tx * 8];
            *(float4*)&b[4] = *(float4*)&Ks[kk][tx * 8 + 4];
            #pragma unroll
            for (int i = 0; i < 8; i++)
                #pragma unroll
                for (int j = 0; j < 8; j++)
                    acc[i][j] += a[i] * b[j];
        }
        __syncthreads();
    }
    #pragma unroll
    for (int i = 0; i < 8; i++) {
        int r = q0 + ty * 8 + i;
        if (r >= cnt) continue;
        #pragma unroll
        for (int j = 0; j < 8; j++) {
            int c = k0 + tx * 8 + j;
            if (c < len)
                Sc[(size_t)r * stride + c] = acc[i][j] * scale;
        }
    }
}

// ---------------------------------------------------------------------------
// grouped row softmax (length = group size or outside-prefix size)
// ---------------------------------------------------------------------------
__global__ __launch_bounds__(256) void softmax_kernel() {
    __shared__ float buf[SEQ];
    __shared__ float red[256];
    int row = blockIdx.x, z = blockIdx.y;
    int g = d_rowg[row], rl = d_rowloc[row];
    int len = (z >= 9) ? d_cntOut[g] : d_cnt[g];
    if (len == 0) return;
    float* p = g_scores + (size_t)z * MATSZ + (size_t)d_scbase[g]
             + (size_t)rl * d_cntPad[g];
    int tid = threadIdx.x;
    float mx = -INFINITY;
    for (int i = tid; i < len; i += 256) { float v = p[i]; buf[i] = v; mx = fmaxf(mx, v); }
    red[tid] = mx; __syncthreads();
    for (int s = 128; s > 0; s >>= 1) {
        if (tid < s) red[tid] = fmaxf(red[tid], red[tid + s]);
        __syncthreads();
    }
    mx = red[0]; __syncthreads();
    float sum = 0.f;
    for (int i = tid; i < len; i += 256) { float e = __expf(buf[i] - mx); buf[i] = e; sum += e; }
    red[tid] = sum; __syncthreads();
    for (int s = 128; s > 0; s >>= 1) {
        if (tid < s) red[tid] += red[tid + s];
        __syncthreads();
    }
    float inv = 1.0f / red[0];
    for (int i = tid; i < len; i += 256) p[i] = buf[i] * inv;
}

// ---------------------------------------------------------------------------
// grouped AV: Out[:, c0:c0+80] (+)= P(group) @ Vp(group), 128x80 tile, 8x5
// grid: (q-tiles<=40, col-chunks, heads)
// ---------------------------------------------------------------------------
__global__ __launch_bounds__(256) void av_kernel(int zbase, int vsel, int headDim,
                                                 int accumulate, int useOut) {
    __shared__ float Ps[16][132];
    __shared__ float Vs[16][80];
    int qt = blockIdx.x;
    if (qt >= d_nqtiles) return;
    int g = d_qtileG[qt], q0 = d_qtileQ0[qt];
    int cnt = d_cnt[g];
    int len = useOut ? d_cntOut[g] : cnt;
    if (len == 0) return;
    int off = d_off[g];
    int stride = d_cntPad[g];
    int z = blockIdx.z;
    int c0 = z * headDim + blockIdx.y * 80;
    const float* P = g_scores + (size_t)(zbase + z) * MATSZ + (size_t)d_scbase[g];
    const float* V = g_proj + (size_t)vsel * SEQ * CD;
    int tid = threadIdx.x;
    int ty = tid >> 4, tx = tid & 15;
    float acc[8][5] = {};
    for (int k0 = 0; k0 < len; k0 += 16) {
        #pragma unroll
        for (int e = 0; e < 8; e++) {
            int lin = tid + e * 256;
            int r = lin >> 4, c = lin & 15;
            bool ok = (q0 + r < cnt) && (k0 + c < len);
            Ps[c][r] = ok ? P[(size_t)(q0 + r) * stride + k0 + c] : 0.f;
        }
        #pragma unroll
        for (int e = 0; e < 5; e++) {
            int lin = tid + e * 256;
            int r = lin / 80, c = lin % 80;
            Vs[r][c] = (k0 + r < len) ? V[(size_t)(off + k0 + r) * CD + c0 + c] : 0.f;
        }
        __syncthreads();
        #pragma unroll
        for (int kk = 0; kk < 16; kk++) {
            float pr[8], vr[5];
            *(float4*)&pr[0] = *(float4*)&Ps[kk][ty * 8];
            *(float4*)&pr[4] = *(float4*)&Ps[kk][ty * 8 + 4];
            #pragma unroll
            for (int j = 0; j < 5; j++) vr[j] = Vs[kk][tx * 5 + j];
            #pragma unroll
            for (int i = 0; i < 8; i++)
                #pragma unroll
                for (int j = 0; j < 5; j++)
                    acc[i][j] += pr[i] * vr[j];
        }
        __syncthreads();
    }
    #pragma unroll
    for (int i = 0; i < 8; i++) {
        int r = q0 + ty * 8 + i;
        if (r >= cnt) continue;
        #pragma unroll
        for (int j = 0; j < 5; j++) {
            size_t o = (size_t)(off + r) * CD + c0 + tx * 5 + j;
            if (accumulate) g_hs[o] += acc[i][j];
            else            g_hs[o] = acc[i][j];
        }
    }
}

// ---------------------------------------------------------------------------
// fallback mean of V_out rows: parallel, coalesced
// ---------------------------------------------------------------------------
__global__ void meanv_kernel() {
    int col = threadIdx.x;                       // 0..639
    const float* V = g_proj + 8ull * SEQ * CD;
    int r0 = blockIdx.x * 256;
    float s = 0.f;
    for (int r = 0; r < 256; r++) s += V[(size_t)(r0 + r) * CD + col];
    atomicAdd(&g_meanVo[col], s * (1.0f / SEQ));
}

__global__ void fb_kernel() {
    int row = blockIdx.x;
    int g = d_rowg[row];
    if (d_cntOut[g] != 0) return;
    for (int c = threadIdx.x; c < CD; c += 256)
        g_hs[(size_t)row * CD + c] += g_meanVo[c];
}

// ---------------------------------------------------------------------------
// final: out[m] = hs_p[iperm[m]] @ Wo^T + residual[m]   128x128, 8x8 micro
// ---------------------------------------------------------------------------
__global__ __launch_bounds__(256) void final_kernel(const float* __restrict__ Wo,
                                                    const float* __restrict__ resid,
                                                    float* __restrict__ Y) {
    __shared__ float Xs[16][132];
    __shared__ float Ws[16][132];
    __shared__ int ip[128];
    int n0 = blockIdx.x * 128, m0 = blockIdx.y * 128;
    int tid = threadIdx.x;
    int ty = tid >> 4, tx = tid & 15;
    if (tid < 128) ip[tid] = g_iperm[m0 + tid];
    __syncthreads();
    float acc[8][8] = {};
    for (int k0 = 0; k0 < CD; k0 += 16) {
        #pragma unroll
        for (int e = 0; e < 8; e++) {
            int lin = tid + e * 256;
            int r = lin >> 4, c = lin & 15;
            Xs[c][r] = g_hs[(size_t)ip[r] * CD + k0 + c];
            Ws[c][r] = Wo[(size_t)(n0 + r) * CD + k0 + c];
        }
        __syncthreads();
        #pragma unroll
        for (int kk = 0; kk < 16; kk++) {
            float a[8], b[8];
            *(float4*)&a[0] = *(float4*)&Xs[kk][ty * 8];
            *(float4*)&a[4] = *(float4*)&Xs[kk][ty * 8 + 4];
            *(float4*)&b[0] = *(float4*)&Ws[kk][tx * 8];
            *(float4*)&b[4] = *(float4*)&Ws[kk][tx * 8 + 4];
            #pragma unroll
            for (int i = 0; i < 8; i++)
                #pragma unroll
                for (int j = 0; j < 8; j++)
                    acc[i][j] += a[i] * b[j];
        }
        __syncthreads();
    }
    #pragma unroll
    for (int i = 0; i < 8; i++)
        #pragma unroll
        for (int j = 0; j < 8; j++) {
            size_t o = (size_t)(m0 + ty * 8 + i) * CD + n0 + tx * 8 + j;
            Y[o] = acc[i][j] + resid[o];
        }
}

// ---------------------------------------------------------------------------
// launch
// ---------------------------------------------------------------------------
extern "C" void kernel_launch(void* const* d_in, const int* in_sizes, int n_in,
                              void* d_out, int out_size) {
    const float* hidden = (const float*)d_in[0];
    const int*   mask   = (const int*)d_in[1];
    const int*   inp    = (const int*)d_in[2];
    W9 ws;
    for (int i = 0; i < 9; i++) ws.w[i] = (const float*)d_in[3 + i];
    const float* Wo = (const float*)d_in[12];
    float* out = (float*)d_out;

    const float s80  = 1.0f / sqrtf(80.0f);
    const float s640 = 1.0f / sqrtf(640.0f);

    labels_kernel<<<16, 256>>>(mask, inp);
    prep_kernel<<<1, 256>>>();
    proj_kernel<<<dim3(5, 32, 9), 256>>>(hidden, ws);
    meanv_kernel<<<16, 640>>>();

    // proj indices: 0=q 1=k 2=v 3=q_ent 4=k_ent 5=v_ent 6=q_out 7=k_out 8=v_out
    scores_kernel<<<dim3(40, 32, 8), 256>>>(0, 1, 0, 80,  s80,  0);  // original
    scores_kernel<<<dim3(40, 32, 1), 256>>>(3, 4, 8, 640, s640, 0);  // entity (1 head)
    scores_kernel<<<dim3(40, 32, 8), 256>>>(6, 7, 9, 80,  s80,  1);  // outside

    softmax_kernel<<<dim3(SEQ, 17), 256>>>();

    av_kernel<<<dim3(40, 1, 8), 256>>>(0, 2, 80,  0, 0);  // writes g_hs
    av_kernel<<<dim3(40, 8, 1), 256>>>(8, 5, 640, 1, 0);  // accumulates
    av_kernel<<<dim3(40, 1, 8), 256>>>(9, 8, 80,  1, 1);  // accumulates

    fb_kernel<<<SEQ, 256>>>();
    final_kernel<<<dim3(5, 32, 1), 256>>>(Wo, hidden, out);
}

// round 6
// speedup vs baseline: 5.7354x; 1.5274x over previous
#include <cuda_runtime.h>
#include <math.h>
#include <stdint.h>

#define SEQ 4096
#define CD  640
#define NHD 8
#define HDD 80
#define MATSZ ((size_t)SEQ * SEQ + (1u << 21))   // grouped storage + 128-pad slack

// ---- device scratch (static; no runtime allocation) ----
__device__ float g_proj[9ull * SEQ * CD];          // 9 projections, PERMUTED row order
__device__ float g_scores[17ull * MATSZ];          // 17 grouped score matrices
__device__ float g_hs[(size_t)SEQ * CD];           // attention output, PERMUTED order
__device__ float g_meanVo[CD];                     // column mean of V_out (fallback)
__device__ int   g_lab[SEQ];
__device__ int   g_outs[SEQ];
__device__ int   g_iperm[SEQ];                     // original row -> permuted row
__device__ int   d_off[4], d_cnt[4], d_cntOut[4], d_cntPad[4];
__device__ long long d_scbase[4];
__device__ int   d_qtileG[40], d_qtileQ0[40];
__device__ int   d_nqtiles;
__device__ int   d_rowg[SEQ], d_rowloc[SEQ];

// ---------------------------------------------------------------------------
__device__ __forceinline__ float to_tf32(float x) {
    uint32_t u; asm("cvt.rna.tf32.f32 %0, %1;" : "=r"(u) : "f"(x));
    return __uint_as_float(u);
}

__device__ __forceinline__ void mma_tf32(float d[4], const uint32_t a[4], const uint32_t b[2]) {
    asm volatile(
        "mma.sync.aligned.m16n8k8.row.col.f32.tf32.tf32.f32 "
        "{%0,%1,%2,%3}, {%4,%5,%6,%7}, {%8,%9}, {%0,%1,%2,%3};\n"
        : "+f"(d[0]), "+f"(d[1]), "+f"(d[2]), "+f"(d[3])
        : "r"(a[0]), "r"(a[1]), "r"(a[2]), "r"(a[3]), "r"(b[0]), "r"(b[1]));
}

// ---------------------------------------------------------------------------
// labels: nearest-resize 512x512 -> 64x64 (idx = i*8); also zero meanVo
// ---------------------------------------------------------------------------
__global__ void labels_kernel(const int* __restrict__ mask,
                              const int* __restrict__ inp) {
    int t = blockIdx.x * blockDim.x + threadIdx.x;
    if (t < CD) g_meanVo[t] = 0.f;
    if (t >= SEQ) return;
    int i = t >> 6, j = t & 63;
    int idx = (i * 8) * 512 + j * 8;
    g_lab[t]  = mask[idx];
    g_outs[t] = (inp[idx] == 0) ? 1 : 0;
}

// ---------------------------------------------------------------------------
// prep: bucket sort by (label, !outside); group metadata; 128-wide q-tiles
// ---------------------------------------------------------------------------
__global__ void prep_kernel() {
    __shared__ int cnt8[8], off8[8], cur8[8];
    int tid = threadIdx.x;
    if (tid < 8) cnt8[tid] = 0;
    __syncthreads();
    for (int t = tid; t < SEQ; t += 256) {
        int b = g_lab[t] * 2 + (g_outs[t] ? 0 : 1);
        atomicAdd(&cnt8[b], 1);
    }
    __syncthreads();
    if (tid == 0) {
        int acc = 0;
        for (int b = 0; b < 8; b++) { off8[b] = acc; acc += cnt8[b]; }
        long long sb = 0;
        int nq = 0;
        for (int g = 0; g < 4; g++) {
            int c = cnt8[2 * g] + cnt8[2 * g + 1];
            d_cnt[g] = c;
            d_cntOut[g] = cnt8[2 * g];
            d_off[g] = off8[2 * g];
            int pad = ((c + 127) >> 7) << 7;
            d_cntPad[g] = pad;
            d_scbase[g] = sb;
            sb += (long long)pad * pad;
            for (int j = 0; j < c; j += 128) { d_qtileG[nq] = g; d_qtileQ0[nq] = j; nq++; }
        }
        d_nqtiles = nq;
    }
    __syncthreads();
    if (tid < 8) cur8[tid] = off8[tid];
    __syncthreads();
    for (int t = tid; t < SEQ; t += 256) {
        int b = g_lab[t] * 2 + (g_outs[t] ? 0 : 1);
        int pos = atomicAdd(&cur8[b], 1);
        g_iperm[t] = pos;
    }
    __syncthreads();
    for (int i = tid; i < SEQ; i += 256) {
        int g = 3;
        if      (i < d_off[1]) g = 0;
        else if (i < d_off[2]) g = 1;
        else if (i < d_off[3]) g = 2;
        d_rowg[i] = g;
        d_rowloc[i] = i - d_off[g];
    }
}

// ---------------------------------------------------------------------------
// 9 projections via tf32 mma: Y_z[iperm[m]] = (X @ W_z^T)[m]   128x128 tiles
// ---------------------------------------------------------------------------
struct W9 { const float* w[9]; };

__global__ __launch_bounds__(256) void proj_kernel(const float* __restrict__ X, W9 ws) {
    __shared__ float Xs[16][136];
    __shared__ float Bs[16][136];
    __shared__ int ip[128];
    int z = blockIdx.z;
    const float* W = ws.w[z];
    float* Y = g_proj + (size_t)z * SEQ * CD;
    int n0 = blockIdx.x * 128, m0 = blockIdx.y * 128;
    int tid = threadIdx.x, lane = tid & 31, warp = tid >> 5;
    int wm = warp & 3, wn = warp >> 2;
    if (tid < 128) ip[tid] = g_iperm[m0 + tid];
    float acc[2][8][4] = {};
    for (int k0 = 0; k0 < CD; k0 += 16) {
        #pragma unroll
        for (int e = 0; e < 8; e++) {
            int lin = tid + e * 256;
            int r = lin >> 4, c = lin & 15;
            Xs[c][r] = to_tf32(X[(size_t)(m0 + r) * CD + k0 + c]);
            Bs[c][r] = to_tf32(W[(size_t)(n0 + r) * CD + k0 + c]);
        }
        __syncthreads();
        #pragma unroll
        for (int k8 = 0; k8 < 16; k8 += 8) {
            uint32_t a[2][4];
            int ar = wm * 32 + (lane >> 2), ac = k8 + (lane & 3);
            #pragma unroll
            for (int i = 0; i < 2; i++) {
                a[i][0] = __float_as_uint(Xs[ac][ar + i * 16]);
                a[i][1] = __float_as_uint(Xs[ac][ar + i * 16 + 8]);
                a[i][2] = __float_as_uint(Xs[ac + 4][ar + i * 16]);
                a[i][3] = __float_as_uint(Xs[ac + 4][ar + i * 16 + 8]);
            }
            #pragma unroll
            for (int j = 0; j < 8; j++) {
                uint32_t b[2];
                int bc = wn * 64 + j * 8 + (lane >> 2);
                b[0] = __float_as_uint(Bs[ac][bc]);
                b[1] = __float_as_uint(Bs[ac + 4][bc]);
                mma_tf32(acc[0][j], a[0], b);
                mma_tf32(acc[1][j], a[1], b);
            }
        }
        __syncthreads();
    }
    int mi = wm * 32 + (lane >> 2);
    int nc = n0 + wn * 64 + 2 * (lane & 3);
    #pragma unroll
    for (int i = 0; i < 2; i++) {
        size_t row0 = (size_t)ip[mi + i * 16] * CD;
        size_t row1 = (size_t)ip[mi + i * 16 + 8] * CD;
        #pragma unroll
        for (int j = 0; j < 8; j++) {
            int c = nc + j * 8;
            *(float2*)&Y[row0 + c] = make_float2(acc[i][j][0], acc[i][j][1]);
            *(float2*)&Y[row1 + c] = make_float2(acc[i][j][2], acc[i][j][3]);
        }
    }
}

// ---------------------------------------------------------------------------
// grouped scores via tf32 mma: S = Qp Kp^T * scale   128x128 tiles
// ---------------------------------------------------------------------------
__global__ __launch_bounds__(256) void scores_kernel(int qsel, int ksel, int zbase,
                                                     int headDim, float scale,
                                                     int useOut) {
    __shared__ float Qs[16][136];
    __shared__ float Ks[16][136];
    int qt = blockIdx.x;
    if (qt >= d_nqtiles) return;
    int g = d_qtileG[qt], q0 = d_qtileQ0[qt];
    int cnt = d_cnt[g];
    int len = useOut ? d_cntOut[g] : cnt;
    int k0 = blockIdx.y * 128;
    if (k0 >= len) return;
    int off = d_off[g];
    int stride = d_cntPad[g];
    int z = blockIdx.z;
    const float* Q = g_proj + (size_t)qsel * SEQ * CD;
    const float* K = g_proj + (size_t)ksel * SEQ * CD;
    float* Sc = g_scores + (size_t)(zbase + z) * MATSZ + (size_t)d_scbase[g];
    int tid = threadIdx.x, lane = tid & 31, warp = tid >> 5;
    int wm = warp & 3, wn = warp >> 2;
    float acc[2][8][4] = {};
    for (int kb = 0; kb < headDim; kb += 16) {
        int colb = z * headDim + kb;
        #pragma unroll
        for (int e = 0; e < 8; e++) {
            int lin = tid + e * 256;
            int r = lin >> 4, c = lin & 15;
            float qv = (q0 + r < cnt) ? Q[(size_t)(off + q0 + r) * CD + colb + c] : 0.f;
            float kv = (k0 + r < len) ? K[(size_t)(off + k0 + r) * CD + colb + c] : 0.f;
            Qs[c][r] = to_tf32(qv);
            Ks[c][r] = to_tf32(kv);
        }
        __syncthreads();
        #pragma unroll
        for (int k8 = 0; k8 < 16; k8 += 8) {
            uint32_t a[2][4];
            int ar = wm * 32 + (lane >> 2), ac = k8 + (lane & 3);
            #pragma unroll
            for (int i = 0; i < 2; i++) {
                a[i][0] = __float_as_uint(Qs[ac][ar + i * 16]);
                a[i][1] = __float_as_uint(Qs[ac][ar + i * 16 + 8]);
                a[i][2] = __float_as_uint(Qs[ac + 4][ar + i * 16]);
                a[i][3] = __float_as_uint(Qs[ac + 4][ar + i * 16 + 8]);
            }
            #pragma unroll
            for (int j = 0; j < 8; j++) {
                uint32_t b[2];
                int bc = wn * 64 + j * 8 + (lane >> 2);
                b[0] = __float_as_uint(Ks[ac][bc]);
                b[1] = __float_as_uint(Ks[ac + 4][bc]);
                mma_tf32(acc[0][j], a[0], b);
                mma_tf32(acc[1][j], a[1], b);
            }
        }
        __syncthreads();
    }
    // unconditional writes: padding region is allocated and never read
    int mr = q0 + wm * 32 + (lane >> 2);
    int nc = k0 + wn * 64 + 2 * (lane & 3);
    #pragma unroll
    for (int i = 0; i < 2; i++) {
        int r0 = mr + i * 16;
        #pragma unroll
        for (int j = 0; j < 8; j++) {
            int c = nc + j * 8;
            *(float2*)&Sc[(size_t)r0 * stride + c] =
                make_float2(acc[i][j][0] * scale, acc[i][j][1] * scale);
            *(float2*)&Sc[(size_t)(r0 + 8) * stride + c] =
                make_float2(acc[i][j][2] * scale, acc[i][j][3] * scale);
        }
    }
}

// ---------------------------------------------------------------------------
// grouped row softmax
// ---------------------------------------------------------------------------
__global__ __launch_bounds__(256) void softmax_kernel() {
    __shared__ float buf[SEQ];
    __shared__ float red[256];
    int row = blockIdx.x, z = blockIdx.y;
    int g = d_rowg[row], rl = d_rowloc[row];
    int len = (z >= 9) ? d_cntOut[g] : d_cnt[g];
    if (len == 0) return;
    float* p = g_scores + (size_t)z * MATSZ + (size_t)d_scbase[g]
             + (size_t)rl * d_cntPad[g];
    int tid = threadIdx.x;
    float mx = -INFINITY;
    for (int i = tid; i < len; i += 256) { float v = p[i]; buf[i] = v; mx = fmaxf(mx, v); }
    red[tid] = mx; __syncthreads();
    for (int s = 128; s > 0; s >>= 1) {
        if (tid < s) red[tid] = fmaxf(red[tid], red[tid + s]);
        __syncthreads();
    }
    mx = red[0]; __syncthreads();
    float sum = 0.f;
    for (int i = tid; i < len; i += 256) { float e = __expf(buf[i] - mx); buf[i] = e; sum += e; }
    red[tid] = sum; __syncthreads();
    for (int s = 128; s > 0; s >>= 1) {
        if (tid < s) red[tid] += red[tid + s];
        __syncthreads();
    }
    float inv = 1.0f / red[0];
    for (int i = tid; i < len; i += 256) p[i] = buf[i] * inv;
}

// ---------------------------------------------------------------------------
// grouped AV via tf32 mma: Out[:, c0:c0+80] (+)= P @ V   128x80 tiles
// ---------------------------------------------------------------------------
__global__ __launch_bounds__(256) void av_kernel(int zbase, int vsel, int headDim,
                                                 int accumulate, int useOut) {
    __shared__ float Ps[16][136];
    __shared__ float Vs[16][88];
    int qt = blockIdx.x;
    if (qt >= d_nqtiles) return;
    int g = d_qtileG[qt], q0 = d_qtileQ0[qt];
    int cnt = d_cnt[g];
    int len = useOut ? d_cntOut[g] : cnt;
    if (len == 0) return;
    int off = d_off[g];
    int stride = d_cntPad[g];
    int z = blockIdx.z;
    int c0 = z * headDim + blockIdx.y * 80;
    const float* P = g_scores + (size_t)(zbase + z) * MATSZ + (size_t)d_scbase[g];
    const float* V = g_proj + (size_t)vsel * SEQ * CD;
    int tid = threadIdx.x, lane = tid & 31, warp = tid >> 5;
    int wm = warp & 3, wn = warp >> 2;
    float acc[2][5][4] = {};
    for (int k0 = 0; k0 < len; k0 += 16) {
        #pragma unroll
        for (int e = 0; e < 8; e++) {
            int lin = tid + e * 256;
            int r = lin >> 4, c = lin & 15;
            float pv = (k0 + c < len) ? P[(size_t)(q0 + r) * stride + k0 + c] : 0.f;
            Ps[c][r] = to_tf32(pv);
        }
        #pragma unroll
        for (int e = 0; e < 5; e++) {
            int lin = tid + e * 256;
            int r = lin / 80, c = lin % 80;
            float vv = (k0 + r < len) ? V[(size_t)(off + k0 + r) * CD + c0 + c] : 0.f;
            Vs[r][c] = to_tf32(vv);
        }
        __syncthreads();
        #pragma unroll
        for (int k8 = 0; k8 < 16; k8 += 8) {
            uint32_t a[2][4];
            int ar = wm * 32 + (lane >> 2), ac = k8 + (lane & 3);
            #pragma unroll
            for (int i = 0; i < 2; i++) {
                a[i][0] = __float_as_uint(Ps[ac][ar + i * 16]);
                a[i][1] = __float_as_uint(Ps[ac][ar + i * 16 + 8]);
                a[i][2] = __float_as_uint(Ps[ac + 4][ar + i * 16]);
                a[i][3] = __float_as_uint(Ps[ac + 4][ar + i * 16 + 8]);
            }
            #pragma unroll
            for (int j = 0; j < 5; j++) {
                uint32_t b[2];
                int bc = wn * 40 + j * 8 + (lane >> 2);
                b[0] = __float_as_uint(Vs[ac][bc]);
                b[1] = __float_as_uint(Vs[ac + 4][bc]);
                mma_tf32(acc[0][j], a[0], b);
                mma_tf32(acc[1][j], a[1], b);
            }
        }
        __syncthreads();
    }
    int mi = wm * 32 + (lane >> 2);
    int nc = c0 + wn * 40 + 2 * (lane & 3);
    #pragma unroll
    for (int i = 0; i < 2; i++) {
        int r0 = q0 + mi + i * 16;
        int r1 = r0 + 8;
        #pragma unroll
        for (int j = 0; j < 5; j++) {
            int c = nc + j * 8;
            if (r0 < cnt) {
                size_t o = (size_t)(off + r0) * CD + c;
                if (accumulate) { g_hs[o] += acc[i][j][0]; g_hs[o + 1] += acc[i][j][1]; }
                else            { g_hs[o]  = acc[i][j][0]; g_hs[o + 1]  = acc[i][j][1]; }
            }
            if (r1 < cnt) {
                size_t o = (size_t)(off + r1) * CD + c;
                if (accumulate) { g_hs[o] += acc[i][j][2]; g_hs[o + 1] += acc[i][j][3]; }
                else            { g_hs[o]  = acc[i][j][2]; g_hs[o + 1]  = acc[i][j][3]; }
            }
        }
    }
}

// ---------------------------------------------------------------------------
// fallback mean of V_out rows
// ---------------------------------------------------------------------------
__global__ void meanv_kernel() {
    int col = threadIdx.x;
    const float* V = g_proj + 8ull * SEQ * CD;
    int r0 = blockIdx.x * 256;
    float s = 0.f;
    for (int r = 0; r < 256; r++) s += V[(size_t)(r0 + r) * CD + col];
    atomicAdd(&g_meanVo[col], s * (1.0f / SEQ));
}

__global__ void fb_kernel() {
    int row = blockIdx.x;
    int g = d_rowg[row];
    if (d_cntOut[g] != 0) return;
    for (int c = threadIdx.x; c < CD; c += 256)
        g_hs[(size_t)row * CD + c] += g_meanVo[c];
}

// ---------------------------------------------------------------------------
// final via tf32 mma: out[m] = hs_p[iperm[m]] @ Wo^T + residual[m]
// ---------------------------------------------------------------------------
__global__ __launch_bounds__(256) void final_kernel(const float* __restrict__ Wo,
                                                    const float* __restrict__ resid,
                                                    float* __restrict__ Y) {
    __shared__ float Xs[16][136];
    __shared__ float Bs[16][136];
    __shared__ int ip[128];
    int n0 = blockIdx.x * 128, m0 = blockIdx.y * 128;
    int tid = threadIdx.x, lane = tid & 31, warp = tid >> 5;
    int wm = warp & 3, wn = warp >> 2;
    if (tid < 128) ip[tid] = g_iperm[m0 + tid];
    __syncthreads();
    float acc[2][8][4] = {};
    for (int k0 = 0; k0 < CD; k0 += 16) {
        #pragma unroll
        for (int e = 0; e < 8; e++) {
            int lin = tid + e * 256;
            int r = lin >> 4, c = lin & 15;
            Xs[c][r] = to_tf32(g_hs[(size_t)ip[r] * CD + k0 + c]);
            Bs[c][r] = to_tf32(Wo[(size_t)(n0 + r) * CD + k0 + c]);
        }
        __syncthreads();
        #pragma unroll
        for (int k8 = 0; k8 < 16; k8 += 8) {
            uint32_t a[2][4];
            int ar = wm * 32 + (lane >> 2), ac = k8 + (lane & 3);
            #pragma unroll
            for (int i = 0; i < 2; i++) {
                a[i][0] = __float_as_uint(Xs[ac][ar + i * 16]);
                a[i][1] = __float_as_uint(Xs[ac][ar + i * 16 + 8]);
                a[i][2] = __float_as_uint(Xs[ac + 4][ar + i * 16]);
                a[i][3] = __float_as_uint(Xs[ac + 4][ar + i * 16 + 8]);
            }
            #pragma unroll
            for (int j = 0; j < 8; j++) {
                uint32_t b[2];
                int bc = wn * 64 + j * 8 + (lane >> 2);
                b[0] = __float_as_uint(Bs[ac][bc]);
                b[1] = __float_as_uint(Bs[ac + 4][bc]);
                mma_tf32(acc[0][j], a[0], b);
                mma_tf32(acc[1][j], a[1], b);
            }
        }
        __syncthreads();
    }
    int mi = wm * 32 + (lane >> 2);
    int nc = n0 + wn * 64 + 2 * (lane & 3);
    #pragma unroll
    for (int i = 0; i < 2; i++) {
        #pragma unroll
        for (int j = 0; j < 8; j++) {
            int c = nc + j * 8;
            size_t o0 = (size_t)(m0 + mi + i * 16) * CD + c;
            size_t o1 = (size_t)(m0 + mi + i * 16 + 8) * CD + c;
            Y[o0]     = acc[i][j][0] + resid[o0];
            Y[o0 + 1] = acc[i][j][1] + resid[o0 + 1];
            Y[o1]     = acc[i][j][2] + resid[o1];
            Y[o1 + 1] = acc[i][j][3] + resid[o1 + 1];
        }
    }
}

// ---------------------------------------------------------------------------
// launch
// ---------------------------------------------------------------------------
extern "C" void kernel_launch(void* const* d_in, const int* in_sizes, int n_in,
                              void* d_out, int out_size) {
    const float* hidden = (const float*)d_in[0];
    const int*   mask   = (const int*)d_in[1];
    const int*   inp    = (const int*)d_in[2];
    W9 ws;
    for (int i = 0; i < 9; i++) ws.w[i] = (const float*)d_in[3 + i];
    const float* Wo = (const float*)d_in[12];
    float* out = (float*)d_out;

    const float s80  = 1.0f / sqrtf(80.0f);
    const float s640 = 1.0f / sqrtf(640.0f);

    labels_kernel<<<16, 256>>>(mask, inp);
    prep_kernel<<<1, 256>>>();
    proj_kernel<<<dim3(5, 32, 9), 256>>>(hidden, ws);
    meanv_kernel<<<16, 640>>>();

    // proj indices: 0=q 1=k 2=v 3=q_ent 4=k_ent 5=v_ent 6=q_out 7=k_out 8=v_out
    scores_kernel<<<dim3(40, 32, 8), 256>>>(0, 1, 0, 80,  s80,  0);  // original
    scores_kernel<<<dim3(40, 32, 1), 256>>>(3, 4, 8, 640, s640, 0);  // entity (1 head)
    scores_kernel<<<dim3(40, 32, 8), 256>>>(6, 7, 9, 80,  s80,  1);  // outside

    softmax_kernel<<<dim3(SEQ, 17), 256>>>();

    av_kernel<<<dim3(40, 1, 8), 256>>>(0, 2, 80,  0, 0);  // writes g_hs
    av_kernel<<<dim3(40, 8, 1), 256>>>(8, 5, 640, 1, 0);  // accumulates
    av_kernel<<<dim3(40, 1, 8), 256>>>(9, 8, 80,  1, 1);  // accumulates

    fb_kernel<<<SEQ, 256>>>();
    final_kernel<<<dim3(5, 32, 1), 256>>>(Wo, hidden, out);
}

// round 7
// speedup vs baseline: 12.7197x; 2.2178x over previous
#include <cuda_runtime.h>
#include <math.h>
#include <stdint.h>

#define SEQ 4096
#define CD  640
#define NHD 8
#define HDD 80
#define MATSZ ((size_t)SEQ * SEQ + (1u << 21))   // grouped storage + 128-pad slack

// ---- device scratch (static; no runtime allocation) ----
__device__ float g_proj[9ull * SEQ * CD];          // 9 projections, PERMUTED row order
__device__ float g_scores[17ull * MATSZ];          // 17 grouped score matrices
__device__ float g_hs[(size_t)SEQ * CD];           // attention output, PERMUTED order
__device__ float g_meanVo[CD];                     // column mean of V_out (fallback)
__device__ int   g_lab[SEQ];
__device__ int   g_outs[SEQ];
__device__ int   g_iperm[SEQ];                     // original row -> permuted row
__device__ int   d_off[4], d_cnt[4], d_cntOut[4], d_cntPad[4];
__device__ long long d_scbase[4];
__device__ int   d_qtileG[40], d_qtileQ0[40];
__device__ int   d_nqtiles;
__device__ int   d_rowg[SEQ], d_rowloc[SEQ];

// ---------------------------------------------------------------------------
__device__ __forceinline__ void mma_tf32(float d[4], const uint32_t a[4], const uint32_t b[2]) {
    asm volatile(
        "mma.sync.aligned.m16n8k8.row.col.f32.tf32.tf32.f32 "
        "{%0,%1,%2,%3}, {%4,%5,%6,%7}, {%8,%9}, {%0,%1,%2,%3};\n"
        : "+f"(d[0]), "+f"(d[1]), "+f"(d[2]), "+f"(d[3])
        : "r"(a[0]), "r"(a[1]), "r"(a[2]), "r"(a[3]), "r"(b[0]), "r"(b[1]));
}

__device__ __forceinline__ uint32_t smem_u32(const void* p) {
    return (uint32_t)__cvta_generic_to_shared(p);
}
__device__ __forceinline__ void cp16(uint32_t dst, const void* src, int nbytes) {
    asm volatile("cp.async.cg.shared.global [%0], [%1], 16, %2;\n"
                 :: "r"(dst), "l"(src), "r"(nbytes));
}
#define CP_COMMIT() asm volatile("cp.async.commit_group;\n")
#define CP_WAIT1()  asm volatile("cp.async.wait_group 1;\n")

// ---------------------------------------------------------------------------
// labels: nearest-resize 512x512 -> 64x64 (idx = i*8); also zero meanVo
// ---------------------------------------------------------------------------
__global__ void labels_kernel(const int* __restrict__ mask,
                              const int* __restrict__ inp) {
    int t = blockIdx.x * blockDim.x + threadIdx.x;
    if (t < CD) g_meanVo[t] = 0.f;
    if (t >= SEQ) return;
    int i = t >> 6, j = t & 63;
    int idx = (i * 8) * 512 + j * 8;
    g_lab[t]  = mask[idx];
    g_outs[t] = (inp[idx] == 0) ? 1 : 0;
}

// ---------------------------------------------------------------------------
// prep: bucket sort by (label, !outside); group metadata; 128-wide q-tiles
// ---------------------------------------------------------------------------
__global__ void prep_kernel() {
    __shared__ int cnt8[8], off8[8], cur8[8];
    int tid = threadIdx.x;
    if (tid < 8) cnt8[tid] = 0;
    __syncthreads();
    for (int t = tid; t < SEQ; t += 256) {
        int b = g_lab[t] * 2 + (g_outs[t] ? 0 : 1);
        atomicAdd(&cnt8[b], 1);
    }
    __syncthreads();
    if (tid == 0) {
        int acc = 0;
        for (int b = 0; b < 8; b++) { off8[b] = acc; acc += cnt8[b]; }
        long long sb = 0;
        int nq = 0;
        for (int g = 0; g < 4; g++) {
            int c = cnt8[2 * g] + cnt8[2 * g + 1];
            d_cnt[g] = c;
            d_cntOut[g] = cnt8[2 * g];
            d_off[g] = off8[2 * g];
            int pad = ((c + 127) >> 7) << 7;
            d_cntPad[g] = pad;
            d_scbase[g] = sb;
            sb += (long long)pad * pad;
            for (int j = 0; j < c; j += 128) { d_qtileG[nq] = g; d_qtileQ0[nq] = j; nq++; }
        }
        d_nqtiles = nq;
    }
    __syncthreads();
    if (tid < 8) cur8[tid] = off8[tid];
    __syncthreads();
    for (int t = tid; t < SEQ; t += 256) {
        int b = g_lab[t] * 2 + (g_outs[t] ? 0 : 1);
        int pos = atomicAdd(&cur8[b], 1);
        g_iperm[t] = pos;
    }
    __syncthreads();
    for (int i = tid; i < SEQ; i += 256) {
        int g = 3;
        if      (i < d_off[1]) g = 0;
        else if (i < d_off[2]) g = 1;
        else if (i < d_off[3]) g = 2;
        d_rowg[i] = g;
        d_rowloc[i] = i - d_off[g];
    }
}

// ---------------------------------------------------------------------------
// 9 projections via tf32 mma + cp.async pipeline: 128x128 tiles
// SMEM row-major, stride 20 floats (80B, 16B-aligned, conflict-free frags)
// ---------------------------------------------------------------------------
struct W9 { const float* w[9]; };

__global__ __launch_bounds__(256) void proj_kernel(const float* __restrict__ X, W9 ws) {
    __shared__ float Xs[2][128 * 20];
    __shared__ float Bs[2][128 * 20];
    __shared__ int ip[128];
    int z = blockIdx.z;
    const float* W = ws.w[z];
    float* Y = g_proj + (size_t)z * SEQ * CD;
    int n0 = blockIdx.x * 128, m0 = blockIdx.y * 128;
    int tid = threadIdx.x, lane = tid & 31, warp = tid >> 5;
    int wm = warp & 3, wn = warp >> 2;
    if (tid < 128) ip[tid] = g_iperm[m0 + tid];
    uint32_t xb = smem_u32(Xs), bb = smem_u32(Bs);

    // stage slab 0
    for (int ch = tid; ch < 512; ch += 256) {
        int r = ch >> 2, c4 = (ch & 3) * 4;
        cp16(xb + (r * 20 + c4) * 4, X + (size_t)(m0 + r) * CD + c4, 16);
        cp16(bb + (r * 20 + c4) * 4, W + (size_t)(n0 + r) * CD + c4, 16);
    }
    CP_COMMIT();

    float acc[2][8][4] = {};
    for (int s = 0; s < 40; s++) {
        if (s + 1 < 40) {
            int k0 = (s + 1) * 16;
            int bo = ((s + 1) & 1) * 2560;
            for (int ch = tid; ch < 512; ch += 256) {
                int r = ch >> 2, c4 = (ch & 3) * 4;
                cp16(xb + (bo + r * 20 + c4) * 4, X + (size_t)(m0 + r) * CD + k0 + c4, 16);
                cp16(bb + (bo + r * 20 + c4) * 4, W + (size_t)(n0 + r) * CD + k0 + c4, 16);
            }
        }
        CP_COMMIT(); CP_WAIT1();
        __syncthreads();
        const float* Xb = Xs[s & 1];
        const float* Bb = Bs[s & 1];
        #pragma unroll
        for (int k8 = 0; k8 < 16; k8 += 8) {
            int ac = k8 + (lane & 3);
            int ar = wm * 32 + (lane >> 2);
            uint32_t a[2][4];
            #pragma unroll
            for (int i = 0; i < 2; i++) {
                a[i][0] = __float_as_uint(Xb[(ar + i * 16) * 20 + ac]);
                a[i][1] = __float_as_uint(Xb[(ar + i * 16 + 8) * 20 + ac]);
                a[i][2] = __float_as_uint(Xb[(ar + i * 16) * 20 + ac + 4]);
                a[i][3] = __float_as_uint(Xb[(ar + i * 16 + 8) * 20 + ac + 4]);
            }
            #pragma unroll
            for (int j = 0; j < 8; j++) {
                int bc = wn * 64 + j * 8 + (lane >> 2);
                uint32_t b[2];
                b[0] = __float_as_uint(Bb[bc * 20 + ac]);
                b[1] = __float_as_uint(Bb[bc * 20 + ac + 4]);
                mma_tf32(acc[0][j], a[0], b);
                mma_tf32(acc[1][j], a[1], b);
            }
        }
        __syncthreads();
    }
    int mi = wm * 32 + (lane >> 2);
    int nc = n0 + wn * 64 + 2 * (lane & 3);
    #pragma unroll
    for (int i = 0; i < 2; i++) {
        size_t row0 = (size_t)ip[mi + i * 16] * CD;
        size_t row1 = (size_t)ip[mi + i * 16 + 8] * CD;
        #pragma unroll
        for (int j = 0; j < 8; j++) {
            int c = nc + j * 8;
            *(float2*)&Y[row0 + c] = make_float2(acc[i][j][0], acc[i][j][1]);
            *(float2*)&Y[row1 + c] = make_float2(acc[i][j][2], acc[i][j][3]);
        }
    }
}

// ---------------------------------------------------------------------------
// grouped scores via tf32 mma + cp.async pipeline: 128x128 tiles
// ---------------------------------------------------------------------------
__global__ __launch_bounds__(256) void scores_kernel(int qsel, int ksel, int zbase,
                                                     int headDim, float scale,
                                                     int useOut) {
    __shared__ float Qs[2][128 * 20];
    __shared__ float Ks[2][128 * 20];
    int qt = blockIdx.x;
    if (qt >= d_nqtiles) return;
    int g = d_qtileG[qt], q0 = d_qtileQ0[qt];
    int cnt = d_cnt[g];
    int len = useOut ? d_cntOut[g] : cnt;
    int k0t = blockIdx.y * 128;
    if (k0t >= len) return;
    int off = d_off[g];
    int stride = d_cntPad[g];
    int z = blockIdx.z;
    const float* Q = g_proj + (size_t)qsel * SEQ * CD;
    const float* K = g_proj + (size_t)ksel * SEQ * CD;
    float* Sc = g_scores + (size_t)(zbase + z) * MATSZ + (size_t)d_scbase[g];
    int tid = threadIdx.x, lane = tid & 31, warp = tid >> 5;
    int wm = warp & 3, wn = warp >> 2;
    uint32_t qb = smem_u32(Qs), kb = smem_u32(Ks);
    int colBase = z * headDim;
    int NS = headDim / 16;

    // stage slab 0
    for (int ch = tid; ch < 512; ch += 256) {
        int r = ch >> 2, c4 = (ch & 3) * 4;
        int qr = q0 + r, kr = k0t + r;
        int qv = (qr < cnt) ? 16 : 0;
        int kv = (kr < len) ? 16 : 0;
        if (qr >= cnt) qr = cnt - 1;
        if (kr >= len) kr = len - 1;
        cp16(qb + (r * 20 + c4) * 4, Q + (size_t)(off + qr) * CD + colBase + c4, qv);
        cp16(kb + (r * 20 + c4) * 4, K + (size_t)(off + kr) * CD + colBase + c4, kv);
    }
    CP_COMMIT();

    float acc[2][8][4] = {};
    for (int s = 0; s < NS; s++) {
        if (s + 1 < NS) {
            int k0 = colBase + (s + 1) * 16;
            int bo = ((s + 1) & 1) * 2560;
            for (int ch = tid; ch < 512; ch += 256) {
                int r = ch >> 2, c4 = (ch & 3) * 4;
                int qr = q0 + r, kr = k0t + r;
                int qv = (qr < cnt) ? 16 : 0;
                int kv = (kr < len) ? 16 : 0;
                if (qr >= cnt) qr = cnt - 1;
                if (kr >= len) kr = len - 1;
                cp16(qb + (bo + r * 20 + c4) * 4, Q + (size_t)(off + qr) * CD + k0 + c4, qv);
                cp16(kb + (bo + r * 20 + c4) * 4, K + (size_t)(off + kr) * CD + k0 + c4, kv);
            }
        }
        CP_COMMIT(); CP_WAIT1();
        __syncthreads();
        const float* Qb = Qs[s & 1];
        const float* Kb = Ks[s & 1];
        #pragma unroll
        for (int k8 = 0; k8 < 16; k8 += 8) {
            int ac = k8 + (lane & 3);
            int ar = wm * 32 + (lane >> 2);
            uint32_t a[2][4];
            #pragma unroll
            for (int i = 0; i < 2; i++) {
                a[i][0] = __float_as_uint(Qb[(ar + i * 16) * 20 + ac]);
                a[i][1] = __float_as_uint(Qb[(ar + i * 16 + 8) * 20 + ac]);
                a[i][2] = __float_as_uint(Qb[(ar + i * 16) * 20 + ac + 4]);
                a[i][3] = __float_as_uint(Qb[(ar + i * 16 + 8) * 20 + ac + 4]);
            }
            #pragma unroll
            for (int j = 0; j < 8; j++) {
                int bc = wn * 64 + j * 8 + (lane >> 2);
                uint32_t b[2];
                b[0] = __float_as_uint(Kb[bc * 20 + ac]);
                b[1] = __float_as_uint(Kb[bc * 20 + ac + 4]);
                mma_tf32(acc[0][j], a[0], b);
                mma_tf32(acc[1][j], a[1], b);
            }
        }
        __syncthreads();
    }
    // unconditional writes: padding region is allocated and never read
    int mr = q0 + wm * 32 + (lane >> 2);
    int nc = k0t + wn * 64 + 2 * (lane & 3);
    #pragma unroll
    for (int i = 0; i < 2; i++) {
        int r0 = mr + i * 16;
        #pragma unroll
        for (int j = 0; j < 8; j++) {
            int c = nc + j * 8;
            *(float2*)&Sc[(size_t)r0 * stride + c] =
                make_float2(acc[i][j][0] * scale, acc[i][j][1] * scale);
            *(float2*)&Sc[(size_t)(r0 + 8) * stride + c] =
                make_float2(acc[i][j][2] * scale, acc[i][j][3] * scale);
        }
    }
}

// ---------------------------------------------------------------------------
// grouped row softmax
// ---------------------------------------------------------------------------
__global__ __launch_bounds__(256) void softmax_kernel() {
    __shared__ float buf[SEQ];
    __shared__ float red[256];
    int row = blockIdx.x, z = blockIdx.y;
    int g = d_rowg[row], rl = d_rowloc[row];
    int len = (z >= 9) ? d_cntOut[g] : d_cnt[g];
    if (len == 0) return;
    float* p = g_scores + (size_t)z * MATSZ + (size_t)d_scbase[g]
             + (size_t)rl * d_cntPad[g];
    int tid = threadIdx.x;
    float mx = -INFINITY;
    for (int i = tid; i < len; i += 256) { float v = p[i]; buf[i] = v; mx = fmaxf(mx, v); }
    red[tid] = mx; __syncthreads();
    for (int s = 128; s > 0; s >>= 1) {
        if (tid < s) red[tid] = fmaxf(red[tid], red[tid + s]);
        __syncthreads();
    }
    mx = red[0]; __syncthreads();
    float sum = 0.f;
    for (int i = tid; i < len; i += 256) { float e = __expf(buf[i] - mx); buf[i] = e; sum += e; }
    red[tid] = sum; __syncthreads();
    for (int s = 128; s > 0; s >>= 1) {
        if (tid < s) red[tid] += red[tid + s];
        __syncthreads();
    }
    float inv = 1.0f / red[0];
    for (int i = tid; i < len; i += 256) p[i] = buf[i] * inv;
}

// ---------------------------------------------------------------------------
// grouped AV via tf32 mma + cp.async pipeline: 128x80 tiles
// P stride 20 floats; V stride 88 floats (both 16B-aligned rows)
// ---------------------------------------------------------------------------
__global__ __launch_bounds__(256) void av_kernel(int zbase, int vsel, int headDim,
                                                 int accumulate, int useOut) {
    __shared__ float Ps[2][128 * 20];
    __shared__ float Vs[2][16 * 88];
    int qt = blockIdx.x;
    if (qt >= d_nqtiles) return;
    int g = d_qtileG[qt], q0 = d_qtileQ0[qt];
    int cnt = d_cnt[g];
    int len = useOut ? d_cntOut[g] : cnt;
    if (len == 0) return;
    int off = d_off[g];
    int stride = d_cntPad[g];
    int z = blockIdx.z;
    int c0 = z * headDim + blockIdx.y * 80;
    const float* P = g_scores + (size_t)(zbase + z) * MATSZ + (size_t)d_scbase[g];
    const float* V = g_proj + (size_t)vsel * SEQ * CD;
    int tid = threadIdx.x, lane = tid & 31, warp = tid >> 5;
    int wm = warp & 3, wn = warp >> 2;
    uint32_t pb = smem_u32(Ps), vb = smem_u32(Vs);
    int NS = (len + 15) >> 4;

    // stage slab 0  (P: zero-fill junk cols >= len; V: zero-fill rows >= len)
    {
        for (int ch = tid; ch < 512; ch += 256) {
            int r = ch >> 2, c4 = (ch & 3) * 4;
            int nb = (len - c4) * 4;
            nb = nb < 0 ? 0 : (nb > 16 ? 16 : nb);
            cp16(pb + (r * 20 + c4) * 4, P + (size_t)(q0 + r) * stride + c4, nb);
        }
        for (int ch = tid; ch < 320; ch += 256) {
            int r = ch / 20, c4 = (ch % 20) * 4;
            int rv = (r < len) ? 16 : 0;
            int rr = (r < len) ? r : (len - 1);
            cp16(vb + (r * 88 + c4) * 4, V + (size_t)(off + rr) * CD + c0 + c4, rv);
        }
    }
    CP_COMMIT();

    float acc[2][5][4] = {};
    for (int s = 0; s < NS; s++) {
        if (s + 1 < NS) {
            int k0 = (s + 1) * 16;
            int bo = ((s + 1) & 1);
            for (int ch = tid; ch < 512; ch += 256) {
                int r = ch >> 2, c4 = (ch & 3) * 4;
                int nb = (len - (k0 + c4)) * 4;
                nb = nb < 0 ? 0 : (nb > 16 ? 16 : nb);
                cp16(pb + (bo * 2560 + r * 20 + c4) * 4,
                     P + (size_t)(q0 + r) * stride + k0 + c4, nb);
            }
            for (int ch = tid; ch < 320; ch += 256) {
                int r = ch / 20, c4 = (ch % 20) * 4;
                int rv = (k0 + r < len) ? 16 : 0;
                int rr = (k0 + r < len) ? (k0 + r) : (len - 1);
                cp16(vb + (bo * 1408 + r * 88 + c4) * 4,
                     V + (size_t)(off + rr) * CD + c0 + c4, rv);
            }
        }
        CP_COMMIT(); CP_WAIT1();
        __syncthreads();
        const float* Pb = Ps[s & 1];
        const float* Vb = Vs[s & 1];
        #pragma unroll
        for (int k8 = 0; k8 < 16; k8 += 8) {
            int ac = k8 + (lane & 3);
            int ar = wm * 32 + (lane >> 2);
            uint32_t a[2][4];
            #pragma unroll
            for (int i = 0; i < 2; i++) {
                a[i][0] = __float_as_uint(Pb[(ar + i * 16) * 20 + ac]);
                a[i][1] = __float_as_uint(Pb[(ar + i * 16 + 8) * 20 + ac]);
                a[i][2] = __float_as_uint(Pb[(ar + i * 16) * 20 + ac + 4]);
                a[i][3] = __float_as_uint(Pb[(ar + i * 16 + 8) * 20 + ac + 4]);
            }
            #pragma unroll
            for (int j = 0; j < 5; j++) {
                int bc = wn * 40 + j * 8 + (lane >> 2);
                uint32_t b[2];
                b[0] = __float_as_uint(Vb[ac * 88 + bc]);
                b[1] = __float_as_uint(Vb[(ac + 4) * 88 + bc]);
                mma_tf32(acc[0][j], a[0], b);
                mma_tf32(acc[1][j], a[1], b);
            }
        }
        __syncthreads();
    }
    int mi = wm * 32 + (lane >> 2);
    int nc = c0 + wn * 40 + 2 * (lane & 3);
    #pragma unroll
    for (int i = 0; i < 2; i++) {
        int r0 = q0 + mi + i * 16;
        int r1 = r0 + 8;
        #pragma unroll
        for (int j = 0; j < 5; j++) {
            int c = nc + j * 8;
            if (r0 < cnt) {
                size_t o = (size_t)(off + r0) * CD + c;
                if (accumulate) { g_hs[o] += acc[i][j][0]; g_hs[o + 1] += acc[i][j][1]; }
                else            { g_hs[o]  = acc[i][j][0]; g_hs[o + 1]  = acc[i][j][1]; }
            }
            if (r1 < cnt) {
                size_t o = (size_t)(off + r1) * CD + c;
                if (accumulate) { g_hs[o] += acc[i][j][2]; g_hs[o + 1] += acc[i][j][3]; }
                else            { g_hs[o]  = acc[i][j][2]; g_hs[o + 1]  = acc[i][j][3]; }
            }
        }
    }
}

// ---------------------------------------------------------------------------
// fallback mean of V_out rows
// ---------------------------------------------------------------------------
__global__ void meanv_kernel() {
    int col = threadIdx.x;
    const float* V = g_proj + 8ull * SEQ * CD;
    int r0 = blockIdx.x * 256;
    float s = 0.f;
    for (int r = 0; r < 256; r++) s += V[(size_t)(r0 + r) * CD + col];
    atomicAdd(&g_meanVo[col], s * (1.0f / SEQ));
}

__global__ void fb_kernel() {
    int row = blockIdx.x;
    int g = d_rowg[row];
    if (d_cntOut[g] != 0) return;
    for (int c = threadIdx.x; c < CD; c += 256)
        g_hs[(size_t)row * CD + c] += g_meanVo[c];
}

// ---------------------------------------------------------------------------
// final via tf32 mma + cp.async: out[m] = hs_p[iperm[m]] @ Wo^T + residual[m]
// ---------------------------------------------------------------------------
__global__ __launch_bounds__(256) void final_kernel(const float* __restrict__ Wo,
                                                    const float* __restrict__ resid,
                                                    float* __restrict__ Y) {
    __shared__ float Xs[2][128 * 20];
    __shared__ float Bs[2][128 * 20];
    __shared__ int ip[128];
    int n0 = blockIdx.x * 128, m0 = blockIdx.y * 128;
    int tid = threadIdx.x, lane = tid & 31, warp = tid >> 5;
    int wm = warp & 3, wn = warp >> 2;
    if (tid < 128) ip[tid] = g_iperm[m0 + tid];
    __syncthreads();
    uint32_t xb = smem_u32(Xs), bb = smem_u32(Bs);

    for (int ch = tid; ch < 512; ch += 256) {
        int r = ch >> 2, c4 = (ch & 3) * 4;
        cp16(xb + (r * 20 + c4) * 4, g_hs + (size_t)ip[r] * CD + c4, 16);
        cp16(bb + (r * 20 + c4) * 4, Wo + (size_t)(n0 + r) * CD + c4, 16);
    }
    CP_COMMIT();

    float acc[2][8][4] = {};
    for (int s = 0; s < 40; s++) {
        if (s + 1 < 40) {
            int k0 = (s + 1) * 16;
            int bo = ((s + 1) & 1) * 2560;
            for (int ch = tid; ch < 512; ch += 256) {
                int r = ch >> 2, c4 = (ch & 3) * 4;
                cp16(xb + (bo + r * 20 + c4) * 4, g_hs + (size_t)ip[r] * CD + k0 + c4, 16);
                cp16(bb + (bo + r * 20 + c4) * 4, Wo + (size_t)(n0 + r) * CD + k0 + c4, 16);
            }
        }
        CP_COMMIT(); CP_WAIT1();
        __syncthreads();
        const float* Xb = Xs[s & 1];
        const float* Bb = Bs[s & 1];
        #pragma unroll
        for (int k8 = 0; k8 < 16; k8 += 8) {
            int ac = k8 + (lane & 3);
            int ar = wm * 32 + (lane >> 2);
            uint32_t a[2][4];
            #pragma unroll
            for (int i = 0; i < 2; i++) {
                a[i][0] = __float_as_uint(Xb[(ar + i * 16) * 20 + ac]);
                a[i][1] = __float_as_uint(Xb[(ar + i * 16 + 8) * 20 + ac]);
                a[i][2] = __float_as_uint(Xb[(ar + i * 16) * 20 + ac + 4]);
                a[i][3] = __float_as_uint(Xb[(ar + i * 16 + 8) * 20 + ac + 4]);
            }
            #pragma unroll
            for (int j = 0; j < 8; j++) {
                int bc = wn * 64 + j * 8 + (lane >> 2);
                uint32_t b[2];
                b[0] = __float_as_uint(Bb[bc * 20 + ac]);
                b[1] = __float_as_uint(Bb[bc * 20 + ac + 4]);
                mma_tf32(acc[0][j], a[0], b);
                mma_tf32(acc[1][j], a[1], b);
            }
        }
        __syncthreads();
    }
    int mi = wm * 32 + (lane >> 2);
    int nc = n0 + wn * 64 + 2 * (lane & 3);
    #pragma unroll
    for (int i = 0; i < 2; i++) {
        #pragma unroll
        for (int j = 0; j < 8; j++) {
            int c = nc + j * 8;
            size_t o0 = (size_t)(m0 + mi + i * 16) * CD + c;
            size_t o1 = (size_t)(m0 + mi + i * 16 + 8) * CD + c;
            Y[o0]     = acc[i][j][0] + resid[o0];
            Y[o0 + 1] = acc[i][j][1] + resid[o0 + 1];
            Y[o1]     = acc[i][j][2] + resid[o1];
            Y[o1 + 1] = acc[i][j][3] + resid[o1 + 1];
        }
    }
}

// ---------------------------------------------------------------------------
// launch
// ---------------------------------------------------------------------------
extern "C" void kernel_launch(void* const* d_in, const int* in_sizes, int n_in,
                              void* d_out, int out_size) {
    const float* hidden = (const float*)d_in[0];
    const int*   mask   = (const int*)d_in[1];
    const int*   inp    = (const int*)d_in[2];
    W9 ws;
    for (int i = 0; i < 9; i++) ws.w[i] = (const float*)d_in[3 + i];
    const float* Wo = (const float*)d_in[12];
    float* out = (float*)d_out;

    const float s80  = 1.0f / sqrtf(80.0f);
    const float s640 = 1.0f / sqrtf(640.0f);

    labels_kernel<<<16, 256>>>(mask, inp);
    prep_kernel<<<1, 256>>>();
    proj_kernel<<<dim3(5, 32, 9), 256>>>(hidden, ws);
    meanv_kernel<<<16, 640>>>();

    // proj indices: 0=q 1=k 2=v 3=q_ent 4=k_ent 5=v_ent 6=q_out 7=k_out 8=v_out
    scores_kernel<<<dim3(40, 32, 8), 256>>>(0, 1, 0, 80,  s80,  0);  // original
    scores_kernel<<<dim3(40, 32, 1), 256>>>(3, 4, 8, 640, s640, 0);  // entity (1 head)
    scores_kernel<<<dim3(40, 32, 8), 256>>>(6, 7, 9, 80,  s80,  1);  // outside

    softmax_kernel<<<dim3(SEQ, 17), 256>>>();

    av_kernel<<<dim3(40, 1, 8), 256>>>(0, 2, 80,  0, 0);  // writes g_hs
    av_kernel<<<dim3(40, 8, 1), 256>>>(8, 5, 640, 1, 0);  // accumulates
    av_kernel<<<dim3(40, 1, 8), 256>>>(9, 8, 80,  1, 1);  // accumulates

    fb_kernel<<<SEQ, 256>>>();
    final_kernel<<<dim3(5, 32, 1), 256>>>(Wo, hidden, out);
}

// round 10
// speedup vs baseline: 16.5952x; 1.3047x over previous
#include <cuda_runtime.h>
#include <cuda_bf16.h>
#include <math.h>
#include <stdint.h>

#define SEQ  4096
#define PSEQ 4608                                  // padded permuted row space (group offs 128-aligned)
#define CD   640
#define MATSZ ((size_t)SEQ * SEQ + (1u << 21))     // entity score arena (covers worst-case 4223^2)

// ---- device scratch (static; no runtime allocation) ----
__device__ float g_proj[9ull * PSEQ * CD];         // 9 projections, PERMUTED(padded) rows
__device__ __nv_bfloat16 g_vbfT[2ull * CD * PSEQ]; // bf16 TRANSPOSED V (orig=0, outside=1): [col][row]
__device__ float g_scores[MATSZ];                  // entity score matrix (grouped)
__device__ float g_hs[(size_t)PSEQ * CD];          // attention output, permuted rows
__device__ float g_meanVo[CD];
__device__ int   g_lab[SEQ];
__device__ int   g_outs[SEQ];
__device__ int   g_iperm[SEQ];                     // original row -> padded permuted row
__device__ int   d_off[4], d_cnt[4], d_cntOut[4], d_cntPad[4];
__device__ long long d_scbase[4];
__device__ int   d_qtileG[40], d_qtileQ0[40];
__device__ int   d_nqtiles;
__device__ int   d_rowg[PSEQ], d_rowloc[PSEQ];     // -1 for gap rows

// ---------------------------------------------------------------------------
__device__ __forceinline__ uint32_t rtf(float x) {          // fp32 bits + half-tf32-ulp => rna-ish
    return __float_as_uint(x) + 0x1000u;
}
__device__ __forceinline__ void mma_tf32(float d[4], const uint32_t a[4], const uint32_t b[2]) {
    asm volatile(
        "mma.sync.aligned.m16n8k8.row.col.f32.tf32.tf32.f32 "
        "{%0,%1,%2,%3}, {%4,%5,%6,%7}, {%8,%9}, {%0,%1,%2,%3};\n"
        : "+f"(d[0]), "+f"(d[1]), "+f"(d[2]), "+f"(d[3])
        : "r"(a[0]), "r"(a[1]), "r"(a[2]), "r"(a[3]), "r"(b[0]), "r"(b[1]));
}
__device__ __forceinline__ void mma_bf16(float d[4], const uint32_t a[4], const uint32_t b[2]) {
    asm volatile(
        "mma.sync.aligned.m16n8k16.row.col.f32.bf16.bf16.f32 "
        "{%0,%1,%2,%3}, {%4,%5,%6,%7}, {%8,%9}, {%0,%1,%2,%3};\n"
        : "+f"(d[0]), "+f"(d[1]), "+f"(d[2]), "+f"(d[3])
        : "r"(a[0]), "r"(a[1]), "r"(a[2]), "r"(a[3]), "r"(b[0]), "r"(b[1]));
}
__device__ __forceinline__ uint32_t bfpack(float lo, float hi) {   // lo -> bits[15:0]
    uint32_t d; asm("cvt.rn.bf16x2.f32 %0, %1, %2;" : "=r"(d) : "f"(hi), "f"(lo)); return d;
}
__device__ __forceinline__ uint32_t smem_u32(const void* p) {
    return (uint32_t)__cvta_generic_to_shared(p);
}
__device__ __forceinline__ void cp16(uint32_t dst, const void* src, int nbytes) {
    asm volatile("cp.async.cg.shared.global [%0], [%1], 16, %2;\n"
                 :: "r"(dst), "l"(src), "r"(nbytes));
}
#define CP_COMMIT() asm volatile("cp.async.commit_group;\n")
#define CP_WAIT1()  asm volatile("cp.async.wait_group 1;\n")

// ---------------------------------------------------------------------------
__global__ void labels_kernel(const int* __restrict__ mask,
                              const int* __restrict__ inp) {
    int t = blockIdx.x * blockDim.x + threadIdx.x;
    if (t < CD) g_meanVo[t] = 0.f;
    if (t >= SEQ) return;
    int i = t >> 6, j = t & 63;
    int idx = (i * 8) * 512 + j * 8;
    g_lab[t]  = mask[idx];
    g_outs[t] = (inp[idx] == 0) ? 1 : 0;
}

// ---------------------------------------------------------------------------
// prep: bucket sort by (label, !outside); group offsets 128-ALIGNED (padded)
// ---------------------------------------------------------------------------
__global__ void prep_kernel() {
    __shared__ int cnt8[8], off8[8], cur8[8];
    int tid = threadIdx.x;
    if (tid < 8) cnt8[tid] = 0;
    __syncthreads();
    for (int t = tid; t < SEQ; t += 256) {
        int b = g_lab[t] * 2 + (g_outs[t] ? 0 : 1);
        atomicAdd(&cnt8[b], 1);
    }
    __syncthreads();
    if (tid == 0) {
        long long sb = 0; int nq = 0; int cum = 0;
        for (int g = 0; g < 4; g++) {
            int c = cnt8[2 * g] + cnt8[2 * g + 1];
            d_off[g] = cum;
            off8[2 * g] = cum; off8[2 * g + 1] = cum + cnt8[2 * g];
            d_cnt[g] = c; d_cntOut[g] = cnt8[2 * g];
            int pad = ((c + 127) >> 7) << 7;
            d_cntPad[g] = pad;
            d_scbase[g] = sb; sb += (long long)pad * pad;
            for (int j = 0; j < c; j += 128) { d_qtileG[nq] = g; d_qtileQ0[nq] = j; nq++; }
            cum = (cum + c + 127) & ~127;
        }
        d_nqtiles = nq;
    }
    __syncthreads();
    if (tid < 8) cur8[tid] = off8[tid];
    __syncthreads();
    for (int t = tid; t < SEQ; t += 256) {
        int b = g_lab[t] * 2 + (g_outs[t] ? 0 : 1);
        g_iperm[t] = atomicAdd(&cur8[b], 1);
    }
    __syncthreads();
    for (int i = tid; i < PSEQ; i += 256) {
        int gg = -1, loc = 0;
        for (int g = 0; g < 4; g++)
            if (i >= d_off[g] && i < d_off[g] + d_cnt[g]) { gg = g; loc = i - d_off[g]; }
        d_rowg[i] = gg; d_rowloc[i] = loc;
    }
}

// ---------------------------------------------------------------------------
// 9 projections via tf32 mma + cp.async; V projections (z=2,8) also emitted
// as bf16 TRANSPOSED copies for the flash kernel.
// ---------------------------------------------------------------------------
struct W9 { const float* w[9]; };

__global__ __launch_bounds__(256) void proj_kernel(const float* __restrict__ X, W9 ws) {
    __shared__ float Xs[2][128 * 20];
    __shared__ float Bs[2][128 * 20];
    __shared__ int ip[128];
    int z = blockIdx.z;
    const float* W = ws.w[z];
    float* Y = g_proj + (size_t)z * PSEQ * CD;
    int n0 = blockIdx.x * 128, m0 = blockIdx.y * 128;
    int tid = threadIdx.x, lane = tid & 31, warp = tid >> 5;
    int wm = warp & 3, wn = warp >> 2;
    if (tid < 128) ip[tid] = g_iperm[m0 + tid];
    uint32_t xb = smem_u32(Xs), bb = smem_u32(Bs);

    for (int ch = tid; ch < 512; ch += 256) {
        int r = ch >> 2, c4 = (ch & 3) * 4;
        cp16(xb + (r * 20 + c4) * 4, X + (size_t)(m0 + r) * CD + c4, 16);
        cp16(bb + (r * 20 + c4) * 4, W + (size_t)(n0 + r) * CD + c4, 16);
    }
    CP_COMMIT();

    float acc[2][8][4] = {};
    for (int s = 0; s < 40; s++) {
        if (s + 1 < 40) {
            int k0 = (s + 1) * 16;
            int bo = ((s + 1) & 1) * 2560;
            for (int ch = tid; ch < 512; ch += 256) {
                int r = ch >> 2, c4 = (ch & 3) * 4;
                cp16(xb + (bo + r * 20 + c4) * 4, X + (size_t)(m0 + r) * CD + k0 + c4, 16);
                cp16(bb + (bo + r * 20 + c4) * 4, W + (size_t)(n0 + r) * CD + k0 + c4, 16);
            }
        }
        CP_COMMIT(); CP_WAIT1();
        __syncthreads();
        const float* Xb = Xs[s & 1];
        const float* Bb = Bs[s & 1];
        #pragma unroll
        for (int k8 = 0; k8 < 16; k8 += 8) {
            int ac = k8 + (lane & 3);
            int ar = wm * 32 + (lane >> 2);
            uint32_t a[2][4];
            #pragma unroll
            for (int i = 0; i < 2; i++) {
                a[i][0] = rtf(Xb[(ar + i * 16) * 20 + ac]);
                a[i][1] = rtf(Xb[(ar + i * 16 + 8) * 20 + ac]);
                a[i][2] = rtf(Xb[(ar + i * 16) * 20 + ac + 4]);
                a[i][3] = rtf(Xb[(ar + i * 16 + 8) * 20 + ac + 4]);
            }
            #pragma unroll
            for (int j = 0; j < 8; j++) {
                int bc = wn * 64 + j * 8 + (lane >> 2);
                uint32_t b[2] = { rtf(Bb[bc * 20 + ac]), rtf(Bb[bc * 20 + ac + 4]) };
                mma_tf32(acc[0][j], a[0], b);
                mma_tf32(acc[1][j], a[1], b);
            }
        }
        __syncthreads();
    }
    int mi = wm * 32 + (lane >> 2);
    int nc = n0 + wn * 64 + 2 * (lane & 3);
    #pragma unroll
    for (int i = 0; i < 2; i++) {
        int pr0 = ip[mi + i * 16], pr1 = ip[mi + i * 16 + 8];
        #pragma unroll
        for (int j = 0; j < 8; j++) {
            int c = nc + j * 8;
            *(float2*)&Y[(size_t)pr0 * CD + c] = make_float2(acc[i][j][0], acc[i][j][1]);
            *(float2*)&Y[(size_t)pr1 * CD + c] = make_float2(acc[i][j][2], acc[i][j][3]);
        }
    }
    if (z == 2 || z == 8) {
        __nv_bfloat16* VT = g_vbfT + (z == 8 ? (size_t)CD * PSEQ : 0);
        #pragma unroll
        for (int i = 0; i < 2; i++) {
            int pr0 = ip[mi + i * 16], pr1 = ip[mi + i * 16 + 8];
            #pragma unroll
            for (int j = 0; j < 8; j++) {
                int c = nc + j * 8;
                VT[(size_t)c * PSEQ + pr0]       = __float2bfloat16(acc[i][j][0]);
                VT[(size_t)(c + 1) * PSEQ + pr0] = __float2bfloat16(acc[i][j][1]);
                VT[(size_t)c * PSEQ + pr1]       = __float2bfloat16(acc[i][j][2]);
                VT[(size_t)(c + 1) * PSEQ + pr1] = __float2bfloat16(acc[i][j][3]);
            }
        }
    }
}

// ---------------------------------------------------------------------------
// FLASH attention for d=80 branches: S(tf32) -> online softmax -> O += P(bf16)@V(bf16)
// grid (qtile<=40, head 0..7); 256 thr = 8 warps, each owns 16 q-rows.
// SMEM: Q 128x84 f32 | K 2x128x84 f32 | V 2x80x68 bf16x2 words
// ---------------------------------------------------------------------------
#define QK_STRIDE 84
#define Q_FLOATS  (128 * QK_STRIDE)               // 10752
#define FA_SMEM_BYTES ((Q_FLOATS + 2 * Q_FLOATS + 2 * 5440) * 4)   // 172544

__global__ __launch_bounds__(256) void fa_kernel(int qsel, int ksel, int vb,
                                                 float scale, int useOut, int accumulate) {
    extern __shared__ float sm[];
    float* Qs = sm;                               // 128 x 84
    float* Ks = sm + Q_FLOATS;                    // 2 x 128 x 84
    uint32_t* VT = (uint32_t*)(sm + 3 * Q_FLOATS);// 2 x 80 x 68 words (bf16x2, [n][kword])

    int qt = blockIdx.x;
    if (qt >= d_nqtiles) return;
    int g = d_qtileG[qt], q0 = d_qtileQ0[qt];
    int cnt = d_cnt[g];
    int len = useOut ? d_cntOut[g] : cnt;
    if (len == 0) return;
    int off = d_off[g];
    int z = blockIdx.y;
    const float* Q = g_proj + (size_t)qsel * PSEQ * CD;
    const float* K = g_proj + (size_t)ksel * PSEQ * CD;
    const __nv_bfloat16* Vsrc = g_vbfT + (size_t)vb * CD * PSEQ;

    int tid = threadIdx.x, lane = tid & 31, w = tid >> 5;
    int t2 = (lane & 3) * 2;
    int rbase = w * 16 + (lane >> 2);
    uint32_t qa = smem_u32(Qs), ka = smem_u32(Ks), va = smem_u32(VT);

    // stage Q (once) + K0: 128 rows x 80 floats = 2560 16B chunks each
    for (int ch = tid; ch < 2560; ch += 256) {
        int r = ch / 20, c4 = (ch % 20) * 4;
        int qr = q0 + r; int nb = (qr < cnt) ? 16 : 0; if (qr >= cnt) qr = cnt - 1;
        cp16(qa + (r * QK_STRIDE + c4) * 4, Q + (size_t)(off + qr) * CD + z * 80 + c4, nb);
        int kr = r; int kb2 = (kr < len) ? 16 : 0; if (kr >= len) kr = len - 1;
        cp16(ka + (r * QK_STRIDE + c4) * 4, K + (size_t)(off + kr) * CD + z * 80 + c4, kb2);
    }
    // stage V0: 80 cols x 64 words (128 keys)
    for (int ch = tid; ch < 1280; ch += 256) {
        int n = ch >> 4, r8 = ch & 15;
        int row = r8 * 8;
        int nb = (len - row) * 2; nb = nb < 0 ? 0 : (nb > 16 ? 16 : nb);
        int rowc = (row < len) ? row : 0;
        cp16(va + (n * 68 + r8 * 4) * 4,
             Vsrc + (size_t)(z * 80 + n) * PSEQ + off + rowc, nb);
    }
    CP_COMMIT();

    float accO[10][4] = {};
    float m_run[2] = {-1e30f, -1e30f}, l_run[2] = {0.f, 0.f};
    int nkt = (len + 127) >> 7;

    for (int it = 0; it < nkt; it++) {
        int kt = it * 128;
        if (it + 1 < nkt) {
            int ktn = kt + 128;
            int bo = (it + 1) & 1;
            for (int ch = tid; ch < 2560; ch += 256) {
                int r = ch / 20, c4 = (ch % 20) * 4;
                int kr = ktn + r; int nb = (kr < len) ? 16 : 0; if (kr >= len) kr = len - 1;
                cp16(ka + (bo * Q_FLOATS + r * QK_STRIDE + c4) * 4,
                     K + (size_t)(off + kr) * CD + z * 80 + c4, nb);
            }
            for (int ch = tid; ch < 1280; ch += 256) {
                int n = ch >> 4, r8 = ch & 15;
                int row = ktn + r8 * 8;
                int nb = (len - row) * 2; nb = nb < 0 ? 0 : (nb > 16 ? 16 : nb);
                int rowc = (row < len) ? row : 0;
                cp16(va + (bo * 5440 + n * 68 + r8 * 4) * 4,
                     Vsrc + (size_t)(z * 80 + n) * PSEQ + off + rowc, nb);
            }
        }
        CP_COMMIT(); CP_WAIT1();
        __syncthreads();
        const float* Kb = Ks + (it & 1) * Q_FLOATS;
        const uint32_t* Vb = VT + (it & 1) * 5440;

        // ---- S = Q K^T (tf32, K=80) ----
        float accS[16][4];
        #pragma unroll
        for (int jj = 0; jj < 16; jj++)
            accS[jj][0] = accS[jj][1] = accS[jj][2] = accS[jj][3] = 0.f;
        #pragma unroll
        for (int s8 = 0; s8 < 80; s8 += 8) {
            int ac = s8 + (lane & 3);
            uint32_t a[4];
            a[0] = rtf(Qs[rbase * QK_STRIDE + ac]);
            a[1] = rtf(Qs[(rbase + 8) * QK_STRIDE + ac]);
            a[2] = rtf(Qs[rbase * QK_STRIDE + ac + 4]);
            a[3] = rtf(Qs[(rbase + 8) * QK_STRIDE + ac + 4]);
            #pragma unroll
            for (int jj = 0; jj < 16; jj++) {
                int bc = jj * 8 + (lane >> 2);
                uint32_t b[2] = { rtf(Kb[bc * QK_STRIDE + ac]),
                                  rtf(Kb[bc * QK_STRIDE + ac + 4]) };
                mma_tf32(accS[jj], a, b);
            }
        }
        // ---- mask + scale + online softmax (warp-local: rows fully in-warp) ----
        bool full = (kt + 128 <= len);
        if (!full) {
            #pragma unroll
            for (int jj = 0; jj < 16; jj++) {
                int c0 = kt + jj * 8 + t2;
                if (c0 >= len)     { accS[jj][0] = -1e30f; accS[jj][2] = -1e30f; }
                if (c0 + 1 >= len) { accS[jj][1] = -1e30f; accS[jj][3] = -1e30f; }
            }
        }
        float mt0 = -1e30f, mt1 = -1e30f;
        #pragma unroll
        for (int jj = 0; jj < 16; jj++) {
            #pragma unroll
            for (int e = 0; e < 4; e++) accS[jj][e] *= scale;
            mt0 = fmaxf(mt0, fmaxf(accS[jj][0], accS[jj][1]));
            mt1 = fmaxf(mt1, fmaxf(accS[jj][2], accS[jj][3]));
        }
        mt0 = fmaxf(mt0, __shfl_xor_sync(0xffffffffu, mt0, 1));
        mt0 = fmaxf(mt0, __shfl_xor_sync(0xffffffffu, mt0, 2));
        mt1 = fmaxf(mt1, __shfl_xor_sync(0xffffffffu, mt1, 1));
        mt1 = fmaxf(mt1, __shfl_xor_sync(0xffffffffu, mt1, 2));
        float mn0 = fmaxf(m_run[0], mt0), mn1 = fmaxf(m_run[1], mt1);
        float f0 = __expf(m_run[0] - mn0), f1 = __expf(m_run[1] - mn1);
        m_run[0] = mn0; m_run[1] = mn1;
        float s0 = 0.f, s1 = 0.f;
        #pragma unroll
        for (int jj = 0; jj < 16; jj++) {
            accS[jj][0] = __expf(accS[jj][0] - mn0); s0 += accS[jj][0];
            accS[jj][1] = __expf(accS[jj][1] - mn0); s0 += accS[jj][1];
            accS[jj][2] = __expf(accS[jj][2] - mn1); s1 += accS[jj][2];
            accS[jj][3] = __expf(accS[jj][3] - mn1); s1 += accS[jj][3];
        }
        s0 += __shfl_xor_sync(0xffffffffu, s0, 1);
        s0 += __shfl_xor_sync(0xffffffffu, s0, 2);
        s1 += __shfl_xor_sync(0xffffffffu, s1, 1);
        s1 += __shfl_xor_sync(0xffffffffu, s1, 2);
        l_run[0] = l_run[0] * f0 + s0;
        l_run[1] = l_run[1] * f1 + s1;
        #pragma unroll
        for (int c = 0; c < 10; c++) {
            accO[c][0] *= f0; accO[c][1] *= f0; accO[c][2] *= f1; accO[c][3] *= f1;
        }
        // ---- O += P(bf16) @ V(bf16), contraction over 128 keys ----
        #pragma unroll
        for (int u = 0; u < 8; u++) {
            uint32_t pa[4];
            pa[0] = bfpack(accS[2 * u][0],     accS[2 * u][1]);
            pa[1] = bfpack(accS[2 * u][2],     accS[2 * u][3]);
            pa[2] = bfpack(accS[2 * u + 1][0], accS[2 * u + 1][1]);
            pa[3] = bfpack(accS[2 * u + 1][2], accS[2 * u + 1][3]);
            #pragma unroll
            for (int c = 0; c < 10; c++) {
                int base = (c * 8 + (lane >> 2)) * 68 + u * 8 + (lane & 3);
                uint32_t b[2] = { Vb[base], Vb[base + 4] };
                mma_bf16(accO[c], pa, b);
            }
        }
        __syncthreads();
    }

    // ---- epilogue: normalize + write ----
    float inv0 = 1.0f / l_run[0], inv1 = 1.0f / l_run[1];
    int r0 = q0 + w * 16 + (lane >> 2);
    int r1 = r0 + 8;
    int cb = z * 80 + t2;
    #pragma unroll
    for (int c = 0; c < 10; c++) {
        int col = cb + c * 8;
        if (r0 < cnt) {
            size_t o = (size_t)(off + r0) * CD + col;
            float v0 = accO[c][0] * inv0, v1 = accO[c][1] * inv0;
            if (accumulate) { g_hs[o] += v0; g_hs[o + 1] += v1; }
            else            { g_hs[o]  = v0; g_hs[o + 1]  = v1; }
        }
        if (r1 < cnt) {
            size_t o = (size_t)(off + r1) * CD + col;
            float v2 = accO[c][2] * inv1, v3 = accO[c][3] * inv1;
            if (accumulate) { g_hs[o] += v2; g_hs[o + 1] += v3; }
            else            { g_hs[o]  = v2; g_hs[o + 1]  = v3; }
        }
    }
}

// ---------------------------------------------------------------------------
// ENTITY branch (d=640): materialized scores (tf32) -> softmax -> AV (tf32)
// ---------------------------------------------------------------------------
__global__ __launch_bounds__(256) void scores_kernel(int qsel, int ksel,
                                                     int headDim, float scale) {
    __shared__ float Qs[2][128 * 20];
    __shared__ float Ks[2][128 * 20];
    int qt = blockIdx.x;
    if (qt >= d_nqtiles) return;
    int g = d_qtileG[qt], q0 = d_qtileQ0[qt];
    int cnt = d_cnt[g];
    int len = cnt;
    int k0t = blockIdx.y * 128;
    if (k0t >= len) return;
    int off = d_off[g];
    int stride = d_cntPad[g];
    const float* Q = g_proj + (size_t)qsel * PSEQ * CD;
    const float* K = g_proj + (size_t)ksel * PSEQ * CD;
    float* Sc = g_scores + (size_t)d_scbase[g];
    int tid = threadIdx.x, lane = tid & 31, warp = tid >> 5;
    int wm = warp & 3, wn = warp >> 2;
    uint32_t qb = smem_u32(Qs), kb = smem_u32(Ks);
    int NS = headDim / 16;

    for (int ch = tid; ch < 512; ch += 256) {
        int r = ch >> 2, c4 = (ch & 3) * 4;
        int qr = q0 + r, kr = k0t + r;
        int qv = (qr < cnt) ? 16 : 0;
        int kv = (kr < len) ? 16 : 0;
        if (qr >= cnt) qr = cnt - 1;
        if (kr >= len) kr = len - 1;
        cp16(qb + (r * 20 + c4) * 4, Q + (size_t)(off + qr) * CD + c4, qv);
        cp16(kb + (r * 20 + c4) * 4, K + (size_t)(off + kr) * CD + c4, kv);
    }
    CP_COMMIT();

    float acc[2][8][4] = {};
    for (int s = 0; s < NS; s++) {
        if (s + 1 < NS) {
            int k0 = (s + 1) * 16;
            int bo = ((s + 1) & 1) * 2560;
            for (int ch = tid; ch < 512; ch += 256) {
                int r = ch >> 2, c4 = (ch & 3) * 4;
                int qr = q0 + r, kr = k0t + r;
                int qv = (qr < cnt) ? 16 : 0;
                int kv = (kr < len) ? 16 : 0;
                if (qr >= cnt) qr = cnt - 1;
                if (kr >= len) kr = len - 1;
                cp16(qb + (bo + r * 20 + c4) * 4, Q + (size_t)(off + qr) * CD + k0 + c4, qv);
                cp16(kb + (bo + r * 20 + c4) * 4, K + (size_t)(off + kr) * CD + k0 + c4, kv);
            }
        }
        CP_COMMIT(); CP_WAIT1();
        __syncthreads();
        const float* Qb = Qs[s & 1];
        const float* Kb = Ks[s & 1];
        #pragma unroll
        for (int k8 = 0; k8 < 16; k8 += 8) {
            int ac = k8 + (lane & 3);
            int ar = wm * 32 + (lane >> 2);
            uint32_t a[2][4];
            #pragma unroll
            for (int i = 0; i < 2; i++) {
                a[i][0] = rtf(Qb[(ar + i * 16) * 20 + ac]);
                a[i][1] = rtf(Qb[(ar + i * 16 + 8) * 20 + ac]);
                a[i][2] = rtf(Qb[(ar + i * 16) * 20 + ac + 4]);
                a[i][3] = rtf(Qb[(ar + i * 16 + 8) * 20 + ac + 4]);
            }
            #pragma unroll
            for (int j = 0; j < 8; j++) {
                int bc = wn * 64 + j * 8 + (lane >> 2);
                uint32_t b[2] = { rtf(Kb[bc * 20 + ac]), rtf(Kb[bc * 20 + ac + 4]) };
                mma_tf32(acc[0][j], a[0], b);
                mma_tf32(acc[1][j], a[1], b);
            }
        }
        __syncthreads();
    }
    int mr = q0 + wm * 32 + (lane >> 2);
    int nc = k0t + wn * 64 + 2 * (lane & 3);
    #pragma unroll
    for (int i = 0; i < 2; i++) {
        int r0 = mr + i * 16;
        #pragma unroll
        for (int j = 0; j < 8; j++) {
            int c = nc + j * 8;
            *(float2*)&Sc[(size_t)r0 * stride + c] =
                make_float2(acc[i][j][0] * scale, acc[i][j][1] * scale);
            *(float2*)&Sc[(size_t)(r0 + 8) * stride + c] =
                make_float2(acc[i][j][2] * scale, acc[i][j][3] * scale);
        }
    }
}

__global__ __launch_bounds__(256) void softmax_kernel() {
    __shared__ float buf[SEQ];
    __shared__ float red[256];
    int row = blockIdx.x;
    int g = d_rowg[row];
    if (g < 0) return;
    int rl = d_rowloc[row];
    int len = d_cnt[g];
    float* p = g_scores + (size_t)d_scbase[g] + (size_t)rl * d_cntPad[g];
    int tid = threadIdx.x;
    float mx = -INFINITY;
    for (int i = tid; i < len; i += 256) { float v = p[i]; buf[i] = v; mx = fmaxf(mx, v); }
    red[tid] = mx; __syncthreads();
    for (int s = 128; s > 0; s >>= 1) {
        if (tid < s) red[tid] = fmaxf(red[tid], red[tid + s]);
        __syncthreads();
    }
    mx = red[0]; __syncthreads();
    float sum = 0.f;
    for (int i = tid; i < len; i += 256) { float e = __expf(buf[i] - mx); buf[i] = e; sum += e; }
    red[tid] = sum; __syncthreads();
    for (int s = 128; s > 0; s >>= 1) {
        if (tid < s) red[tid] += red[tid + s];
        __syncthreads();
    }
    float inv = 1.0f / red[0];
    for (int i = tid; i < len; i += 256) p[i] = buf[i] * inv;
}

__global__ __launch_bounds__(256) void av_kernel(int vsel) {
    __shared__ float Ps[2][128 * 20];
    __shared__ float Vs[2][16 * 88];
    int qt = blockIdx.x;
    if (qt >= d_nqtiles) return;
    int g = d_qtileG[qt], q0 = d_qtileQ0[qt];
    int cnt = d_cnt[g];
    int len = cnt;
    int off = d_off[g];
    int stride = d_cntPad[g];
    int c0 = blockIdx.y * 80;
    const float* P = g_scores + (size_t)d_scbase[g];
    const float* V = g_proj + (size_t)vsel * PSEQ * CD;
    int tid = threadIdx.x, lane = tid & 31, warp = tid >> 5;
    int wm = warp & 3, wn = warp >> 2;
    uint32_t pb = smem_u32(Ps), vb = smem_u32(Vs);
    int NS = (len + 15) >> 4;

    for (int ch = tid; ch < 512; ch += 256) {
        int r = ch >> 2, c4 = (ch & 3) * 4;
        int nb = (len - c4) * 4;
        nb = nb < 0 ? 0 : (nb > 16 ? 16 : nb);
        cp16(pb + (r * 20 + c4) * 4, P + (size_t)(q0 + r) * stride + c4, nb);
    }
    for (int ch = tid; ch < 320; ch += 256) {
        int r = ch / 20, c4 = (ch % 20) * 4;
        int rv = (r < len) ? 16 : 0;
        int rr = (r < len) ? r : (len - 1);
        cp16(vb + (r * 88 + c4) * 4, V + (size_t)(off + rr) * CD + c0 + c4, rv);
    }
    CP_COMMIT();

    float acc[2][5][4] = {};
    for (int s = 0; s < NS; s++) {
        if (s + 1 < NS) {
            int k0 = (s + 1) * 16;
            int bo = ((s + 1) & 1);
            for (int ch = tid; ch < 512; ch += 256) {
                int r = ch >> 2, c4 = (ch & 3) * 4;
                int nb = (len - (k0 + c4)) * 4;
                nb = nb < 0 ? 0 : (nb > 16 ? 16 : nb);
                cp16(pb + (bo * 2560 + r * 20 + c4) * 4,
                     P + (size_t)(q0 + r) * stride + k0 + c4, nb);
            }
            for (int ch = tid; ch < 320; ch += 256) {
                int r = ch / 20, c4 = (ch % 20) * 4;
                int rv = (k0 + r < len) ? 16 : 0;
                int rr = (k0 + r < len) ? (k0 + r) : (len - 1);
                cp16(vb + (bo * 1408 + r * 88 + c4) * 4,
                     V + (size_t)(off + rr) * CD + c0 + c4, rv);
            }
        }
        CP_COMMIT(); CP_WAIT1();
        __syncthreads();
        const float* Pb = Ps[s & 1];
        const float* Vb = Vs[s & 1];
        #pragma unroll
        for (int k8 = 0; k8 < 16; k8 += 8) {
            int ac = k8 + (lane & 3);
            int ar = wm * 32 + (lane >> 2);
            uint32_t a[2][4];
            #pragma unroll
            for (int i = 0; i < 2; i++) {
                a[i][0] = rtf(Pb[(ar + i * 16) * 20 + ac]);
                a[i][1] = rtf(Pb[(ar + i * 16 + 8) * 20 + ac]);
                a[i][2] = rtf(Pb[(ar + i * 16) * 20 + ac + 4]);
                a[i][3] = rtf(Pb[(ar + i * 16 + 8) * 20 + ac + 4]);
            }
            #pragma unroll
            for (int j = 0; j < 5; j++) {
                int bc = wn * 40 + j * 8 + (lane >> 2);
                uint32_t b[2] = { rtf(Vb[ac * 88 + bc]), rtf(Vb[(ac + 4) * 88 + bc]) };
                mma_tf32(acc[0][j], a[0], b);
                mma_tf32(acc[1][j], a[1], b);
            }
        }
        __syncthreads();
    }
    int mi = wm * 32 + (lane >> 2);
    int nc = c0 + wn * 40 + 2 * (lane & 3);
    #pragma unroll
    for (int i = 0; i < 2; i++) {
        int r0 = q0 + mi + i * 16;
        int r1 = r0 + 8;
        #pragma unroll
        for (int j = 0; j < 5; j++) {
            int c = nc + j * 8;
            if (r0 < cnt) {
                size_t o = (size_t)(off + r0) * CD + c;
                g_hs[o] += acc[i][j][0]; g_hs[o + 1] += acc[i][j][1];
            }
            if (r1 < cnt) {
                size_t o = (size_t)(off + r1) * CD + c;
                g_hs[o] += acc[i][j][2]; g_hs[o + 1] += acc[i][j][3];
            }
        }
    }
}

// ---------------------------------------------------------------------------
__global__ void meanv_kernel() {
    int col = threadIdx.x;
    const float* V = g_proj + 8ull * PSEQ * CD;
    int r0 = blockIdx.x * 256;
    float s = 0.f;
    for (int r = 0; r < 256; r++) {
        int row = r0 + r;
        if (row < PSEQ && d_rowg[row] >= 0) s += V[(size_t)row * CD + col];
    }
    atomicAdd(&g_meanVo[col], s * (1.0f / SEQ));
}

__global__ void fb_kernel() {
    int row = blockIdx.x;
    int g = d_rowg[row];
    if (g < 0 || d_cntOut[g] != 0) return;
    for (int c = threadIdx.x; c < CD; c += 256)
        g_hs[(size_t)row * CD + c] += g_meanVo[c];
}

// ---------------------------------------------------------------------------
__global__ __launch_bounds__(256) void final_kernel(const float* __restrict__ Wo,
                                                    const float* __restrict__ resid,
                                                    float* __restrict__ Y) {
    __shared__ float Xs[2][128 * 20];
    __shared__ float Bs[2][128 * 20];
    __shared__ int ip[128];
    int n0 = blockIdx.x * 128, m0 = blockIdx.y * 128;
    int tid = threadIdx.x, lane = tid & 31, warp = tid >> 5;
    int wm = warp & 3, wn = warp >> 2;
    if (tid < 128) ip[tid] = g_iperm[m0 + tid];
    __syncthreads();
    uint32_t xb = smem_u32(Xs), bb = smem_u32(Bs);

    for (int ch = tid; ch < 512; ch += 256) {
        int r = ch >> 2, c4 = (ch & 3) * 4;
        cp16(xb + (r * 20 + c4) * 4, g_hs + (size_t)ip[r] * CD + c4, 16);
        cp16(bb + (r * 20 + c4) * 4, Wo + (size_t)(n0 + r) * CD + c4, 16);
    }
    CP_COMMIT();

    float acc[2][8][4] = {};
    for (int s = 0; s < 40; s++) {
        if (s + 1 < 40) {
            int k0 = (s + 1) * 16;
            int bo = ((s + 1) & 1) * 2560;
            for (int ch = tid; ch < 512; ch += 256) {
                int r = ch >> 2, c4 = (ch & 3) * 4;
                cp16(xb + (bo + r * 20 + c4) * 4, g_hs + (size_t)ip[r] * CD + k0 + c4, 16);
                cp16(bb + (bo + r * 20 + c4) * 4, Wo + (size_t)(n0 + r) * CD + k0 + c4, 16);
            }
        }
        CP_COMMIT(); CP_WAIT1();
        __syncthreads();
        const float* Xb = Xs[s & 1];
        const float* Bb = Bs[s & 1];
        #pragma unroll
        for (int k8 = 0; k8 < 16; k8 += 8) {
            int ac = k8 + (lane & 3);
            int ar = wm * 32 + (lane >> 2);
            uint32_t a[2][4];
            #pragma unroll
            for (int i = 0; i < 2; i++) {
                a[i][0] = rtf(Xb[(ar + i * 16) * 20 + ac]);
                a[i][1] = rtf(Xb[(ar + i * 16 + 8) * 20 + ac]);
                a[i][2] = rtf(Xb[(ar + i * 16) * 20 + ac + 4]);
                a[i][3] = rtf(Xb[(ar + i * 16 + 8) * 20 + ac + 4]);
            }
            #pragma unroll
            for (int j = 0; j < 8; j++) {
                int bc = wn * 64 + j * 8 + (lane >> 2);
                uint32_t b[2] = { rtf(Bb[bc * 20 + ac]), rtf(Bb[bc * 20 + ac + 4]) };
                mma_tf32(acc[0][j], a[0], b);
                mma_tf32(acc[1][j], a[1], b);
            }
        }
        __syncthreads();
    }
    int mi = wm * 32 + (lane >> 2);
    int nc = n0 + wn * 64 + 2 * (lane & 3);
    #pragma unroll
    for (int i = 0; i < 2; i++) {
        #pragma unroll
        for (int j = 0; j < 8; j++) {
            int c = nc + j * 8;
            size_t o0 = (size_t)(m0 + mi + i * 16) * CD + c;
            size_t o1 = (size_t)(m0 + mi + i * 16 + 8) * CD + c;
            Y[o0]     = acc[i][j][0] + resid[o0];
            Y[o0 + 1] = acc[i][j][1] + resid[o0 + 1];
            Y[o1]     = acc[i][j][2] + resid[o1];
            Y[o1 + 1] = acc[i][j][3] + resid[o1 + 1];
        }
    }
}

// ---------------------------------------------------------------------------
extern "C" void kernel_launch(void* const* d_in, const int* in_sizes, int n_in,
                              void* d_out, int out_size) {
    const float* hidden = (const float*)d_in[0];
    const int*   mask   = (const int*)d_in[1];
    const int*   inp    = (const int*)d_in[2];
    W9 ws;
    for (int i = 0; i < 9; i++) ws.w[i] = (const float*)d_in[3 + i];
    const float* Wo = (const float*)d_in[12];
    float* out = (float*)d_out;

    const float s80  = 1.0f / sqrtf(80.0f);
    const float s640 = 1.0f / sqrtf(640.0f);

    cudaFuncSetAttribute(fa_kernel, cudaFuncAttributeMaxDynamicSharedMemorySize, FA_SMEM_BYTES);

    labels_kernel<<<16, 256>>>(mask, inp);
    prep_kernel<<<1, 256>>>();
    proj_kernel<<<dim3(5, 32, 9), 256>>>(hidden, ws);
    meanv_kernel<<<18, 640>>>();

    // proj indices: 0=q 1=k 2=v 3=q_ent 4=k_ent 5=v_ent 6=q_out 7=k_out 8=v_out
    fa_kernel<<<dim3(40, 8), 256, FA_SMEM_BYTES>>>(0, 1, 0, s80, 0, 0);   // orig: writes g_hs

    scores_kernel<<<dim3(40, 32), 256>>>(3, 4, 640, s640);                // entity
    softmax_kernel<<<PSEQ, 256>>>();
    av_kernel<<<dim3(40, 8), 256>>>(5);                                   // entity: accumulates

    fa_kernel<<<dim3(40, 8), 256, FA_SMEM_BYTES>>>(6, 7, 1, s80, 1, 1);   // outside: accumulates

    fb_kernel<<<PSEQ, 256>>>();
    final_kernel<<<dim3(5, 32), 256>>>(Wo, hidden, out);
}

// round 12
// speedup vs baseline: 17.8277x; 1.0743x over previous
#include <cuda_runtime.h>
#include <cuda_bf16.h>
#include <math.h>
#include <stdint.h>

#define SEQ  4096
#define PSEQ 4608                                  // padded permuted row space (group offs 128-aligned)
#define CD   640
#define MATSZ ((size_t)SEQ * SEQ + (1u << 21))     // entity score arena

// ---- device scratch (static; no runtime allocation) ----
__device__ float g_proj[9ull * PSEQ * CD];         // 9 projections, PERMUTED(padded) rows
__device__ __nv_bfloat16 g_vbfT[2ull * CD * PSEQ]; // bf16 TRANSPOSED V (orig=0, outside=1): [col][row]
__device__ float g_scores[MATSZ];                  // entity score matrix (grouped)
__device__ float g_hs[(size_t)PSEQ * CD];          // attention output, permuted rows
__device__ float g_meanVo[CD];
__device__ float g_rowmask[PSEQ];                  // 1.0 for real rows, 0.0 for gaps
__device__ int   g_lab[SEQ];
__device__ int   g_outs[SEQ];
__device__ int   g_iperm[SEQ];                     // original row -> padded permuted row
__device__ int   d_off[4], d_cnt[4], d_cntOut[4], d_cntPad[4];
__device__ long long d_scbase[4];
__device__ int   d_qtileG[40], d_qtileQ0[40];
__device__ int   d_nqtiles;
__device__ int   d_rowg[PSEQ], d_rowloc[PSEQ];     // -1 for gap rows

// ---------------------------------------------------------------------------
__device__ __forceinline__ uint32_t rtf(float x) {          // fp32 bits + half-tf32-ulp => rna-ish
    return __float_as_uint(x) + 0x1000u;
}
__device__ __forceinline__ void mma_tf32(float d[4], const uint32_t a[4], const uint32_t b[2]) {
    asm volatile(
        "mma.sync.aligned.m16n8k8.row.col.f32.tf32.tf32.f32 "
        "{%0,%1,%2,%3}, {%4,%5,%6,%7}, {%8,%9}, {%0,%1,%2,%3};\n"
        : "+f"(d[0]), "+f"(d[1]), "+f"(d[2]), "+f"(d[3])
        : "r"(a[0]), "r"(a[1]), "r"(a[2]), "r"(a[3]), "r"(b[0]), "r"(b[1]));
}
__device__ __forceinline__ void mma_bf16(float d[4], const uint32_t a[4], const uint32_t b[2]) {
    asm volatile(
        "mma.sync.aligned.m16n8k16.row.col.f32.bf16.bf16.f32 "
        "{%0,%1,%2,%3}, {%4,%5,%6,%7}, {%8,%9}, {%0,%1,%2,%3};\n"
        : "+f"(d[0]), "+f"(d[1]), "+f"(d[2]), "+f"(d[3])
        : "r"(a[0]), "r"(a[1]), "r"(a[2]), "r"(a[3]), "r"(b[0]), "r"(b[1]));
}
__device__ __forceinline__ uint32_t bfpack(float lo, float hi) {   // lo -> bits[15:0]
    uint32_t d; asm("cvt.rn.bf16x2.f32 %0, %1, %2;" : "=r"(d) : "f"(hi), "f"(lo)); return d;
}
__device__ __forceinline__ uint32_t smem_u32(const void* p) {
    return (uint32_t)__cvta_generic_to_shared(p);
}
__device__ __forceinline__ void cp16(uint32_t dst, const void* src, int nbytes) {
    asm volatile("cp.async.cg.shared.global [%0], [%1], 16, %2;\n"
                 :: "r"(dst), "l"(src), "r"(nbytes));
}
#define CP_COMMIT() asm volatile("cp.async.commit_group;\n")
#define CP_WAIT1()  asm volatile("cp.async.wait_group 1;\n")

// ---------------------------------------------------------------------------
__global__ void labels_kernel(const int* __restrict__ mask,
                              const int* __restrict__ inp) {
    int t = blockIdx.x * blockDim.x + threadIdx.x;
    if (t < CD) g_meanVo[t] = 0.f;
    if (t >= SEQ) return;
    int i = t >> 6, j = t & 63;
    int idx = (i * 8) * 512 + j * 8;
    g_lab[t]  = mask[idx];
    g_outs[t] = (inp[idx] == 0) ? 1 : 0;
}

// ---------------------------------------------------------------------------
// prep: bucket sort by (label, !outside); group offsets 128-ALIGNED (padded)
// ---------------------------------------------------------------------------
__global__ void prep_kernel() {
    __shared__ int cnt8[8], off8[8], cur8[8];
    int tid = threadIdx.x;
    if (tid < 8) cnt8[tid] = 0;
    __syncthreads();
    for (int t = tid; t < SEQ; t += 256) {
        int b = g_lab[t] * 2 + (g_outs[t] ? 0 : 1);
        atomicAdd(&cnt8[b], 1);
    }
    __syncthreads();
    if (tid == 0) {
        long long sb = 0; int nq = 0; int cum = 0;
        for (int g = 0; g < 4; g++) {
            int c = cnt8[2 * g] + cnt8[2 * g + 1];
            d_off[g] = cum;
            off8[2 * g] = cum; off8[2 * g + 1] = cum + cnt8[2 * g];
            d_cnt[g] = c; d_cntOut[g] = cnt8[2 * g];
            int pad = ((c + 127) >> 7) << 7;
            d_cntPad[g] = pad;
            d_scbase[g] = sb; sb += (long long)pad * pad;
            for (int j = 0; j < c; j += 128) { d_qtileG[nq] = g; d_qtileQ0[nq] = j; nq++; }
            cum = (cum + c + 127) & ~127;
        }
        d_nqtiles = nq;
    }
    __syncthreads();
    if (tid < 8) cur8[tid] = off8[tid];
    __syncthreads();
    for (int t = tid; t < SEQ; t += 256) {
        int b = g_lab[t] * 2 + (g_outs[t] ? 0 : 1);
        g_iperm[t] = atomicAdd(&cur8[b], 1);
    }
    __syncthreads();
    for (int i = tid; i < PSEQ; i += 256) {
        int gg = -1, loc = 0;
        for (int g = 0; g < 4; g++)
            if (i >= d_off[g] && i < d_off[g] + d_cnt[g]) { gg = g; loc = i - d_off[g]; }
        d_rowg[i] = gg; d_rowloc[i] = loc;
        g_rowmask[i] = (gg >= 0) ? 1.0f : 0.0f;
    }
}

// ---------------------------------------------------------------------------
// 9 projections via tf32 mma + cp.async; V projections (z=2,8) also emitted
// as bf16 TRANSPOSED copies for the flash kernel.
// ---------------------------------------------------------------------------
struct W9 { const float* w[9]; };

__global__ __launch_bounds__(256) void proj_kernel(const float* __restrict__ X, W9 ws) {
    __shared__ float Xs[2][128 * 20];
    __shared__ float Bs[2][128 * 20];
    __shared__ int ip[128];
    int z = blockIdx.z;
    const float* W = ws.w[z];
    float* Y = g_proj + (size_t)z * PSEQ * CD;
    int n0 = blockIdx.x * 128, m0 = blockIdx.y * 128;
    int tid = threadIdx.x, lane = tid & 31, warp = tid >> 5;
    int wm = warp & 3, wn = warp >> 2;
    if (tid < 128) ip[tid] = g_iperm[m0 + tid];
    uint32_t xb = smem_u32(Xs), bb = smem_u32(Bs);

    for (int ch = tid; ch < 512; ch += 256) {
        int r = ch >> 2, c4 = (ch & 3) * 4;
        cp16(xb + (r * 20 + c4) * 4, X + (size_t)(m0 + r) * CD + c4, 16);
        cp16(bb + (r * 20 + c4) * 4, W + (size_t)(n0 + r) * CD + c4, 16);
    }
    CP_COMMIT();

    float acc[2][8][4] = {};
    for (int s = 0; s < 40; s++) {
        if (s + 1 < 40) {
            int k0 = (s + 1) * 16;
            int bo = ((s + 1) & 1) * 2560;
            for (int ch = tid; ch < 512; ch += 256) {
                int r = ch >> 2, c4 = (ch & 3) * 4;
                cp16(xb + (bo + r * 20 + c4) * 4, X + (size_t)(m0 + r) * CD + k0 + c4, 16);
                cp16(bb + (bo + r * 20 + c4) * 4, W + (size_t)(n0 + r) * CD + k0 + c4, 16);
            }
        }
        CP_COMMIT(); CP_WAIT1();
        __syncthreads();
        const float* Xb = Xs[s & 1];
        const float* Bb = Bs[s & 1];
        #pragma unroll
        for (int k8 = 0; k8 < 16; k8 += 8) {
            int ac = k8 + (lane & 3);
            int ar = wm * 32 + (lane >> 2);
            uint32_t a[2][4];
            #pragma unroll
            for (int i = 0; i < 2; i++) {
                a[i][0] = rtf(Xb[(ar + i * 16) * 20 + ac]);
                a[i][1] = rtf(Xb[(ar + i * 16 + 8) * 20 + ac]);
                a[i][2] = rtf(Xb[(ar + i * 16) * 20 + ac + 4]);
                a[i][3] = rtf(Xb[(ar + i * 16 + 8) * 20 + ac + 4]);
            }
            #pragma unroll
            for (int j = 0; j < 8; j++) {
                int bc = wn * 64 + j * 8 + (lane >> 2);
                uint32_t b[2] = { rtf(Bb[bc * 20 + ac]), rtf(Bb[bc * 20 + ac + 4]) };
                mma_tf32(acc[0][j], a[0], b);
                mma_tf32(acc[1][j], a[1], b);
            }
        }
        __syncthreads();
    }
    int mi = wm * 32 + (lane >> 2);
    int nc = n0 + wn * 64 + 2 * (lane & 3);
    #pragma unroll
    for (int i = 0; i < 2; i++) {
        int pr0 = ip[mi + i * 16], pr1 = ip[mi + i * 16 + 8];
        #pragma unroll
        for (int j = 0; j < 8; j++) {
            int c = nc + j * 8;
            *(float2*)&Y[(size_t)pr0 * CD + c] = make_float2(acc[i][j][0], acc[i][j][1]);
            *(float2*)&Y[(size_t)pr1 * CD + c] = make_float2(acc[i][j][2], acc[i][j][3]);
        }
    }
    if (z == 2 || z == 8) {
        __nv_bfloat16* VT = g_vbfT + (z == 8 ? (size_t)CD * PSEQ : 0);
        #pragma unroll
        for (int i = 0; i < 2; i++) {
            int pr0 = ip[mi + i * 16], pr1 = ip[mi + i * 16 + 8];
            #pragma unroll
            for (int j = 0; j < 8; j++) {
                int c = nc + j * 8;
                VT[(size_t)c * PSEQ + pr0]       = __float2bfloat16(acc[i][j][0]);
                VT[(size_t)(c + 1) * PSEQ + pr0] = __float2bfloat16(acc[i][j][1]);
                VT[(size_t)c * PSEQ + pr1]       = __float2bfloat16(acc[i][j][2]);
                VT[(size_t)(c + 1) * PSEQ + pr1] = __float2bfloat16(acc[i][j][3]);
            }
        }
    }
}

// ---------------------------------------------------------------------------
// FLASH attention for d=80 branches: S(tf32) -> online softmax -> O += P(bf16)@V(bf16)
// grid (qtile<=40, head 0..7); 256 thr = 8 warps, each owns 16 q-rows.
// K-tile = 64 keys. SMEM: Q 128x84 | K 2x64x84 | V 2x80x36 words = 109,056 B
// -> 2 CTAs/SM.
// ---------------------------------------------------------------------------
#define QK_STRIDE 84
#define Q_FLOATS  (128 * QK_STRIDE)               // 10752
#define K_FLOATS  (64 * QK_STRIDE)                // 5376 per buffer
#define V_WORDS   (80 * 36)                       // 2880 per buffer
#define FA_SMEM_BYTES ((Q_FLOATS + 2 * K_FLOATS + 2 * V_WORDS) * 4)   // 109056

__global__ __launch_bounds__(256, 2) void fa_kernel(int qsel, int ksel, int vb,
                                                    float scale, int useOut, int accumulate) {
    extern __shared__ float sm[];
    float* Qs = sm;                                   // 128 x 84
    float* Ks = sm + Q_FLOATS;                        // 2 x 64 x 84
    uint32_t* VT = (uint32_t*)(sm + Q_FLOATS + 2 * K_FLOATS);  // 2 x 80 x 36 words

    int qt = blockIdx.x;
    if (qt >= d_nqtiles) return;
    int g = d_qtileG[qt], q0 = d_qtileQ0[qt];
    int cnt = d_cnt[g];
    int len = useOut ? d_cntOut[g] : cnt;
    if (len == 0) return;
    int off = d_off[g];
    int z = blockIdx.y;
    const float* Q = g_proj + (size_t)qsel * PSEQ * CD;
    const float* K = g_proj + (size_t)ksel * PSEQ * CD;
    const __nv_bfloat16* Vsrc = g_vbfT + (size_t)vb * CD * PSEQ;

    int tid = threadIdx.x, lane = tid & 31, w = tid >> 5;
    int t2 = (lane & 3) * 2;
    int rbase = w * 16 + (lane >> 2);
    uint32_t qa = smem_u32(Qs), ka = smem_u32(Ks), va = smem_u32(VT);

    // stage Q (once): 128 rows x 20 chunks
    for (int ch = tid; ch < 2560; ch += 256) {
        int r = ch / 20, c4 = (ch % 20) * 4;
        int qr = q0 + r; int nb = (qr < cnt) ? 16 : 0; if (qr >= cnt) qr = cnt - 1;
        cp16(qa + (r * QK_STRIDE + c4) * 4, Q + (size_t)(off + qr) * CD + z * 80 + c4, nb);
    }
    // stage K0 (64 rows) + V0 (80 cols x 8 chunks of 64 keys)
    for (int ch = tid; ch < 1280; ch += 256) {
        int r = ch / 20, c4 = (ch % 20) * 4;
        int kr = r; int nb = (kr < len) ? 16 : 0; if (kr >= len) kr = len - 1;
        cp16(ka + (r * QK_STRIDE + c4) * 4, K + (size_t)(off + kr) * CD + z * 80 + c4, nb);
    }
    for (int ch = tid; ch < 640; ch += 256) {
        int n = ch >> 3, r8 = ch & 7;
        int row = r8 * 8;
        int nb = (len - row) * 2; nb = nb < 0 ? 0 : (nb > 16 ? 16 : nb);
        int rowc = (row < len) ? row : 0;
        cp16(va + (n * 36 + r8 * 4) * 4,
             Vsrc + (size_t)(z * 80 + n) * PSEQ + off + rowc, nb);
    }
    CP_COMMIT();

    float accO[10][4] = {};
    float m_run[2] = {-1e30f, -1e30f}, l_run[2] = {0.f, 0.f};
    int nkt = (len + 63) >> 6;

    for (int it = 0; it < nkt; it++) {
        int kt = it * 64;
        if (it + 1 < nkt) {
            int ktn = kt + 64;
            int bo = (it + 1) & 1;
            for (int ch = tid; ch < 1280; ch += 256) {
                int r = ch / 20, c4 = (ch % 20) * 4;
                int kr = ktn + r; int nb = (kr < len) ? 16 : 0; if (kr >= len) kr = len - 1;
                cp16(ka + (bo * K_FLOATS + r * QK_STRIDE + c4) * 4,
                     K + (size_t)(off + kr) * CD + z * 80 + c4, nb);
            }
            for (int ch = tid; ch < 640; ch += 256) {
                int n = ch >> 3, r8 = ch & 7;
                int row = ktn + r8 * 8;
                int nb = (len - row) * 2; nb = nb < 0 ? 0 : (nb > 16 ? 16 : nb);
                int rowc = (row < len) ? row : 0;
                cp16(va + (bo * V_WORDS + n * 36 + r8 * 4) * 4,
                     Vsrc + (size_t)(z * 80 + n) * PSEQ + off + rowc, nb);
            }
        }
        CP_COMMIT(); CP_WAIT1();
        __syncthreads();
        const float* Kb = Ks + (it & 1) * K_FLOATS;
        const uint32_t* Vb = VT + (it & 1) * V_WORDS;

        // ---- S = Q K^T (tf32, K=80), 64 keys ----
        float accS[8][4];
        #pragma unroll
        for (int jj = 0; jj < 8; jj++)
            accS[jj][0] = accS[jj][1] = accS[jj][2] = accS[jj][3] = 0.f;
        #pragma unroll
        for (int s8 = 0; s8 < 80; s8 += 8) {
            int ac = s8 + (lane & 3);
            uint32_t a[4];
            a[0] = rtf(Qs[rbase * QK_STRIDE + ac]);
            a[1] = rtf(Qs[(rbase + 8) * QK_STRIDE + ac]);
            a[2] = rtf(Qs[rbase * QK_STRIDE + ac + 4]);
            a[3] = rtf(Qs[(rbase + 8) * QK_STRIDE + ac + 4]);
            #pragma unroll
            for (int jj = 0; jj < 8; jj++) {
                int bc = jj * 8 + (lane >> 2);
                uint32_t b[2] = { rtf(Kb[bc * QK_STRIDE + ac]),
                                  rtf(Kb[bc * QK_STRIDE + ac + 4]) };
                mma_tf32(accS[jj], a, b);
            }
        }
        // ---- mask + scale + online softmax (warp-local) ----
        if (kt + 64 > len) {
            #pragma unroll
            for (int jj = 0; jj < 8; jj++) {
                int c0 = kt + jj * 8 + t2;
                if (c0 >= len)     { accS[jj][0] = -1e30f; accS[jj][2] = -1e30f; }
                if (c0 + 1 >= len) { accS[jj][1] = -1e30f; accS[jj][3] = -1e30f; }
            }
        }
        float mt0 = -1e30f, mt1 = -1e30f;
        #pragma unroll
        for (int jj = 0; jj < 8; jj++) {
            #pragma unroll
            for (int e = 0; e < 4; e++) accS[jj][e] *= scale;
            mt0 = fmaxf(mt0, fmaxf(accS[jj][0], accS[jj][1]));
            mt1 = fmaxf(mt1, fmaxf(accS[jj][2], accS[jj][3]));
        }
        mt0 = fmaxf(mt0, __shfl_xor_sync(0xffffffffu, mt0, 1));
        mt0 = fmaxf(mt0, __shfl_xor_sync(0xffffffffu, mt0, 2));
        mt1 = fmaxf(mt1, __shfl_xor_sync(0xffffffffu, mt1, 1));
        mt1 = fmaxf(mt1, __shfl_xor_sync(0xffffffffu, mt1, 2));
        float mn0 = fmaxf(m_run[0], mt0), mn1 = fmaxf(m_run[1], mt1);
        float f0 = __expf(m_run[0] - mn0), f1 = __expf(m_run[1] - mn1);
        m_run[0] = mn0; m_run[1] = mn1;
        float s0 = 0.f, s1 = 0.f;
        #pragma unroll
        for (int jj = 0; jj < 8; jj++) {
            accS[jj][0] = __expf(accS[jj][0] - mn0); s0 += accS[jj][0];
            accS[jj][1] = __expf(accS[jj][1] - mn0); s0 += accS[jj][1];
            accS[jj][2] = __expf(accS[jj][2] - mn1); s1 += accS[jj][2];
            accS[jj][3] = __expf(accS[jj][3] - mn1); s1 += accS[jj][3];
        }
        s0 += __shfl_xor_sync(0xffffffffu, s0, 1);
        s0 += __shfl_xor_sync(0xffffffffu, s0, 2);
        s1 += __shfl_xor_sync(0xffffffffu, s1, 1);
        s1 += __shfl_xor_sync(0xffffffffu, s1, 2);
        l_run[0] = l_run[0] * f0 + s0;
        l_run[1] = l_run[1] * f1 + s1;
        #pragma unroll
        for (int c = 0; c < 10; c++) {
            accO[c][0] *= f0; accO[c][1] *= f0; accO[c][2] *= f1; accO[c][3] *= f1;
        }
        // ---- O += P(bf16) @ V(bf16), contraction over 64 keys ----
        #pragma unroll
        for (int u = 0; u < 4; u++) {
            uint32_t pa[4];
            pa[0] = bfpack(accS[2 * u][0],     accS[2 * u][1]);
            pa[1] = bfpack(accS[2 * u][2],     accS[2 * u][3]);
            pa[2] = bfpack(accS[2 * u + 1][0], accS[2 * u + 1][1]);
            pa[3] = bfpack(accS[2 * u + 1][2], accS[2 * u + 1][3]);
            #pragma unroll
            for (int c = 0; c < 10; c++) {
                int base = (c * 8 + (lane >> 2)) * 36 + u * 8 + (lane & 3);
                uint32_t b[2] = { Vb[base], Vb[base + 4] };
                mma_bf16(accO[c], pa, b);
            }
        }
        __syncthreads();
    }

    // ---- epilogue: normalize + write ----
    float inv0 = 1.0f / l_run[0], inv1 = 1.0f / l_run[1];
    int r0 = q0 + w * 16 + (lane >> 2);
    int r1 = r0 + 8;
    int cb = z * 80 + t2;
    #pragma unroll
    for (int c = 0; c < 10; c++) {
        int col = cb + c * 8;
        if (r0 < cnt) {
            size_t o = (size_t)(off + r0) * CD + col;
            float v0 = accO[c][0] * inv0, v1 = accO[c][1] * inv0;
            if (accumulate) { g_hs[o] += v0; g_hs[o + 1] += v1; }
            else            { g_hs[o]  = v0; g_hs[o + 1]  = v1; }
        }
        if (r1 < cnt) {
            size_t o = (size_t)(off + r1) * CD + col;
            float v2 = accO[c][2] * inv1, v3 = accO[c][3] * inv1;
            if (accumulate) { g_hs[o] += v2; g_hs[o + 1] += v3; }
            else            { g_hs[o]  = v2; g_hs[o + 1]  = v3; }
        }
    }
}

// ---------------------------------------------------------------------------
// ENTITY branch (d=640): materialized scores (tf32) -> softmax -> AV (tf32)
// ---------------------------------------------------------------------------
__global__ __launch_bounds__(256) void scores_kernel(int qsel, int ksel,
                                                     int headDim, float scale) {
    __shared__ float Qs[2][128 * 20];
    __shared__ float Ks[2][128 * 20];
    int qt = blockIdx.x;
    if (qt >= d_nqtiles) return;
    int g = d_qtileG[qt], q0 = d_qtileQ0[qt];
    int cnt = d_cnt[g];
    int len = cnt;
    int k0t = blockIdx.y * 128;
    if (k0t >= len) return;
    int off = d_off[g];
    int stride = d_cntPad[g];
    const float* Q = g_proj + (size_t)qsel * PSEQ * CD;
    const float* K = g_proj + (size_t)ksel * PSEQ * CD;
    float* Sc = g_scores + (size_t)d_scbase[g];
    int tid = threadIdx.x, lane = tid & 31, warp = tid >> 5;
    int wm = warp & 3, wn = warp >> 2;
    uint32_t qb = smem_u32(Qs), kb = smem_u32(Ks);
    int NS = headDim / 16;

    for (int ch = tid; ch < 512; ch += 256) {
        int r = ch >> 2, c4 = (ch & 3) * 4;
        int qr = q0 + r, kr = k0t + r;
        int qv = (qr < cnt) ? 16 : 0;
        int kv = (kr < len) ? 16 : 0;
        if (qr >= cnt) qr = cnt - 1;
        if (kr >= len) kr = len - 1;
        cp16(qb + (r * 20 + c4) * 4, Q + (size_t)(off + qr) * CD + c4, qv);
        cp16(kb + (r * 20 + c4) * 4, K + (size_t)(off + kr) * CD + c4, kv);
    }
    CP_COMMIT();

    float acc[2][8][4] = {};
    for (int s = 0; s < NS; s++) {
        if (s + 1 < NS) {
            int k0 = (s + 1) * 16;
            int bo = ((s + 1) & 1) * 2560;
            for (int ch = tid; ch < 512; ch += 256) {
                int r = ch >> 2, c4 = (ch & 3) * 4;
                int qr = q0 + r, kr = k0t + r;
                int qv = (qr < cnt) ? 16 : 0;
                int kv = (kr < len) ? 16 : 0;
                if (qr >= cnt) qr = cnt - 1;
                if (kr >= len) kr = len - 1;
                cp16(qb + (bo + r * 20 + c4) * 4, Q + (size_t)(off + qr) * CD + k0 + c4, qv);
                cp16(kb + (bo + r * 20 + c4) * 4, K + (size_t)(off + kr) * CD + k0 + c4, kv);
            }
        }
        CP_COMMIT(); CP_WAIT1();
        __syncthreads();
        const float* Qb = Qs[s & 1];
        const float* Kb = Ks[s & 1];
        #pragma unroll
        for (int k8 = 0; k8 < 16; k8 += 8) {
            int ac = k8 + (lane & 3);
            int ar = wm * 32 + (lane >> 2);
            uint32_t a[2][4];
            #pragma unroll
            for (int i = 0; i < 2; i++) {
                a[i][0] = rtf(Qb[(ar + i * 16) * 20 + ac]);
                a[i][1] = rtf(Qb[(ar + i * 16 + 8) * 20 + ac]);
                a[i][2] = rtf(Qb[(ar + i * 16) * 20 + ac + 4]);
                a[i][3] = rtf(Qb[(ar + i * 16 + 8) * 20 + ac + 4]);
            }
            #pragma unroll
            for (int j = 0; j < 8; j++) {
                int bc = wn * 64 + j * 8 + (lane >> 2);
                uint32_t b[2] = { rtf(Kb[bc * 20 + ac]), rtf(Kb[bc * 20 + ac + 4]) };
                mma_tf32(acc[0][j], a[0], b);
                mma_tf32(acc[1][j], a[1], b);
            }
        }
        __syncthreads();
    }
    int mr = q0 + wm * 32 + (lane >> 2);
    int nc = k0t + wn * 64 + 2 * (lane & 3);
    #pragma unroll
    for (int i = 0; i < 2; i++) {
        int r0 = mr + i * 16;
        #pragma unroll
        for (int j = 0; j < 8; j++) {
            int c = nc + j * 8;
            *(float2*)&Sc[(size_t)r0 * stride + c] =
                make_float2(acc[i][j][0] * scale, acc[i][j][1] * scale);
            *(float2*)&Sc[(size_t)(r0 + 8) * stride + c] =
                make_float2(acc[i][j][2] * scale, acc[i][j][3] * scale);
        }
    }
}

__global__ __launch_bounds__(256) void softmax_kernel() {
    __shared__ float buf[SEQ];
    __shared__ float red[256];
    int row = blockIdx.x;
    int g = d_rowg[row];
    if (g < 0) return;
    int rl = d_rowloc[row];
    int len = d_cnt[g];
    float* p = g_scores + (size_t)d_scbase[g] + (size_t)rl * d_cntPad[g];
    int tid = threadIdx.x;
    float mx = -INFINITY;
    for (int i = tid; i < len; i += 256) { float v = p[i]; buf[i] = v; mx = fmaxf(mx, v); }
    red[tid] = mx; __syncthreads();
    for (int s = 128; s > 0; s >>= 1) {
        if (tid < s) red[tid] = fmaxf(red[tid], red[tid + s]);
        __syncthreads();
    }
    mx = red[0]; __syncthreads();
    float sum = 0.f;
    for (int i = tid; i < len; i += 256) { float e = __expf(buf[i] - mx); buf[i] = e; sum += e; }
    red[tid] = sum; __syncthreads();
    for (int s = 128; s > 0; s >>= 1) {
        if (tid < s) red[tid] += red[tid + s];
        __syncthreads();
    }
    float inv = 1.0f / red[0];
    for (int i = tid; i < len; i += 256) p[i] = buf[i] * inv;
}

__global__ __launch_bounds__(256) void av_kernel(int vsel) {
    __shared__ float Ps[2][128 * 20];
    __shared__ float Vs[2][16 * 88];
    int qt = blockIdx.x;
    if (qt >= d_nqtiles) return;
    int g = d_qtileG[qt], q0 = d_qtileQ0[qt];
    int cnt = d_cnt[g];
    int len = cnt;
    int off = d_off[g];
    int stride = d_cntPad[g];
    int c0 = blockIdx.y * 80;
    const float* P = g_scores + (size_t)d_scbase[g];
    const float* V = g_proj + (size_t)vsel * PSEQ * CD;
    int tid = threadIdx.x, lane = tid & 31, warp = tid >> 5;
    int wm = warp & 3, wn = warp >> 2;
    uint32_t pb = smem_u32(Ps), vb = smem_u32(Vs);
    int NS = (len + 15) >> 4;

    for (int ch = tid; ch < 512; ch += 256) {
        int r = ch >> 2, c4 = (ch & 3) * 4;
        int nb = (len - c4) * 4;
        nb = nb < 0 ? 0 : (nb > 16 ? 16 : nb);
        cp16(pb + (r * 20 + c4) * 4, P + (size_t)(q0 + r) * stride + c4, nb);
    }
    for (int ch = tid; ch < 320; ch += 256) {
        int r = ch / 20, c4 = (ch % 20) * 4;
        int rv = (r < len) ? 16 : 0;
        int rr = (r < len) ? r : (len - 1);
        cp16(vb + (r * 88 + c4) * 4, V + (size_t)(off + rr) * CD + c0 + c4, rv);
    }
    CP_COMMIT();

    float acc[2][5][4] = {};
    for (int s = 0; s < NS; s++) {
        if (s + 1 < NS) {
            int k0 = (s + 1) * 16;
            int bo = ((s + 1) & 1);
            for (int ch = tid; ch < 512; ch += 256) {
                int r = ch >> 2, c4 = (ch & 3) * 4;
                int nb = (len - (k0 + c4)) * 4;
                nb = nb < 0 ? 0 : (nb > 16 ? 16 : nb);
                cp16(pb + (bo * 2560 + r * 20 + c4) * 4,
                     P + (size_t)(q0 + r) * stride + k0 + c4, nb);
            }
            for (int ch = tid; ch < 320; ch += 256) {
                int r = ch / 20, c4 = (ch % 20) * 4;
                int rv = (k0 + r < len) ? 16 : 0;
                int rr = (k0 + r < len) ? (k0 + r) : (len - 1);
                cp16(vb + (bo * 1408 + r * 88 + c4) * 4,
                     V + (size_t)(off + rr) * CD + c0 + c4, rv);
            }
        }
        CP_COMMIT(); CP_WAIT1();
        __syncthreads();
        const float* Pb = Ps[s & 1];
        const float* Vb = Vs[s & 1];
        #pragma unroll
        for (int k8 = 0; k8 < 16; k8 += 8) {
            int ac = k8 + (lane & 3);
            int ar = wm * 32 + (lane >> 2);
            uint32_t a[2][4];
            #pragma unroll
            for (int i = 0; i < 2; i++) {
                a[i][0] = rtf(Pb[(ar + i * 16) * 20 + ac]);
                a[i][1] = rtf(Pb[(ar + i * 16 + 8) * 20 + ac]);
                a[i][2] = rtf(Pb[(ar + i * 16) * 20 + ac + 4]);
                a[i][3] = rtf(Pb[(ar + i * 16 + 8) * 20 + ac + 4]);
            }
            #pragma unroll
            for (int j = 0; j < 5; j++) {
                int bc = wn * 40 + j * 8 + (lane >> 2);
                uint32_t b[2] = { rtf(Vb[ac * 88 + bc]), rtf(Vb[(ac + 4) * 88 + bc]) };
                mma_tf32(acc[0][j], a[0], b);
                mma_tf32(acc[1][j], a[1], b);
            }
        }
        __syncthreads();
    }
    int mi = wm * 32 + (lane >> 2);
    int nc = c0 + wn * 40 + 2 * (lane & 3);
    #pragma unroll
    for (int i = 0; i < 2; i++) {
        int r0 = q0 + mi + i * 16;
        int r1 = r0 + 8;
        #pragma unroll
        for (int j = 0; j < 5; j++) {
            int c = nc + j * 8;
            if (r0 < cnt) {
                size_t o = (size_t)(off + r0) * CD + c;
                g_hs[o] += acc[i][j][0]; g_hs[o + 1] += acc[i][j][1];
            }
            if (r1 < cnt) {
                size_t o = (size_t)(off + r1) * CD + c;
                g_hs[o] += acc[i][j][2]; g_hs[o + 1] += acc[i][j][3];
            }
        }
    }
}

// ---------------------------------------------------------------------------
// fallback mean of V_out rows: branch-free (rowmask multiply keeps MLP high)
// ---------------------------------------------------------------------------
__global__ void meanv_kernel() {
    int col = threadIdx.x;
    const float* V = g_proj + 8ull * PSEQ * CD;
    int r0 = blockIdx.x * 256;
    float s = 0.f;
    #pragma unroll 4
    for (int r = 0; r < 256; r++) {
        int row = r0 + r;
        s += V[(size_t)row * CD + col] * g_rowmask[row];
    }
    atomicAdd(&g_meanVo[col], s * (1.0f / SEQ));
}

__global__ void fb_kernel() {
    int row = blockIdx.x;
    int g = d_rowg[row];
    if (g < 0 || d_cntOut[g] != 0) return;
    for (int c = threadIdx.x; c < CD; c += 256)
        g_hs[(size_t)row * CD + c] += g_meanVo[c];
}

// ---------------------------------------------------------------------------
__global__ __launch_bounds__(256) void final_kernel(const float* __restrict__ Wo,
                                                    const float* __restrict__ resid,
                                                    float* __restrict__ Y) {
    __shared__ float Xs[2][128 * 20];
    __shared__ float Bs[2][128 * 20];
    __shared__ int ip[128];
    int n0 = blockIdx.x * 128, m0 = blockIdx.y * 128;
    int tid = threadIdx.x, lane = tid & 31, warp = tid >> 5;
    int wm = warp & 3, wn = warp >> 2;
    if (tid < 128) ip[tid] = g_iperm[m0 + tid];
    __syncthreads();
    uint32_t xb = smem_u32(Xs), bb = smem_u32(Bs);

    for (int ch = tid; ch < 512; ch += 256) {
        int r = ch >> 2, c4 = (ch & 3) * 4;
        cp16(xb + (r * 20 + c4) * 4, g_hs + (size_t)ip[r] * CD + c4, 16);
        cp16(bb + (r * 20 + c4) * 4, Wo + (size_t)(n0 + r) * CD + c4, 16);
    }
    CP_COMMIT();

    float acc[2][8][4] = {};
    for (int s = 0; s < 40; s++) {
        if (s + 1 < 40) {
            int k0 = (s + 1) * 16;
            int bo = ((s + 1) & 1) * 2560;
            for (int ch = tid; ch < 512; ch += 256) {
                int r = ch >> 2, c4 = (ch & 3) * 4;
                cp16(xb + (bo + r * 20 + c4) * 4, g_hs + (size_t)ip[r] * CD + k0 + c4, 16);
                cp16(bb + (bo + r * 20 + c4) * 4, Wo + (size_t)(n0 + r) * CD + k0 + c4, 16);
            }
        }
        CP_COMMIT(); CP_WAIT1();
        __syncthreads();
        const float* Xb = Xs[s & 1];
        const float* Bb = Bs[s & 1];
        #pragma unroll
        for (int k8 = 0; k8 < 16; k8 += 8) {
            int ac = k8 + (lane & 3);
            int ar = wm * 32 + (lane >> 2);
            uint32_t a[2][4];
            #pragma unroll
            for (int i = 0; i < 2; i++) {
                a[i][0] = rtf(Xb[(ar + i * 16) * 20 + ac]);
                a[i][1] = rtf(Xb[(ar + i * 16 + 8) * 20 + ac]);
                a[i][2] = rtf(Xb[(ar + i * 16) * 20 + ac + 4]);
                a[i][3] = rtf(Xb[(ar + i * 16 + 8) * 20 + ac + 4]);
            }
            #pragma unroll
            for (int j = 0; j < 8; j++) {
                int bc = wn * 64 + j * 8 + (lane >> 2);
                uint32_t b[2] = { rtf(Bb[bc * 20 + ac]), rtf(Bb[bc * 20 + ac + 4]) };
                mma_tf32(acc[0][j], a[0], b);
                mma_tf32(acc[1][j], a[1], b);
            }
        }
        __syncthreads();
    }
    int mi = wm * 32 + (lane >> 2);
    int nc = n0 + wn * 64 + 2 * (lane & 3);
    #pragma unroll
    for (int i = 0; i < 2; i++) {
        #pragma unroll
        for (int j = 0; j < 8; j++) {
            int c = nc + j * 8;
            size_t o0 = (size_t)(m0 + mi + i * 16) * CD + c;
            size_t o1 = (size_t)(m0 + mi + i * 16 + 8) * CD + c;
            Y[o0]     = acc[i][j][0] + resid[o0];
            Y[o0 + 1] = acc[i][j][1] + resid[o0 + 1];
            Y[o1]     = acc[i][j][2] + resid[o1];
            Y[o1 + 1] = acc[i][j][3] + resid[o1 + 1];
        }
    }
}

// ---------------------------------------------------------------------------
extern "C" void kernel_launch(void* const* d_in, const int* in_sizes, int n_in,
                              void* d_out, int out_size) {
    const float* hidden = (const float*)d_in[0];
    const int*   mask   = (const int*)d_in[1];
    const int*   inp    = (const int*)d_in[2];
    W9 ws;
    for (int i = 0; i < 9; i++) ws.w[i] = (const float*)d_in[3 + i];
    const float* Wo = (const float*)d_in[12];
    float* out = (float*)d_out;

    const float s80  = 1.0f / sqrtf(80.0f);
    const float s640 = 1.0f / sqrtf(640.0f);

    cudaFuncSetAttribute(fa_kernel, cudaFuncAttributeMaxDynamicSharedMemorySize, FA_SMEM_BYTES);

    labels_kernel<<<16, 256>>>(mask, inp);
    prep_kernel<<<1, 256>>>();
    proj_kernel<<<dim3(5, 32, 9), 256>>>(hidden, ws);
    meanv_kernel<<<18, 640>>>();

    // proj indices: 0=q 1=k 2=v 3=q_ent 4=k_ent 5=v_ent 6=q_out 7=k_out 8=v_out
    fa_kernel<<<dim3(40, 8), 256, FA_SMEM_BYTES>>>(0, 1, 0, s80, 0, 0);   // orig: writes g_hs

    scores_kernel<<<dim3(40, 32), 256>>>(3, 4, 640, s640);                // entity
    softmax_kernel<<<PSEQ, 256>>>();
    av_kernel<<<dim3(40, 8), 256>>>(5);                                   // entity: accumulates

    fa_kernel<<<dim3(40, 8), 256, FA_SMEM_BYTES>>>(6, 7, 1, s80, 1, 1);   // outside: accumulates

    fb_kernel<<<PSEQ, 256>>>();
    final_kernel<<<dim3(5, 32), 256>>>(Wo, hidden, out);
}

// round 15
// speedup vs baseline: 18.5859x; 1.0425x over previous
#include <cuda_runtime.h>
#include <cuda_bf16.h>
#include <math.h>
#include <stdint.h>

#define SEQ  4096
#define PSEQ 4608                                  // padded permuted row space (group offs 128-aligned)
#define CD   640
#define MATSZ ((size_t)SEQ * SEQ + (1u << 21))     // entity score arena

// ---- device scratch (static; no runtime allocation) ----
__device__ float g_proj[9ull * PSEQ * CD];         // 9 projections, PERMUTED(padded) rows
__device__ __nv_bfloat16 g_vbfT[2ull * CD * PSEQ]; // bf16 TRANSPOSED V (orig=0, outside=1): [col][row]
__device__ float g_scores[MATSZ];                  // entity score matrix (grouped)
__device__ float g_hs[(size_t)PSEQ * CD];          // attention output, permuted rows
__device__ float g_meanVo[CD];
__device__ float g_rowmask[PSEQ];                  // 1.0 for real rows, 0.0 for gaps
__device__ int   g_lab[SEQ];
__device__ int   g_outs[SEQ];
__device__ int   g_iperm[SEQ];                     // original row -> padded permuted row
__device__ int   d_off[4], d_cnt[4], d_cntOut[4], d_cntPad[4];
__device__ long long d_scbase[4];
__device__ int   d_qtileG[40], d_qtileQ0[40];
__device__ int   d_nqtiles;
__device__ int   d_rowg[PSEQ], d_rowloc[PSEQ];     // -1 for gap rows

// ---------------------------------------------------------------------------
__device__ __forceinline__ uint32_t rtf(float x) {          // fp32 bits + half-tf32-ulp => rna-ish
    return __float_as_uint(x) + 0x1000u;
}
__device__ __forceinline__ void mma_tf32(float d[4], const uint32_t a[4], const uint32_t b[2]) {
    asm volatile(
        "mma.sync.aligned.m16n8k8.row.col.f32.tf32.tf32.f32 "
        "{%0,%1,%2,%3}, {%4,%5,%6,%7}, {%8,%9}, {%0,%1,%2,%3};\n"
        : "+f"(d[0]), "+f"(d[1]), "+f"(d[2]), "+f"(d[3])
        : "r"(a[0]), "r"(a[1]), "r"(a[2]), "r"(a[3]), "r"(b[0]), "r"(b[1]));
}
__device__ __forceinline__ void mma_bf16(float d[4], const uint32_t a[4], const uint32_t b[2]) {
    asm volatile(
        "mma.sync.aligned.m16n8k16.row.col.f32.bf16.bf16.f32 "
        "{%0,%1,%2,%3}, {%4,%5,%6,%7}, {%8,%9}, {%0,%1,%2,%3};\n"
        : "+f"(d[0]), "+f"(d[1]), "+f"(d[2]), "+f"(d[3])
        : "r"(a[0]), "r"(a[1]), "r"(a[2]), "r"(a[3]), "r"(b[0]), "r"(b[1]));
}
__device__ __forceinline__ uint32_t bfpack(float lo, float hi) {   // lo -> bits[15:0]
    uint32_t d; asm("cvt.rn.bf16x2.f32 %0, %1, %2;" : "=r"(d) : "f"(hi), "f"(lo)); return d;
}
__device__ __forceinline__ uint32_t smem_u32(const void* p) {
    return (uint32_t)__cvta_generic_to_shared(p);
}
__device__ __forceinline__ void cp16(uint32_t dst, const void* src, int nbytes) {
    asm volatile("cp.async.cg.shared.global [%0], [%1], 16, %2;\n"
                 :: "r"(dst), "l"(src), "r"(nbytes));
}
#define CP_COMMIT() asm volatile("cp.async.commit_group;\n")
#define CP_WAIT1()  asm volatile("cp.async.wait_group 1;\n")

// ---------------------------------------------------------------------------
__global__ void labels_kernel(const int* __restrict__ mask,
                              const int* __restrict__ inp) {
    int t = blockIdx.x * blockDim.x + threadIdx.x;
    if (t < CD) g_meanVo[t] = 0.f;
    if (t >= SEQ) return;
    int i = t >> 6, j = t & 63;
    int idx = (i * 8) * 512 + j * 8;
    g_lab[t]  = mask[idx];
    g_outs[t] = (inp[idx] == 0) ? 1 : 0;
}

// ---------------------------------------------------------------------------
// zero g_hs (fa branches now accumulate atomically into it)
// ---------------------------------------------------------------------------
__global__ void zero_hs_kernel() {
    size_t i = (size_t)blockIdx.x * blockDim.x + threadIdx.x;
    if (i < (size_t)PSEQ * CD / 4)
        ((float4*)g_hs)[i] = make_float4(0.f, 0.f, 0.f, 0.f);
}

// ---------------------------------------------------------------------------
// prep: bucket sort by (label, !outside); group offsets 128-ALIGNED (padded)
// ---------------------------------------------------------------------------
__global__ void prep_kernel() {
    __shared__ int cnt8[8], off8[8], cur8[8];
    int tid = threadIdx.x;
    if (tid < 8) cnt8[tid] = 0;
    __syncthreads();
    for (int t = tid; t < SEQ; t += 256) {
        int b = g_lab[t] * 2 + (g_outs[t] ? 0 : 1);
        atomicAdd(&cnt8[b], 1);
    }
    __syncthreads();
    if (tid == 0) {
        long long sb = 0; int nq = 0; int cum = 0;
        for (int g = 0; g < 4; g++) {
            int c = cnt8[2 * g] + cnt8[2 * g + 1];
            d_off[g] = cum;
            off8[2 * g] = cum; off8[2 * g + 1] = cum + cnt8[2 * g];
            d_cnt[g] = c; d_cntOut[g] = cnt8[2 * g];
            int pad = ((c + 127) >> 7) << 7;
            d_cntPad[g] = pad;
            d_scbase[g] = sb; sb += (long long)pad * pad;
            for (int j = 0; j < c; j += 128) { d_qtileG[nq] = g; d_qtileQ0[nq] = j; nq++; }
            cum = (cum + c + 127) & ~127;
        }
        d_nqtiles = nq;
    }
    __syncthreads();
    if (tid < 8) cur8[tid] = off8[tid];
    __syncthreads();
    for (int t = tid; t < SEQ; t += 256) {
        int b = g_lab[t] * 2 + (g_outs[t] ? 0 : 1);
        g_iperm[t] = atomicAdd(&cur8[b], 1);
    }
    __syncthreads();
    for (int i = tid; i < PSEQ; i += 256) {
        int gg = -1, loc = 0;
        for (int g = 0; g < 4; g++)
            if (i >= d_off[g] && i < d_off[g] + d_cnt[g]) { gg = g; loc = i - d_off[g]; }
        d_rowg[i] = gg; d_rowloc[i] = loc;
        g_rowmask[i] = (gg >= 0) ? 1.0f : 0.0f;
    }
}

// ---------------------------------------------------------------------------
// 9 projections via tf32 mma + cp.async; V projections (z=2,8) also emitted
// as bf16 TRANSPOSED copies for the flash kernel.
// ---------------------------------------------------------------------------
struct W9 { const float* w[9]; };

__global__ __launch_bounds__(256) void proj_kernel(const float* __restrict__ X, W9 ws) {
    __shared__ float Xs[2][128 * 20];
    __shared__ float Bs[2][128 * 20];
    __shared__ int ip[128];
    int z = blockIdx.z;
    const float* W = ws.w[z];
    float* Y = g_proj + (size_t)z * PSEQ * CD;
    int n0 = blockIdx.x * 128, m0 = blockIdx.y * 128;
    int tid = threadIdx.x, lane = tid & 31, warp = tid >> 5;
    int wm = warp & 3, wn = warp >> 2;
    if (tid < 128) ip[tid] = g_iperm[m0 + tid];
    uint32_t xb = smem_u32(Xs), bb = smem_u32(Bs);

    for (int ch = tid; ch < 512; ch += 256) {
        int r = ch >> 2, c4 = (ch & 3) * 4;
        cp16(xb + (r * 20 + c4) * 4, X + (size_t)(m0 + r) * CD + c4, 16);
        cp16(bb + (r * 20 + c4) * 4, W + (size_t)(n0 + r) * CD + c4, 16);
    }
    CP_COMMIT();

    float acc[2][8][4] = {};
    for (int s = 0; s < 40; s++) {
        if (s + 1 < 40) {
            int k0 = (s + 1) * 16;
            int bo = ((s + 1) & 1) * 2560;
            for (int ch = tid; ch < 512; ch += 256) {
                int r = ch >> 2, c4 = (ch & 3) * 4;
                cp16(xb + (bo + r * 20 + c4) * 4, X + (size_t)(m0 + r) * CD + k0 + c4, 16);
                cp16(bb + (bo + r * 20 + c4) * 4, W + (size_t)(n0 + r) * CD + k0 + c4, 16);
            }
        }
        CP_COMMIT(); CP_WAIT1();
        __syncthreads();
        const float* Xb = Xs[s & 1];
        const float* Bb = Bs[s & 1];
        #pragma unroll
        for (int k8 = 0; k8 < 16; k8 += 8) {
            int ac = k8 + (lane & 3);
            int ar = wm * 32 + (lane >> 2);
            uint32_t a[2][4];
            #pragma unroll
            for (int i = 0; i < 2; i++) {
                a[i][0] = rtf(Xb[(ar + i * 16) * 20 + ac]);
                a[i][1] = rtf(Xb[(ar + i * 16 + 8) * 20 + ac]);
                a[i][2] = rtf(Xb[(ar + i * 16) * 20 + ac + 4]);
                a[i][3] = rtf(Xb[(ar + i * 16 + 8) * 20 + ac + 4]);
            }
            #pragma unroll
            for (int j = 0; j < 8; j++) {
                int bc = wn * 64 + j * 8 + (lane >> 2);
                uint32_t b[2] = { rtf(Bb[bc * 20 + ac]), rtf(Bb[bc * 20 + ac + 4]) };
                mma_tf32(acc[0][j], a[0], b);
                mma_tf32(acc[1][j], a[1], b);
            }
        }
        __syncthreads();
    }
    int mi = wm * 32 + (lane >> 2);
    int nc = n0 + wn * 64 + 2 * (lane & 3);
    #pragma unroll
    for (int i = 0; i < 2; i++) {
        int pr0 = ip[mi + i * 16], pr1 = ip[mi + i * 16 + 8];
        #pragma unroll
        for (int j = 0; j < 8; j++) {
            int c = nc + j * 8;
            *(float2*)&Y[(size_t)pr0 * CD + c] = make_float2(acc[i][j][0], acc[i][j][1]);
            *(float2*)&Y[(size_t)pr1 * CD + c] = make_float2(acc[i][j][2], acc[i][j][3]);
        }
    }
    if (z == 2 || z == 8) {
        __nv_bfloat16* VT = g_vbfT + (z == 8 ? (size_t)CD * PSEQ : 0);
        #pragma unroll
        for (int i = 0; i < 2; i++) {
            int pr0 = ip[mi + i * 16], pr1 = ip[mi + i * 16 + 8];
            #pragma unroll
            for (int j = 0; j < 8; j++) {
                int c = nc + j * 8;
                VT[(size_t)c * PSEQ + pr0]       = __float2bfloat16(acc[i][j][0]);
                VT[(size_t)(c + 1) * PSEQ + pr0] = __float2bfloat16(acc[i][j][1]);
                VT[(size_t)c * PSEQ + pr1]       = __float2bfloat16(acc[i][j][2]);
                VT[(size_t)(c + 1) * PSEQ + pr1] = __float2bfloat16(acc[i][j][3]);
            }
        }
    }
}

// ---------------------------------------------------------------------------
// FLASH attention, BOTH d=80 branches in one launch: grid (qtile<=40, head, branch)
// branch 0: orig (q=0,k=1,vbT=0, full group); branch 1: outside (q=6,k=7,vbT=1, prefix)
// Epilogue: atomicAdd into zeroed g_hs (branches run concurrently).
// K-tile = 64 keys. SMEM 109,056 B -> 2 CTAs/SM.
// ---------------------------------------------------------------------------
#define QK_STRIDE 84
#define Q_FLOATS  (128 * QK_STRIDE)               // 10752
#define K_FLOATS  (64 * QK_STRIDE)                // 5376 per buffer
#define V_WORDS   (80 * 36)                       // 2880 per buffer
#define FA_SMEM_BYTES ((Q_FLOATS + 2 * K_FLOATS + 2 * V_WORDS) * 4)   // 109056

__global__ __launch_bounds__(256, 2) void fa_kernel(float scale) {
    extern __shared__ float sm[];
    float* Qs = sm;                                   // 128 x 84
    float* Ks = sm + Q_FLOATS;                        // 2 x 64 x 84
    uint32_t* VT = (uint32_t*)(sm + Q_FLOATS + 2 * K_FLOATS);  // 2 x 80 x 36 words

    int qt = blockIdx.x;
    if (qt >= d_nqtiles) return;
    int branch = blockIdx.z;
    int qsel = branch ? 6 : 0;
    int ksel = branch ? 7 : 1;
    int g = d_qtileG[qt], q0 = d_qtileQ0[qt];
    int cnt = d_cnt[g];
    int len = branch ? d_cntOut[g] : cnt;
    if (len == 0) return;
    int off = d_off[g];
    int z = blockIdx.y;
    const float* Q = g_proj + (size_t)qsel * PSEQ * CD;
    const float* K = g_proj + (size_t)ksel * PSEQ * CD;
    const __nv_bfloat16* Vsrc = g_vbfT + (size_t)branch * CD * PSEQ;

    int tid = threadIdx.x, lane = tid & 31, w = tid >> 5;
    int t2 = (lane & 3) * 2;
    int rbase = w * 16 + (lane >> 2);
    uint32_t qa = smem_u32(Qs), ka = smem_u32(Ks), va = smem_u32(VT);

    // stage Q (once): 128 rows x 20 chunks
    for (int ch = tid; ch < 2560; ch += 256) {
        int r = ch / 20, c4 = (ch % 20) * 4;
        int qr = q0 + r; int nb = (qr < cnt) ? 16 : 0; if (qr >= cnt) qr = cnt - 1;
        cp16(qa + (r * QK_STRIDE + c4) * 4, Q + (size_t)(off + qr) * CD + z * 80 + c4, nb);
    }
    // stage K0 (64 rows) + V0 (80 cols x 8 chunks of 64 keys)
    for (int ch = tid; ch < 1280; ch += 256) {
        int r = ch / 20, c4 = (ch % 20) * 4;
        int kr = r; int nb = (kr < len) ? 16 : 0; if (kr >= len) kr = len - 1;
        cp16(ka + (r * QK_STRIDE + c4) * 4, K + (size_t)(off + kr) * CD + z * 80 + c4, nb);
    }
    for (int ch = tid; ch < 640; ch += 256) {
        int n = ch >> 3, r8 = ch & 7;
        int row = r8 * 8;
        int nb = (len - row) * 2; nb = nb < 0 ? 0 : (nb > 16 ? 16 : nb);
        int rowc = (row < len) ? row : 0;
        cp16(va + (n * 36 + r8 * 4) * 4,
             Vsrc + (size_t)(z * 80 + n) * PSEQ + off + rowc, nb);
    }
    CP_COMMIT();

    float accO[10][4] = {};
    float m_run[2] = {-1e30f, -1e30f}, l_run[2] = {0.f, 0.f};
    int nkt = (len + 63) >> 6;

    for (int it = 0; it < nkt; it++) {
        int kt = it * 64;
        if (it + 1 < nkt) {
            int ktn = kt + 64;
            int bo = (it + 1) & 1;
            for (int ch = tid; ch < 1280; ch += 256) {
                int r = ch / 20, c4 = (ch % 20) * 4;
                int kr = ktn + r; int nb = (kr < len) ? 16 : 0; if (kr >= len) kr = len - 1;
                cp16(ka + (bo * K_FLOATS + r * QK_STRIDE + c4) * 4,
                     K + (size_t)(off + kr) * CD + z * 80 + c4, nb);
            }
            for (int ch = tid; ch < 640; ch += 256) {
                int n = ch >> 3, r8 = ch & 7;
                int row = ktn + r8 * 8;
                int nb = (len - row) * 2; nb = nb < 0 ? 0 : (nb > 16 ? 16 : nb);
                int rowc = (row < len) ? row : 0;
                cp16(va + (bo * V_WORDS + n * 36 + r8 * 4) * 4,
                     Vsrc + (size_t)(z * 80 + n) * PSEQ + off + rowc, nb);
            }
        }
        CP_COMMIT(); CP_WAIT1();
        __syncthreads();
        const float* Kb = Ks + (it & 1) * K_FLOATS;
        const uint32_t* Vb = VT + (it & 1) * V_WORDS;

        // ---- S = Q K^T (tf32, K=80), 64 keys ----
        float accS[8][4];
        #pragma unroll
        for (int jj = 0; jj < 8; jj++)
            accS[jj][0] = accS[jj][1] = accS[jj][2] = accS[jj][3] = 0.f;
        #pragma unroll
        for (int s8 = 0; s8 < 80; s8 += 8) {
            int ac = s8 + (lane & 3);
            uint32_t a[4];
            a[0] = rtf(Qs[rbase * QK_STRIDE + ac]);
            a[1] = rtf(Qs[(rbase + 8) * QK_STRIDE + ac]);
            a[2] = rtf(Qs[rbase * QK_STRIDE + ac + 4]);
            a[3] = rtf(Qs[(rbase + 8) * QK_STRIDE + ac + 4]);
            #pragma unroll
            for (int jj = 0; jj < 8; jj++) {
                int bc = jj * 8 + (lane >> 2);
                uint32_t b[2] = { rtf(Kb[bc * QK_STRIDE + ac]),
                                  rtf(Kb[bc * QK_STRIDE + ac + 4]) };
                mma_tf32(accS[jj], a, b);
            }
        }
        // ---- mask + scale + online softmax (warp-local) ----
        if (kt + 64 > len) {
            #pragma unroll
            for (int jj = 0; jj < 8; jj++) {
                int c0 = kt + jj * 8 + t2;
                if (c0 >= len)     { accS[jj][0] = -1e30f; accS[jj][2] = -1e30f; }
                if (c0 + 1 >= len) { accS[jj][1] = -1e30f; accS[jj][3] = -1e30f; }
            }
        }
        float mt0 = -1e30f, mt1 = -1e30f;
        #pragma unroll
        for (int jj = 0; jj < 8; jj++) {
            #pragma unroll
            for (int e = 0; e < 4; e++) accS[jj][e] *= scale;
            mt0 = fmaxf(mt0, fmaxf(accS[jj][0], accS[jj][1]));
            mt1 = fmaxf(mt1, fmaxf(accS[jj][2], accS[jj][3]));
        }
        mt0 = fmaxf(mt0, __shfl_xor_sync(0xffffffffu, mt0, 1));
        mt0 = fmaxf(mt0, __shfl_xor_sync(0xffffffffu, mt0, 2));
        mt1 = fmaxf(mt1, __shfl_xor_sync(0xffffffffu, mt1, 1));
        mt1 = fmaxf(mt1, __shfl_xor_sync(0xffffffffu, mt1, 2));
        float mn0 = fmaxf(m_run[0], mt0), mn1 = fmaxf(m_run[1], mt1);
        float f0 = __expf(m_run[0] - mn0), f1 = __expf(m_run[1] - mn1);
        m_run[0] = mn0; m_run[1] = mn1;
        float s0 = 0.f, s1 = 0.f;
        #pragma unroll
        for (int jj = 0; jj < 8; jj++) {
            accS[jj][0] = __expf(accS[jj][0] - mn0); s0 += accS[jj][0];
            accS[jj][1] = __expf(accS[jj][1] - mn0); s0 += accS[jj][1];
            accS[jj][2] = __expf(accS[jj][2] - mn1); s1 += accS[jj][2];
            accS[jj][3] = __expf(accS[jj][3] - mn1); s1 += accS[jj][3];
        }
        s0 += __shfl_xor_sync(0xffffffffu, s0, 1);
        s0 += __shfl_xor_sync(0xffffffffu, s0, 2);
        s1 += __shfl_xor_sync(0xffffffffu, s1, 1);
        s1 += __shfl_xor_sync(0xffffffffu, s1, 2);
        l_run[0] = l_run[0] * f0 + s0;
        l_run[1] = l_run[1] * f1 + s1;
        #pragma unroll
        for (int c = 0; c < 10; c++) {
            accO[c][0] *= f0; accO[c][1] *= f0; accO[c][2] *= f1; accO[c][3] *= f1;
        }
        // ---- O += P(bf16) @ V(bf16), contraction over 64 keys ----
        #pragma unroll
        for (int u = 0; u < 4; u++) {
            uint32_t pa[4];
            pa[0] = bfpack(accS[2 * u][0],     accS[2 * u][1]);
            pa[1] = bfpack(accS[2 * u][2],     accS[2 * u][3]);
            pa[2] = bfpack(accS[2 * u + 1][0], accS[2 * u + 1][1]);
            pa[3] = bfpack(accS[2 * u + 1][2], accS[2 * u + 1][3]);
            #pragma unroll
            for (int c = 0; c < 10; c++) {
                int base = (c * 8 + (lane >> 2)) * 36 + u * 8 + (lane & 3);
                uint32_t b[2] = { Vb[base], Vb[base + 4] };
                mma_bf16(accO[c], pa, b);
            }
        }
        __syncthreads();
    }

    // ---- epilogue: normalize + atomic accumulate ----
    float inv0 = 1.0f / l_run[0], inv1 = 1.0f / l_run[1];
    int r0 = q0 + w * 16 + (lane >> 2);
    int r1 = r0 + 8;
    int cb = z * 80 + t2;
    #pragma unroll
    for (int c = 0; c < 10; c++) {
        int col = cb + c * 8;
        if (r0 < cnt) {
            size_t o = (size_t)(off + r0) * CD + col;
            atomicAdd(&g_hs[o],     accO[c][0] * inv0);
            atomicAdd(&g_hs[o + 1], accO[c][1] * inv0);
        }
        if (r1 < cnt) {
            size_t o = (size_t)(off + r1) * CD + col;
            atomicAdd(&g_hs[o],     accO[c][2] * inv1);
            atomicAdd(&g_hs[o + 1], accO[c][3] * inv1);
        }
    }
}

// ---------------------------------------------------------------------------
// ENTITY branch (d=640): materialized scores (tf32) -> softmax -> AV (tf32)
// ---------------------------------------------------------------------------
__global__ __launch_bounds__(256) void scores_kernel(int qsel, int ksel,
                                                     int headDim, float scale) {
    __shared__ float Qs[2][128 * 20];
    __shared__ float Ks[2][128 * 20];
    int qt = blockIdx.x;
    if (qt >= d_nqtiles) return;
    int g = d_qtileG[qt], q0 = d_qtileQ0[qt];
    int cnt = d_cnt[g];
    int len = cnt;
    int k0t = blockIdx.y * 128;
    if (k0t >= len) return;
    int off = d_off[g];
    int stride = d_cntPad[g];
    const float* Q = g_proj + (size_t)qsel * PSEQ * CD;
    const float* K = g_proj + (size_t)ksel * PSEQ * CD;
    float* Sc = g_scores + (size_t)d_scbase[g];
    int tid = threadIdx.x, lane = tid & 31, warp = tid >> 5;
    int wm = warp & 3, wn = warp >> 2;
    uint32_t qb = smem_u32(Qs), kb = smem_u32(Ks);
    int NS = headDim / 16;

    for (int ch = tid; ch < 512; ch += 256) {
        int r = ch >> 2, c4 = (ch & 3) * 4;
        int qr = q0 + r, kr = k0t + r;
        int qv = (qr < cnt) ? 16 : 0;
        int kv = (kr < len) ? 16 : 0;
        if (qr >= cnt) qr = cnt - 1;
        if (kr >= len) kr = len - 1;
        cp16(qb + (r * 20 + c4) * 4, Q + (size_t)(off + qr) * CD + c4, qv);
        cp16(kb + (r * 20 + c4) * 4, K + (size_t)(off + kr) * CD + c4, kv);
    }
    CP_COMMIT();

    float acc[2][8][4] = {};
    for (int s = 0; s < NS; s++) {
        if (s + 1 < NS) {
            int k0 = (s + 1) * 16;
            int bo = ((s + 1) & 1) * 2560;
            for (int ch = tid; ch < 512; ch += 256) {
                int r = ch >> 2, c4 = (ch & 3) * 4;
                int qr = q0 + r, kr = k0t + r;
                int qv = (qr < cnt) ? 16 : 0;
                int kv = (kr < len) ? 16 : 0;
                if (qr >= cnt) qr = cnt - 1;
                if (kr >= len) kr = len - 1;
                cp16(qb + (bo + r * 20 + c4) * 4, Q + (size_t)(off + qr) * CD + k0 + c4, qv);
                cp16(kb + (bo + r * 20 + c4) * 4, K + (size_t)(off + kr) * CD + k0 + c4, kv);
            }
        }
        CP_COMMIT(); CP_WAIT1();
        __syncthreads();
        const float* Qb = Qs[s & 1];
        const float* Kb = Ks[s & 1];
        #pragma unroll
        for (int k8 = 0; k8 < 16; k8 += 8) {
            int ac = k8 + (lane & 3);
            int ar = wm * 32 + (lane >> 2);
            uint32_t a[2][4];
            #pragma unroll
            for (int i = 0; i < 2; i++) {
                a[i][0] = rtf(Qb[(ar + i * 16) * 20 + ac]);
                a[i][1] = rtf(Qb[(ar + i * 16 + 8) * 20 + ac]);
                a[i][2] = rtf(Qb[(ar + i * 16) * 20 + ac + 4]);
                a[i][3] = rtf(Qb[(ar + i * 16 + 8) * 20 + ac + 4]);
            }
            #pragma unroll
            for (int j = 0; j < 8; j++) {
                int bc = wn * 64 + j * 8 + (lane >> 2);
                uint32_t b[2] = { rtf(Kb[bc * 20 + ac]), rtf(Kb[bc * 20 + ac + 4]) };
                mma_tf32(acc[0][j], a[0], b);
                mma_tf32(acc[1][j], a[1], b);
            }
        }
        __syncthreads();
    }
    int mr = q0 + wm * 32 + (lane >> 2);
    int nc = k0t + wn * 64 + 2 * (lane & 3);
    #pragma unroll
    for (int i = 0; i < 2; i++) {
        int r0 = mr + i * 16;
        #pragma unroll
        for (int j = 0; j < 8; j++) {
            int c = nc + j * 8;
            *(float2*)&Sc[(size_t)r0 * stride + c] =
                make_float2(acc[i][j][0] * scale, acc[i][j][1] * scale);
            *(float2*)&Sc[(size_t)(r0 + 8) * stride + c] =
                make_float2(acc[i][j][2] * scale, acc[i][j][3] * scale);
        }
    }
}

__global__ __launch_bounds__(256) void softmax_kernel() {
    __shared__ float buf[SEQ];
    __shared__ float red[256];
    int row = blockIdx.x;
    int g = d_rowg[row];
    if (g < 0) return;
    int rl = d_rowloc[row];
    int len = d_cnt[g];
    float* p = g_scores + (size_t)d_scbase[g] + (size_t)rl * d_cntPad[g];
    int tid = threadIdx.x;
    float mx = -INFINITY;
    for (int i = tid; i < len; i += 256) { float v = p[i]; buf[i] = v; mx = fmaxf(mx, v); }
    red[tid] = mx; __syncthreads();
    for (int s = 128; s > 0; s >>= 1) {
        if (tid < s) red[tid] = fmaxf(red[tid], red[tid + s]);
        __syncthreads();
    }
    mx = red[0]; __syncthreads();
    float sum = 0.f;
    for (int i = tid; i < len; i += 256) { float e = __expf(buf[i] - mx); buf[i] = e; sum += e; }
    red[tid] = sum; __syncthreads();
    for (int s = 128; s > 0; s >>= 1) {
        if (tid < s) red[tid] += red[tid + s];
        __syncthreads();
    }
    float inv = 1.0f / red[0];
    for (int i = tid; i < len; i += 256) p[i] = buf[i] * inv;
}

__global__ __launch_bounds__(256) void av_kernel(int vsel) {
    __shared__ float Ps[2][128 * 20];
    __shared__ float Vs[2][16 * 88];
    int qt = blockIdx.x;
    if (qt >= d_nqtiles) return;
    int g = d_qtileG[qt], q0 = d_qtileQ0[qt];
    int cnt = d_cnt[g];
    int len = cnt;
    int off = d_off[g];
    int stride = d_cntPad[g];
    int c0 = blockIdx.y * 80;
    const float* P = g_scores + (size_t)d_scbase[g];
    const float* V = g_proj + (size_t)vsel * PSEQ * CD;
    int tid = threadIdx.x, lane = tid & 31, warp = tid >> 5;
    int wm = warp & 3, wn = warp >> 2;
    uint32_t pb = smem_u32(Ps), vb = smem_u32(Vs);
    int NS = (len + 15) >> 4;

    for (int ch = tid; ch < 512; ch += 256) {
        int r = ch >> 2, c4 = (ch & 3) * 4;
        int nb = (len - c4) * 4;
        nb = nb < 0 ? 0 : (nb > 16 ? 16 : nb);
        cp16(pb + (r * 20 + c4) * 4, P + (size_t)(q0 + r) * stride + c4, nb);
    }
    for (int ch = tid; ch < 320; ch += 256) {
        int r = ch / 20, c4 = (ch % 20) * 4;
        int rv = (r < len) ? 16 : 0;
        int rr = (r < len) ? r : (len - 1);
        cp16(vb + (r * 88 + c4) * 4, V + (size_t)(off + rr) * CD + c0 + c4, rv);
    }
    CP_COMMIT();

    float acc[2][5][4] = {};
    for (int s = 0; s < NS; s++) {
        if (s + 1 < NS) {
            int k0 = (s + 1) * 16;
            int bo = ((s + 1) & 1);
            for (int ch = tid; ch < 512; ch += 256) {
                int r = ch >> 2, c4 = (ch & 3) * 4;
                int nb = (len - (k0 + c4)) * 4;
                nb = nb < 0 ? 0 : (nb > 16 ? 16 : nb);
                cp16(pb + (bo * 2560 + r * 20 + c4) * 4,
                     P + (size_t)(q0 + r) * stride + k0 + c4, nb);
            }
            for (int ch = tid; ch < 320; ch += 256) {
                int r = ch / 20, c4 = (ch % 20) * 4;
                int rv = (k0 + r < len) ? 16 : 0;
                int rr = (k0 + r < len) ? (k0 + r) : (len - 1);
                cp16(vb + (bo * 1408 + r * 88 + c4) * 4,
                     V + (size_t)(off + rr) * CD + c0 + c4, rv);
            }
        }
        CP_COMMIT(); CP_WAIT1();
        __syncthreads();
        const float* Pb = Ps[s & 1];
        const float* Vb = Vs[s & 1];
        #pragma unroll
        for (int k8 = 0; k8 < 16; k8 += 8) {
            int ac = k8 + (lane & 3);
            int ar = wm * 32 + (lane >> 2);
            uint32_t a[2][4];
            #pragma unroll
            for (int i = 0; i < 2; i++) {
                a[i][0] = rtf(Pb[(ar + i * 16) * 20 + ac]);
                a[i][1] = rtf(Pb[(ar + i * 16 + 8) * 20 + ac]);
                a[i][2] = rtf(Pb[(ar + i * 16) * 20 + ac + 4]);
                a[i][3] = rtf(Pb[(ar + i * 16 + 8) * 20 + ac + 4]);
            }
            #pragma unroll
            for (int j = 0; j < 5; j++) {
                int bc = wn * 40 + j * 8 + (lane >> 2);
                uint32_t b[2] = { rtf(Vb[ac * 88 + bc]), rtf(Vb[(ac + 4) * 88 + bc]) };
                mma_tf32(acc[0][j], a[0], b);
                mma_tf32(acc[1][j], a[1], b);
            }
        }
        __syncthreads();
    }
    int mi = wm * 32 + (lane >> 2);
    int nc = c0 + wn * 40 + 2 * (lane & 3);
    #pragma unroll
    for (int i = 0; i < 2; i++) {
        int r0 = q0 + mi + i * 16;
        int r1 = r0 + 8;
        #pragma unroll
        for (int j = 0; j < 5; j++) {
            int c = nc + j * 8;
            if (r0 < cnt) {
                size_t o = (size_t)(off + r0) * CD + c;
                g_hs[o] += acc[i][j][0]; g_hs[o + 1] += acc[i][j][1];
            }
            if (r1 < cnt) {
                size_t o = (size_t)(off + r1) * CD + c;
                g_hs[o] += acc[i][j][2]; g_hs[o + 1] += acc[i][j][3];
            }
        }
    }
}

// ---------------------------------------------------------------------------
// fallback mean of V_out rows: branch-free, 72 blocks x 64 rows
// ---------------------------------------------------------------------------
__global__ void meanv_kernel() {
    int col = threadIdx.x;
    const float* V = g_proj + 8ull * PSEQ * CD;
    int r0 = blockIdx.x * 64;
    float s = 0.f;
    #pragma unroll 4
    for (int r = 0; r < 64; r++) {
        int row = r0 + r;
        s += V[(size_t)row * CD + col] * g_rowmask[row];
    }
    atomicAdd(&g_meanVo[col], s * (1.0f / SEQ));
}

__global__ void fb_kernel() {
    int row = blockIdx.x;
    int g = d_rowg[row];
    if (g < 0 || d_cntOut[g] != 0) return;
    for (int c = threadIdx.x; c < CD; c += 256)
        g_hs[(size_t)row * CD + c] += g_meanVo[c];
}

// ---------------------------------------------------------------------------
__global__ __launch_bounds__(256) void final_kernel(const float* __restrict__ Wo,
                                                    const float* __restrict__ resid,
                                                    float* __restrict__ Y) {
    __shared__ float Xs[2][128 * 20];
    __shared__ float Bs[2][128 * 20];
    __shared__ int ip[128];
    int n0 = blockIdx.x * 128, m0 = blockIdx.y * 128;
    int tid = threadIdx.x, lane = tid & 31, warp = tid >> 5;
    int wm = warp & 3, wn = warp >> 2;
    if (tid < 128) ip[tid] = g_iperm[m0 + tid];
    __syncthreads();
    uint32_t xb = smem_u32(Xs), bb = smem_u32(Bs);

    for (int ch = tid; ch < 512; ch += 256) {
        int r = ch >> 2, c4 = (ch & 3) * 4;
        cp16(xb + (r * 20 + c4) * 4, g_hs + (size_t)ip[r] * CD + c4, 16);
        cp16(bb + (r * 20 + c4) * 4, Wo + (size_t)(n0 + r) * CD + c4, 16);
    }
    CP_COMMIT();

    float acc[2][8][4] = {};
    for (int s = 0; s < 40; s++) {
        if (s + 1 < 40) {
            int k0 = (s + 1) * 16;
            int bo = ((s + 1) & 1) * 2560;
            for (int ch = tid; ch < 512; ch += 256) {
                int r = ch >> 2, c4 = (ch & 3) * 4;
                cp16(xb + (bo + r * 20 + c4) * 4, g_hs + (size_t)ip[r] * CD + k0 + c4, 16);
                cp16(bb + (bo + r * 20 + c4) * 4, Wo + (size_t)(n0 + r) * CD + k0 + c4, 16);
            }
        }
        CP_COMMIT(); CP_WAIT1();
        __syncthreads();
        const float* Xb = Xs[s & 1];
        const float* Bb = Bs[s & 1];
        #pragma unroll
        for (int k8 = 0; k8 < 16; k8 += 8) {
            int ac = k8 + (lane & 3);
            int ar = wm * 32 + (lane >> 2);
            uint32_t a[2][4];
            #pragma unroll
            for (int i = 0; i < 2; i++) {
                a[i][0] = rtf(Xb[(ar + i * 16) * 20 + ac]);
                a[i][1] = rtf(Xb[(ar + i * 16 + 8) * 20 + ac]);
                a[i][2] = rtf(Xb[(ar + i * 16) * 20 + ac + 4]);
                a[i][3] = rtf(Xb[(ar + i * 16 + 8) * 20 + ac + 4]);
            }
            #pragma unroll
            for (int j = 0; j < 8; j++) {
                int bc = wn * 64 + j * 8 + (lane >> 2);
                uint32_t b[2] = { rtf(Bb[bc * 20 + ac]), rtf(Bb[bc * 20 + ac + 4]) };
                mma_tf32(acc[0][j], a[0], b);
                mma_tf32(acc[1][j], a[1], b);
            }
        }
        __syncthreads();
    }
    int mi = wm * 32 + (lane >> 2);
    int nc = n0 + wn * 64 + 2 * (lane & 3);
    #pragma unroll
    for (int i = 0; i < 2; i++) {
        #pragma unroll
        for (int j = 0; j < 8; j++) {
            int c = nc + j * 8;
            size_t o0 = (size_t)(m0 + mi + i * 16) * CD + c;
            size_t o1 = (size_t)(m0 + mi + i * 16 + 8) * CD + c;
            Y[o0]     = acc[i][j][0] + resid[o0];
            Y[o0 + 1] = acc[i][j][1] + resid[o0 + 1];
            Y[o1]     = acc[i][j][2] + resid[o1];
            Y[o1 + 1] = acc[i][j][3] + resid[o1 + 1];
        }
    }
}

// ---------------------------------------------------------------------------
extern "C" void kernel_launch(void* const* d_in, const int* in_sizes, int n_in,
                              void* d_out, int out_size) {
    const float* hidden = (const float*)d_in[0];
    const int*   mask   = (const int*)d_in[1];
    const int*   inp    = (const int*)d_in[2];
    W9 ws;
    for (int i = 0; i < 9; i++) ws.w[i] = (const float*)d_in[3 + i];
    const float* Wo = (const float*)d_in[12];
    float* out = (float*)d_out;

    const float s80  = 1.0f / sqrtf(80.0f);
    const float s640 = 1.0f / sqrtf(640.0f);

    cudaFuncSetAttribute(fa_kernel, cudaFuncAttributeMaxDynamicSharedMemorySize, FA_SMEM_BYTES);

    labels_kernel<<<16, 256>>>(mask, inp);
    prep_kernel<<<1, 256>>>();
    zero_hs_kernel<<<2880, 256>>>();
    proj_kernel<<<dim3(5, 32, 9), 256>>>(hidden, ws);
    meanv_kernel<<<72, 640>>>();

    // both d=80 branches in one launch; epilogue atomicAdd into zeroed g_hs
    fa_kernel<<<dim3(40, 8, 2), 256, FA_SMEM_BYTES>>>(s80);

    scores_kernel<<<dim3(40, 32), 256>>>(3, 4, 640, s640);   // entity
    softmax_kernel<<<PSEQ, 256>>>();
    av_kernel<<<dim3(40, 8), 256>>>(5);                      // entity: accumulates

    fb_kernel<<<PSEQ, 256>>>();
    final_kernel<<<dim3(5, 32), 256>>>(Wo, hidden, out);
}